// round 1
// baseline (speedup 1.0000x reference)
#include <cuda_runtime.h>
#include <math.h>

#define B_    128
#define H_    512
#define F_    16
#define HID_  64
#define NF_   257
#define M_    (B_*F_)       // 2048
#define K_    (NF_*HID_)    // 16448
#define NPAD_ 288

// ---------------- scratch (static device memory; no allocations) ----------------
__device__ float g_csd_re[B_*NF_];
__device__ float g_csd_im[B_*NF_];
__device__ float g_fft_re[M_*NF_];   // layout [m = b*F+f][n]
__device__ float g_fft_im[M_*NF_];
__device__ float g_w[M_*NF_];        // gate weights, [m][n]
__device__ float g_wpad[K_*NPAD_];   // W_gate padded to 288 cols
__device__ float g_flat[(size_t)M_*K_]; // proj in GEMM layout: [m][n*64+h]

// ---------------- in-block 512-pt Stockham FFT (256 threads) ----------------
// sign = -1 forward, +1 inverse. Result pointers returned via outr/outi.
__device__ __forceinline__ void block_fft512(float* r0, float* i0, float* r1, float* i1,
                                             int tid, float sign,
                                             float*& outr, float*& outi)
{
    float *ar = r0, *ai = i0, *br = r1, *bi = i1;
    int l = 256, logm = 0;
#pragma unroll
    for (int st = 0; st < 9; st++) {
        __syncthreads();
        int m = 1 << logm;
        int j = tid >> logm;
        int k = tid & (m - 1);
        float c0r = ar[tid],       c0i = ai[tid];
        float c1r = ar[tid + 256], c1i = ai[tid + 256];
        float sr = c0r - c1r, si = c0i - c1i;
        float invl = 1.0f / (float)l;                  // exact power of two
        float ang = sign * 3.14159265358979323846f * (float)j * invl;
        float ws, wc;
        sincosf(ang, &ws, &wc);
        int o0 = k + (j << (logm + 1));
        br[o0]     = c0r + c1r;
        bi[o0]     = c0i + c1i;
        br[o0 + m] = wc * sr - ws * si;
        bi[o0 + m] = wc * si + ws * sr;
        float* t;
        t = ar; ar = br; br = t;
        t = ai; ai = bi; bi = t;
        l >>= 1; logm++;
    }
    __syncthreads();
    outr = ar; outi = ai;
}

// ---------------- kernel 1: CSD via channel-sum autocorrelation ----------------
// mean_{i,j} conv_{ij}[t] = (1/F^2) * sum_k s[t+k-255]*s[k],  s = sum over channels
__global__ void k_csd(const float* __restrict__ x)
{
    __shared__ float s[512];
    __shared__ float r0[512], i0[512], r1[512], i1[512];
    int b = blockIdx.x, tid = threadIdx.x;

    for (int t = tid; t < 512; t += 256) {
        const float4* p = (const float4*)(x + ((size_t)(b * 512 + t)) * 16);
        float4 a = p[0], bb = p[1], c = p[2], d = p[3];
        s[t] = (a.x + a.y + a.z + a.w) + (bb.x + bb.y + bb.z + bb.w)
             + (c.x + c.y + c.z + c.w) + (d.x + d.y + d.z + d.w);
    }
    __syncthreads();

    for (int t = tid; t < 512; t += 256) {
        int k0 = 255 - t; if (k0 < 0)   k0 = 0;
        int k1 = 766 - t; if (k1 > 511) k1 = 511;
        float acc = 0.f;
        for (int k = k0; k <= k1; k++)
            acc = fmaf(s[t + k - 255], s[k], acc);
        r0[t] = acc; i0[t] = 0.f;
    }

    float *orr, *oi;
    block_fft512(r0, i0, r1, i1, tid, -1.f, orr, oi);

    const float SC = 0.044194173824159216f / 256.0f;  // ortho * (1/F^2)
    for (int n = tid; n < NF_; n += 256) {
        g_csd_re[b * NF_ + n] = orr[n] * SC;
        g_csd_im[b * NF_ + n] = oi[n]  * SC;
    }
}

// ---------------- kernel 2: rfft(x) + csd, features, proj -> g_flat ----------------
__global__ void k_fftproj(const float* __restrict__ x,
                          const float* __restrict__ Wp,
                          const float* __restrict__ bp)
{
    __shared__ float r0[512], i0[512], r1[512], i1[512];
    __shared__ float fre[NF_], fim[NF_];
    __shared__ float wp_s[256], bp_s[64];

    int m = blockIdx.x;
    int b = m >> 4, f = m & 15;
    int tid = threadIdx.x;

    if (tid < 256) wp_s[tid] = Wp[tid];
    if (tid < 64)  bp_s[tid] = bp[tid];

    for (int t = tid; t < 512; t += 256) {
        r0[t] = x[((size_t)(b * 512 + t)) * 16 + f];
        i0[t] = 0.f;
    }

    float *orr, *oi;
    block_fft512(r0, i0, r1, i1, tid, -1.f, orr, oi);

    const float SC = 0.044194173824159216f;  // 1/sqrt(512)
    for (int n = tid; n < NF_; n += 256) {
        float re = orr[n] * SC + g_csd_re[b * NF_ + n];
        float im = oi[n]  * SC + g_csd_im[b * NF_ + n];
        fre[n] = re; fim[n] = im;
        g_fft_re[(size_t)m * NF_ + n] = re;
        g_fft_im[(size_t)m * NF_ + n] = im;
    }
    __syncthreads();

    float* flat = g_flat + (size_t)m * K_;
    for (int idx = tid; idx < K_; idx += 256) {
        int n = idx >> 6, h = idx & 63;
        float re = fre[n], im = fim[n];
        float mag = sqrtf(re * re + im * im);
        float sa, ca;
        if (mag > 0.f) { float inv = 1.f / mag; sa = im * inv; ca = re * inv; }
        else           { sa = 0.f; ca = 1.f; }    // angle(0)=0
        float fr = (float)n * 0.1953125f;         // FS/H
        float v = fmaf(mag, wp_s[h], bp_s[h]);
        v = fmaf(sa, wp_s[64  + h], v);
        v = fmaf(ca, wp_s[128 + h], v);
        v = fmaf(fr, wp_s[192 + h], v);
        flat[idx] = fmaxf(v, 0.f);
    }
}

// ---------------- kernel 3a: pad W_gate to 288 columns ----------------
__global__ void k_pad(const float* __restrict__ Wg)
{
    int idx = blockIdx.x * 256 + threadIdx.x;
    if (idx >= K_ * NPAD_) return;
    int row = idx / NPAD_, col = idx - row * NPAD_;
    g_wpad[idx] = (col < NF_) ? Wg[row * NF_ + col] : 0.f;
}

// ---------------- kernel 3b: gate SGEMM 2048x288x16448 + bias + SiLU + sigmoid ----------------
// BM=64, BN=32, BK=16, 128 threads, 4x4 per thread, double-buffered smem.
__global__ void __launch_bounds__(128) k_gemm(const float* __restrict__ bg)
{
    __shared__ float As[2][16][64];
    __shared__ float Bs[2][16][32];

    int tid = threadIdx.x;
    int m0 = blockIdx.y * 64;
    int n0 = blockIdx.x * 32;
    const float* Ag = g_flat + (size_t)m0 * K_;
    const float* Bg = g_wpad + n0;

    float acc[4][4];
#pragma unroll
    for (int i = 0; i < 4; i++)
#pragma unroll
        for (int j = 0; j < 4; j++) acc[i][j] = 0.f;

    int ty = tid >> 3, tx = tid & 7;
    int la_row0 = tid >> 2,        la_k0 = (tid & 3) << 2;   // A: 2 float4 per thread
    int la_row1 = (tid + 128) >> 2, la_k1 = ((tid + 128) & 3) << 2;
    int lb_k = tid >> 4, lb_n = (tid & 15) << 1;             // B: 1 float2 per thread
    // B tile is 16x32 = 512 floats / 128 threads = 4 floats -> use float4 mapping:
    int lbk = tid >> 3, lbn4 = (tid & 7) << 2;

    float4 aR0, aR1, bR;

    // prologue: load tile 0
    aR0 = *(const float4*)(Ag + (size_t)la_row0 * K_ + la_k0);
    aR1 = *(const float4*)(Ag + (size_t)la_row1 * K_ + la_k1);
    bR  = *(const float4*)(Bg + (size_t)lbk * NPAD_ + lbn4);
    As[0][la_k0 + 0][la_row0] = aR0.x; As[0][la_k0 + 1][la_row0] = aR0.y;
    As[0][la_k0 + 2][la_row0] = aR0.z; As[0][la_k0 + 3][la_row0] = aR0.w;
    As[0][la_k1 + 0][la_row1] = aR1.x; As[0][la_k1 + 1][la_row1] = aR1.y;
    As[0][la_k1 + 2][la_row1] = aR1.z; As[0][la_k1 + 3][la_row1] = aR1.w;
    *(float4*)&Bs[0][lbk][lbn4] = bR;
    __syncthreads();

    const int NKB = K_ / 16;  // 1028
    for (int kb = 0; kb < NKB; kb++) {
        int p = kb & 1;
        if (kb + 1 < NKB) {
            const float* Ak = Ag + (kb + 1) * 16;
            aR0 = *(const float4*)(Ak + (size_t)la_row0 * K_ + la_k0);
            aR1 = *(const float4*)(Ak + (size_t)la_row1 * K_ + la_k1);
            bR  = *(const float4*)(Bg + (size_t)((kb + 1) * 16 + lbk) * NPAD_ + lbn4);
        }
#pragma unroll
        for (int k = 0; k < 16; k++) {
            float4 a = *(const float4*)(&As[p][k][ty * 4]);
            float4 b = *(const float4*)(&Bs[p][k][tx * 4]);
            float av[4] = { a.x, a.y, a.z, a.w };
            float bv[4] = { b.x, b.y, b.z, b.w };
#pragma unroll
            for (int i = 0; i < 4; i++)
#pragma unroll
                for (int j = 0; j < 4; j++)
                    acc[i][j] = fmaf(av[i], bv[j], acc[i][j]);
        }
        if (kb + 1 < NKB) {
            int q = p ^ 1;
            As[q][la_k0 + 0][la_row0] = aR0.x; As[q][la_k0 + 1][la_row0] = aR0.y;
            As[q][la_k0 + 2][la_row0] = aR0.z; As[q][la_k0 + 3][la_row0] = aR0.w;
            As[q][la_k1 + 0][la_row1] = aR1.x; As[q][la_k1 + 1][la_row1] = aR1.y;
            As[q][la_k1 + 2][la_row1] = aR1.z; As[q][la_k1 + 3][la_row1] = aR1.w;
            *(float4*)&Bs[q][lbk][lbn4] = bR;
        }
        __syncthreads();
    }

    (void)lb_k; (void)lb_n;
#pragma unroll
    for (int i = 0; i < 4; i++) {
        int mm = m0 + ty * 4 + i;
#pragma unroll
        for (int j = 0; j < 4; j++) {
            int nn = n0 + tx * 4 + j;
            if (nn < NF_) {
                float g = acc[i][j] + bg[nn];
                float s1 = 1.f / (1.f + expf(-g));
                g = g * s1;                              // SiLU
                float w = 1.f / (1.f + expf(-g));        // gate weight
                g_w[(size_t)mm * NF_ + nn] = w;
            }
        }
    }
}

// ---------------- kernel 4: mag/phase heads + complexify + blend (in place) ----------------
__global__ void k_combine(const float* __restrict__ mag_w, const float* __restrict__ mag_b,
                          const float* __restrict__ ph_w,  const float* __restrict__ ph_b)
{
    int m = blockIdx.x;
    int tid = threadIdx.x;
    const float* flat = g_flat + (size_t)m * K_;

    for (int n = tid; n < NF_; n += 256) {
        const float4* pr = (const float4*)(flat + n * 64);
        const float4* mw = (const float4*)(mag_w + n * 64);
        const float4* pw = (const float4*)(ph_w + n * 64);
        float dm = 0.f, dp = 0.f;
#pragma unroll
        for (int q = 0; q < 16; q++) {
            float4 p = pr[q], a = mw[q], c = pw[q];
            dm = fmaf(p.x, a.x, dm); dm = fmaf(p.y, a.y, dm);
            dm = fmaf(p.z, a.z, dm); dm = fmaf(p.w, a.w, dm);
            dp = fmaf(p.x, c.x, dp); dp = fmaf(p.y, c.y, dp);
            dp = fmaf(p.z, c.z, dp); dp = fmaf(p.w, c.w, dp);
        }
        float mo = fmaxf(dm + mag_b[n], 0.f);
        float ph = 6.283185307179586f / (1.f + expf(-(dp + ph_b[n])));
        float sp, cp;
        sincosf(ph, &sp, &cp);
        float nr = mo * cp, ni = mo * sp;
        size_t id = (size_t)m * NF_ + n;
        float wv = g_w[id];
        g_fft_re[id] = wv * nr + (1.f - wv) * g_fft_re[id];
        g_fft_im[id] = wv * ni + (1.f - wv) * g_fft_im[id];
    }
}

// ---------------- kernel 5: irfft (ortho) + residual ----------------
__global__ void k_irfft(const float* __restrict__ x, float* __restrict__ out)
{
    __shared__ float r0[512], i0[512], r1[512], i1[512];
    int m = blockIdx.x;
    int b = m >> 4, f = m & 15;
    int tid = threadIdx.x;
    const float* wr = g_fft_re + (size_t)m * NF_;
    const float* wi = g_fft_im + (size_t)m * NF_;

    for (int n = tid; n < 512; n += 256) {
        float re, im;
        if (n == 0)        { re = wr[0];   im = 0.f; }        // imag ignored (c2r)
        else if (n < 256)  { re = wr[n];   im = wi[n]; }
        else if (n == 256) { re = wr[256]; im = 0.f; }        // imag ignored (c2r)
        else               { re = wr[512 - n]; im = -wi[512 - n]; }
        r0[n] = re; i0[n] = im;
    }

    float *orr, *oi;
    block_fft512(r0, i0, r1, i1, tid, +1.f, orr, oi);

    const float SC = 0.044194173824159216f;  // 1/sqrt(512)
    for (int t = tid; t < 512; t += 256) {
        size_t xi = ((size_t)(b * 512 + t)) * 16 + f;
        out[xi] = orr[t] * SC + x[xi];
    }
}

// ---------------- kernel 6: LayerNorm over F=16 ----------------
__global__ void k_ln(float* __restrict__ out,
                     const float* __restrict__ gamma, const float* __restrict__ beta)
{
    int row = blockIdx.x * blockDim.x + threadIdx.x;  // b*512 + t, 65536 rows
    if (row >= B_ * H_) return;
    float* p = out + (size_t)row * 16;
    float v[16];
    float4* pv = (float4*)p;
#pragma unroll
    for (int q = 0; q < 4; q++) {
        float4 t = pv[q];
        v[q * 4 + 0] = t.x; v[q * 4 + 1] = t.y; v[q * 4 + 2] = t.z; v[q * 4 + 3] = t.w;
    }
    float s = 0.f;
#pragma unroll
    for (int i = 0; i < 16; i++) s += v[i];
    float mu = s * (1.f / 16.f);
    float ss = 0.f;
#pragma unroll
    for (int i = 0; i < 16; i++) { float d = v[i] - mu; ss = fmaf(d, d, ss); }
    float inv = 1.f / sqrtf(ss * (1.f / 16.f) + 1e-5f);
#pragma unroll
    for (int i = 0; i < 16; i++)
        v[i] = (v[i] - mu) * inv * __ldg(&gamma[i]) + __ldg(&beta[i]);
#pragma unroll
    for (int q = 0; q < 4; q++) {
        float4 t;
        t.x = v[q * 4 + 0]; t.y = v[q * 4 + 1]; t.z = v[q * 4 + 2]; t.w = v[q * 4 + 3];
        pv[q] = t;
    }
}

// ---------------- launcher ----------------
extern "C" void kernel_launch(void* const* d_in, const int* in_sizes, int n_in,
                              void* d_out, int out_size)
{
    const float* x       = (const float*)d_in[0];
    const float* W_proj  = (const float*)d_in[1];
    const float* b_proj  = (const float*)d_in[2];
    const float* W_gate  = (const float*)d_in[3];
    const float* b_gate  = (const float*)d_in[4];
    const float* mag_w   = (const float*)d_in[5];
    const float* mag_b   = (const float*)d_in[6];
    const float* phase_w = (const float*)d_in[7];
    const float* phase_b = (const float*)d_in[8];
    const float* ln_g    = (const float*)d_in[9];
    const float* ln_b    = (const float*)d_in[10];
    float* out = (float*)d_out;

    k_csd<<<B_, 256>>>(x);
    k_fftproj<<<M_, 256>>>(x, W_proj, b_proj);
    k_pad<<<(K_ * NPAD_ + 255) / 256, 256>>>(W_gate);
    k_gemm<<<dim3(NPAD_ / 32, M_ / 64), 128>>>(b_gate);
    k_combine<<<M_, 256>>>(mag_w, mag_b, phase_w, phase_b);
    k_irfft<<<M_, 256>>>(x, out);
    k_ln<<<(B_ * H_ + 255) / 256, 256>>>(out, ln_g, ln_b);
}

// round 3
// speedup vs baseline: 2.3225x; 2.3225x over previous
#include <cuda_runtime.h>
#include <math.h>
#include <stdint.h>

#define B_    128
#define H_    512
#define F_    16
#define HID_  64
#define NF_   257
#define M_    (B_*F_)       // 2048
#define K_    (NF_*HID_)    // 16448
#define NPAD_ 288
#define SPLITS_ 4

// ---------------- scratch (static device memory; no allocations) ----------------
__device__ __align__(128) float g_csd_re[B_*NF_];
__device__ __align__(128) float g_csd_im[B_*NF_];
__device__ __align__(128) float g_fft_re[M_*NF_];
__device__ __align__(128) float g_fft_im[M_*NF_];
__device__ __align__(128) float g_new_re[M_*NF_];
__device__ __align__(128) float g_new_im[M_*NF_];
__device__ __align__(128) float g_wt[(size_t)NPAD_*K_];        // W_gate^T [n][k], tf32-rounded, rows>=257 zero
__device__ __align__(128) float g_part[SPLITS_][(size_t)M_*NPAD_];
__device__ __align__(128) float g_flat[(size_t)M_*K_];         // proj, tf32-rounded, [m][n*64+h]

// ================= helpers =================
__device__ __forceinline__ float f2tf32(float f) {
    uint32_t u;
    asm("cvt.rna.tf32.f32 %0, %1;" : "=r"(u) : "f"(f));
    return __uint_as_float(u);
}
#define CP_ASYNC16(dst, src) \
    asm volatile("cp.async.cg.shared.global [%0], [%1], 16;\n" :: "r"(dst), "l"(src))
__device__ __forceinline__ uint32_t smem_u32(const void* p) {
    uint32_t a;
    asm("{ .reg .u64 t; cvta.to.shared.u64 t, %1; cvt.u32.u64 %0, t; }" : "=r"(a) : "l"(p));
    return a;
}
__device__ __forceinline__ void mma_tf32(float c[4], const uint32_t a[4], const uint32_t b[2]) {
    asm volatile(
        "mma.sync.aligned.m16n8k8.row.col.f32.tf32.tf32.f32 "
        "{%0,%1,%2,%3}, {%4,%5,%6,%7}, {%8,%9}, {%0,%1,%2,%3};"
        : "+f"(c[0]), "+f"(c[1]), "+f"(c[2]), "+f"(c[3])
        : "r"(a[0]), "r"(a[1]), "r"(a[2]), "r"(a[3]), "r"(b[0]), "r"(b[1]));
}

// ---------------- in-block 512-pt Stockham FFT (256 threads) ----------------
__device__ __forceinline__ void block_fft512(float* r0, float* i0, float* r1, float* i1,
                                             int tid, float sign, float*& outr, float*& outi)
{
    float *ar = r0, *ai = i0, *br = r1, *bi = i1;
    int l = 256, logm = 0;
#pragma unroll
    for (int st = 0; st < 9; st++) {
        __syncthreads();
        int m = 1 << logm;
        int j = tid >> logm;
        int k = tid & (m - 1);
        float c0r = ar[tid],       c0i = ai[tid];
        float c1r = ar[tid + 256], c1i = ai[tid + 256];
        float sr = c0r - c1r, si = c0i - c1i;
        float invl = 1.0f / (float)l;
        float ang = sign * 3.14159265358979323846f * (float)j * invl;
        float ws, wc;
        sincosf(ang, &ws, &wc);
        int o0 = k + (j << (logm + 1));
        br[o0]     = c0r + c1r;
        bi[o0]     = c0i + c1i;
        br[o0 + m] = wc * sr - ws * si;
        bi[o0 + m] = wc * si + ws * sr;
        float* t;
        t = ar; ar = br; br = t;
        t = ai; ai = bi; bi = t;
        l >>= 1; logm++;
    }
    __syncthreads();
    outr = ar; outi = ai;
}

// ---------------- kernel 1: CSD via channel-sum autocorrelation ----------------
__global__ void k_csd(const float* __restrict__ x)
{
    __shared__ float s[512];
    __shared__ float r0[512], i0[512], r1[512], i1[512];
    int b = blockIdx.x, tid = threadIdx.x;

    for (int t = tid; t < 512; t += 256) {
        const float4* p = (const float4*)(x + ((size_t)(b * 512 + t)) * 16);
        float4 a = p[0], bb = p[1], c = p[2], d = p[3];
        s[t] = (a.x + a.y + a.z + a.w) + (bb.x + bb.y + bb.z + bb.w)
             + (c.x + c.y + c.z + c.w) + (d.x + d.y + d.z + d.w);
    }
    __syncthreads();

    for (int t = tid; t < 512; t += 256) {
        int k0 = 255 - t; if (k0 < 0)   k0 = 0;
        int k1 = 766 - t; if (k1 > 511) k1 = 511;
        float acc = 0.f;
        for (int k = k0; k <= k1; k++)
            acc = fmaf(s[t + k - 255], s[k], acc);
        r0[t] = acc; i0[t] = 0.f;
    }

    float *orr, *oi;
    block_fft512(r0, i0, r1, i1, tid, -1.f, orr, oi);

    const float SC = 0.044194173824159216f / 256.0f;
    for (int n = tid; n < NF_; n += 256) {
        g_csd_re[b * NF_ + n] = orr[n] * SC;
        g_csd_im[b * NF_ + n] = oi[n]  * SC;
    }
}

// ---------------- kernel 2: rfft + csd, features, proj -> g_flat (tf32), heads -> g_new ----------------
__global__ void k_fftproj(const float* __restrict__ x,
                          const float* __restrict__ Wp,
                          const float* __restrict__ bp,
                          const float* __restrict__ mag_w,
                          const float* __restrict__ mag_b,
                          const float* __restrict__ ph_w,
                          const float* __restrict__ ph_b)
{
    __shared__ float r0[512], i0[512], r1[512], i1[512];
    __shared__ __align__(16) float wp_s[256];
    __shared__ __align__(16) float bp_s[64];

    int m = blockIdx.x;
    int b = m >> 4, f = m & 15;
    int tid = threadIdx.x;

    if (tid < 256) wp_s[tid] = Wp[tid];
    if (tid < 64)  bp_s[tid] = bp[tid];

    for (int t = tid; t < 512; t += 256) {
        r0[t] = x[((size_t)(b * 512 + t)) * 16 + f];
        i0[t] = 0.f;
    }

    float *orr, *oi;
    block_fft512(r0, i0, r1, i1, tid, -1.f, orr, oi);

    const float SC = 0.044194173824159216f;
    for (int n = tid; n < NF_; n += 256) {
        float re = orr[n] * SC + g_csd_re[b * NF_ + n];
        float im = oi[n]  * SC + g_csd_im[b * NF_ + n];
        orr[n] = re; oi[n] = im;
        g_fft_re[(size_t)m * NF_ + n] = re;
        g_fft_im[(size_t)m * NF_ + n] = im;
    }
    __syncthreads();

    for (int n = tid; n < NF_; n += 256) {
        float re = orr[n], im = oi[n];
        float mag = sqrtf(re * re + im * im);
        float sa, ca;
        if (mag > 0.f) { float inv = 1.f / mag; sa = im * inv; ca = re * inv; }
        else           { sa = 0.f; ca = 1.f; }
        float fr = (float)n * 0.1953125f;

        float4* dst = (float4*)(g_flat + (size_t)m * K_ + (size_t)n * 64);
        const float4* mw = (const float4*)(mag_w + (size_t)n * 64);
        const float4* pw = (const float4*)(ph_w  + (size_t)n * 64);
        float dm = 0.f, dp = 0.f;
#pragma unroll
        for (int q = 0; q < 16; q++) {
            float4 w0 = *(const float4*)&wp_s[q * 4];
            float4 w1 = *(const float4*)&wp_s[64 + q * 4];
            float4 w2 = *(const float4*)&wp_s[128 + q * 4];
            float4 w3 = *(const float4*)&wp_s[192 + q * 4];
            float4 bb = *(const float4*)&bp_s[q * 4];
            float4 v;
            v.x = fmaxf(fmaf(mag, w0.x, fmaf(sa, w1.x, fmaf(ca, w2.x, fmaf(fr, w3.x, bb.x)))), 0.f);
            v.y = fmaxf(fmaf(mag, w0.y, fmaf(sa, w1.y, fmaf(ca, w2.y, fmaf(fr, w3.y, bb.y)))), 0.f);
            v.z = fmaxf(fmaf(mag, w0.z, fmaf(sa, w1.z, fmaf(ca, w2.z, fmaf(fr, w3.z, bb.z)))), 0.f);
            v.w = fmaxf(fmaf(mag, w0.w, fmaf(sa, w1.w, fmaf(ca, w2.w, fmaf(fr, w3.w, bb.w)))), 0.f);
            float4 vt;
            vt.x = f2tf32(v.x); vt.y = f2tf32(v.y); vt.z = f2tf32(v.z); vt.w = f2tf32(v.w);
            dst[q] = vt;                    // rounded copy for tensor GEMM
            float4 a = __ldg(&mw[q]);
            float4 c = __ldg(&pw[q]);
            dm = fmaf(v.x, a.x, dm); dm = fmaf(v.y, a.y, dm);
            dm = fmaf(v.z, a.z, dm); dm = fmaf(v.w, a.w, dm);
            dp = fmaf(v.x, c.x, dp); dp = fmaf(v.y, c.y, dp);
            dp = fmaf(v.z, c.z, dp); dp = fmaf(v.w, c.w, dp);
        }
        float mo  = fmaxf(dm + __ldg(&mag_b[n]), 0.f);
        float phv = 6.283185307179586f / (1.f + expf(-(dp + __ldg(&ph_b[n]))));
        float sp, cp;
        sincosf(phv, &sp, &cp);
        g_new_re[(size_t)m * NF_ + n] = mo * cp;
        g_new_im[(size_t)m * NF_ + n] = mo * sp;
    }
}

// ---------------- kernel 3a: transpose W_gate [K][257] -> g_wt [288][K] (tf32, zero pad) ----------------
__global__ void k_transpose(const float* __restrict__ Wg)
{
    __shared__ float tile[32][33];
    int tid = threadIdx.x;
    int tx = tid & 31, ty = tid >> 5;
    int kb = blockIdx.x * 32, nb = blockIdx.y * 32;
#pragma unroll
    for (int r = 0; r < 4; r++) {
        int kk = kb + ty + r * 8;
        int nn = nb + tx;
        tile[ty + r * 8][tx] = (nn < NF_) ? f2tf32(Wg[(size_t)kk * NF_ + nn]) : 0.f;
    }
    __syncthreads();
#pragma unroll
    for (int r = 0; r < 4; r++) {
        int nn = nb + ty + r * 8;
        int kk = kb + tx;
        g_wt[(size_t)nn * K_ + kk] = tile[tx][ty + r * 8];
    }
}

// ---------------- kernel 3b: tf32 mma.sync split-K GEMM ----------------
// CTA tile 128x96x32, 8 warps (4x2), warp tile 32x48 (2x6 m16n8k8), 3-stage cp.async.
#define BK_       32
#define NCHUNK_   (K_/BK_)        // 514
#define ASTRIDE_  36              // 32 + 4 pad -> conflict-free fragment LDS
#define A_WORDS_  (128*ASTRIDE_)  // 4608
#define B_WORDS_  (96*ASTRIDE_)   // 3456
#define STG_WORDS_ (A_WORDS_+B_WORDS_)  // 8064
#define GEMM_SMEM_ (3*STG_WORDS_*4)     // 96768 bytes

__device__ __forceinline__ void load_chunk(uint32_t sbase, const float* __restrict__ Ab,
                                           const float* __restrict__ Bb, int kbase, int tid)
{
    uint32_t sA = sbase;
    uint32_t sB = sbase + A_WORDS_ * 4;
#pragma unroll
    for (int i = 0; i < 4; i++) {             // A: 128 rows x 8 float4
        int g = tid + (i << 8);
        int r = g >> 3, c = g & 7;
        CP_ASYNC16(sA + (uint32_t)(r * (ASTRIDE_*4) + c * 16),
                   Ab + (size_t)r * K_ + kbase + c * 4);
    }
#pragma unroll
    for (int i = 0; i < 3; i++) {             // B: 96 rows x 8 float4
        int g = tid + (i << 8);
        int r = g >> 3, c = g & 7;
        CP_ASYNC16(sB + (uint32_t)(r * (ASTRIDE_*4) + c * 16),
                   Bb + (size_t)r * K_ + kbase + c * 4);
    }
    asm volatile("cp.async.commit_group;\n" ::: "memory");
}

__global__ void __launch_bounds__(256, 2) k_gemm()
{
    extern __shared__ __align__(16) float smem[];

    int tid = threadIdx.x;
    int nt0 = blockIdx.x;           // 0..2
    int m0  = blockIdx.y * 128;
    int s   = blockIdx.z;           // split 0..3
    const float* Ab = g_flat + (size_t)m0 * K_;
    const float* Bb = g_wt + (size_t)(nt0 * 96) * K_;

    int warp = tid >> 5, lane = tid & 31;
    int wm = warp & 3;              // m: wm*32
    int wn = warp >> 2;             // n: wn*48
    int lr = lane >> 2, lc = lane & 3;

    float acc[2][6][4];
#pragma unroll
    for (int i = 0; i < 2; i++)
#pragma unroll
        for (int j = 0; j < 6; j++)
#pragma unroll
            for (int q = 0; q < 4; q++) acc[i][j][q] = 0.f;

    const int cs = (s * NCHUNK_) / SPLITS_;
    const int ce = ((s + 1) * NCHUNK_) / SPLITS_;
    const int CN = ce - cs;

    uint32_t sb = smem_u32(smem);

    load_chunk(sb + 0 * STG_WORDS_ * 4, Ab, Bb, (cs + 0) * BK_, tid);
    load_chunk(sb + 1 * STG_WORDS_ * 4, Ab, Bb, (cs + 1) * BK_, tid);

    for (int i = 0; i < CN; i++) {
        if (i + 2 < CN)
            load_chunk(sb + ((i + 2) % 3) * STG_WORDS_ * 4, Ab, Bb, (cs + i + 2) * BK_, tid);
        else
            asm volatile("cp.async.commit_group;\n" ::: "memory");
        asm volatile("cp.async.wait_group 2;\n" ::: "memory");
        __syncthreads();

        const float* sA = smem + ((size_t)(i % 3)) * STG_WORDS_;
        const float* sB = sA + A_WORDS_;
        const uint32_t* Awp = (const uint32_t*)(sA + (wm * 32 + lr) * ASTRIDE_ + lc);
        const uint32_t* Bwp = (const uint32_t*)(sB + (wn * 48 + lr) * ASTRIDE_ + lc);

#pragma unroll
        for (int kt = 0; kt < 4; kt++) {
            uint32_t a[2][4];
#pragma unroll
            for (int mt = 0; mt < 2; mt++) {
                const uint32_t* p = Awp + mt * 16 * ASTRIDE_ + kt * 8;
                a[mt][0] = p[0];
                a[mt][1] = p[8 * ASTRIDE_];
                a[mt][2] = p[4];
                a[mt][3] = p[8 * ASTRIDE_ + 4];
            }
            uint32_t bfr[6][2];
#pragma unroll
            for (int nt = 0; nt < 6; nt++) {
                const uint32_t* p = Bwp + nt * 8 * ASTRIDE_ + kt * 8;
                bfr[nt][0] = p[0];
                bfr[nt][1] = p[4];
            }
#pragma unroll
            for (int mt = 0; mt < 2; mt++)
#pragma unroll
                for (int nt = 0; nt < 6; nt++)
                    mma_tf32(acc[mt][nt], a[mt], bfr[nt]);
        }
        __syncthreads();
    }

    // epilogue: write partials
    float* P = g_part[s];
#pragma unroll
    for (int mt = 0; mt < 2; mt++) {
        int row = m0 + wm * 32 + mt * 16 + lr;
#pragma unroll
        for (int nt = 0; nt < 6; nt++) {
            int col = nt0 * 96 + wn * 48 + nt * 8 + lc * 2;
            float2 v0 = make_float2(acc[mt][nt][0], acc[mt][nt][1]);
            float2 v1 = make_float2(acc[mt][nt][2], acc[mt][nt][3]);
            *(float2*)(P + (size_t)row * NPAD_ + col)       = v0;
            *(float2*)(P + (size_t)(row + 8) * NPAD_ + col) = v1;
        }
    }
}

// ---------------- kernel 4: reduce split-K + bias + SiLU + sigmoid + blend ----------------
__global__ void k_reduce_blend(const float* __restrict__ bg)
{
    int idx = blockIdx.x * 256 + threadIdx.x;
    if (idx >= M_ * NF_) return;
    int m = idx / NF_, n = idx - m * NF_;
    size_t pofs = (size_t)m * NPAD_ + n;
    float acc = 0.f;
#pragma unroll
    for (int s = 0; s < SPLITS_; s++) acc += g_part[s][pofs];
    float g = acc + __ldg(&bg[n]);
    float s1 = 1.f / (1.f + expf(-g));
    g = g * s1;                              // SiLU
    float w = 1.f / (1.f + expf(-g));        // gate weight
    float re = w * g_new_re[idx] + (1.f - w) * g_fft_re[idx];
    float im = w * g_new_im[idx] + (1.f - w) * g_fft_im[idx];
    g_fft_re[idx] = re;
    g_fft_im[idx] = im;
}

// ---------------- kernel 5: irfft (ortho) + residual ----------------
__global__ void k_irfft(const float* __restrict__ x, float* __restrict__ out)
{
    __shared__ float r0[512], i0[512], r1[512], i1[512];
    int m = blockIdx.x;
    int b = m >> 4, f = m & 15;
    int tid = threadIdx.x;
    const float* wr = g_fft_re + (size_t)m * NF_;
    const float* wi = g_fft_im + (size_t)m * NF_;

    for (int n = tid; n < 512; n += 256) {
        float re, im;
        if (n == 0)        { re = wr[0];   im = 0.f; }
        else if (n < 256)  { re = wr[n];   im = wi[n]; }
        else if (n == 256) { re = wr[256]; im = 0.f; }
        else               { re = wr[512 - n]; im = -wi[512 - n]; }
        r0[n] = re; i0[n] = im;
    }

    float *orr, *oi;
    block_fft512(r0, i0, r1, i1, tid, +1.f, orr, oi);

    const float SC = 0.044194173824159216f;
    for (int t = tid; t < 512; t += 256) {
        size_t xi = ((size_t)(b * 512 + t)) * 16 + f;
        out[xi] = orr[t] * SC + x[xi];
    }
}

// ---------------- kernel 6: LayerNorm over F=16 ----------------
__global__ void k_ln(float* __restrict__ out,
                     const float* __restrict__ gamma, const float* __restrict__ beta)
{
    int row = blockIdx.x * blockDim.x + threadIdx.x;
    if (row >= B_ * H_) return;
    float* p = out + (size_t)row * 16;
    float v[16];
    float4* pv = (float4*)p;
#pragma unroll
    for (int q = 0; q < 4; q++) {
        float4 t = pv[q];
        v[q * 4 + 0] = t.x; v[q * 4 + 1] = t.y; v[q * 4 + 2] = t.z; v[q * 4 + 3] = t.w;
    }
    float sm = 0.f;
#pragma unroll
    for (int i = 0; i < 16; i++) sm += v[i];
    float mu = sm * (1.f / 16.f);
    float ss = 0.f;
#pragma unroll
    for (int i = 0; i < 16; i++) { float d = v[i] - mu; ss = fmaf(d, d, ss); }
    float inv = 1.f / sqrtf(ss * (1.f / 16.f) + 1e-5f);
#pragma unroll
    for (int i = 0; i < 16; i++)
        v[i] = (v[i] - mu) * inv * __ldg(&gamma[i]) + __ldg(&beta[i]);
#pragma unroll
    for (int q = 0; q < 4; q++) {
        float4 t;
        t.x = v[q * 4 + 0]; t.y = v[q * 4 + 1]; t.z = v[q * 4 + 2]; t.w = v[q * 4 + 3];
        pv[q] = t;
    }
}

// ---------------- launcher ----------------
extern "C" void kernel_launch(void* const* d_in, const int* in_sizes, int n_in,
                              void* d_out, int out_size)
{
    const float* x       = (const float*)d_in[0];
    const float* W_proj  = (const float*)d_in[1];
    const float* b_proj  = (const float*)d_in[2];
    const float* W_gate  = (const float*)d_in[3];
    const float* b_gate  = (const float*)d_in[4];
    const float* mag_w   = (const float*)d_in[5];
    const float* mag_b   = (const float*)d_in[6];
    const float* phase_w = (const float*)d_in[7];
    const float* phase_b = (const float*)d_in[8];
    const float* ln_g    = (const float*)d_in[9];
    const float* ln_b    = (const float*)d_in[10];
    float* out = (float*)d_out;

    cudaFuncSetAttribute(k_gemm, cudaFuncAttributeMaxDynamicSharedMemorySize, GEMM_SMEM_);

    k_csd<<<B_, 256>>>(x);
    k_fftproj<<<M_, 256>>>(x, W_proj, b_proj, mag_w, mag_b, phase_w, phase_b);
    k_transpose<<<dim3(K_ / 32, NPAD_ / 32), 256>>>(W_gate);
    k_gemm<<<dim3(3, 16, SPLITS_), 256, GEMM_SMEM_>>>();
    k_reduce_blend<<<(M_ * NF_ + 255) / 256, 256>>>(b_gate);
    k_irfft<<<M_, 256>>>(x, out);
    k_ln<<<(B_ * H_ + 255) / 256, 256>>>(out, ln_g, ln_b);
}

// round 4
// speedup vs baseline: 2.8190x; 1.2138x over previous
#include <cuda_runtime.h>
#include <math.h>
#include <stdint.h>

#define B_    128
#define H_    512
#define F_    16
#define HID_  64
#define NF_   257
#define M_    (B_*F_)       // 2048
#define K_    (NF_*HID_)    // 16448
#define NPAD_ 288
#define SPLITS_ 6

// ---------------- scratch (static device memory; no allocations) ----------------
__device__ __align__(128) float g_csd_re[B_*NF_];
__device__ __align__(128) float g_csd_im[B_*NF_];
__device__ __align__(128) float g_fft_re[M_*NF_];
__device__ __align__(128) float g_fft_im[M_*NF_];
__device__ __align__(128) float g_new_re[M_*NF_];
__device__ __align__(128) float g_new_im[M_*NF_];
__device__ __align__(128) float g_wt[(size_t)NPAD_*K_];        // W_gate^T [n][k], tf32-rounded
__device__ __align__(128) float g_part[SPLITS_][(size_t)M_*NPAD_];
__device__ __align__(128) float g_flat[(size_t)M_*K_];         // proj, tf32-rounded, [m][n*64+h]

// ================= helpers =================
__device__ __forceinline__ float f2tf32(float f) {
    uint32_t u;
    asm("cvt.rna.tf32.f32 %0, %1;" : "=r"(u) : "f"(f));
    return __uint_as_float(u);
}
#define CP_ASYNC16(dst, src) \
    asm volatile("cp.async.cg.shared.global [%0], [%1], 16;\n" :: "r"(dst), "l"(src))
__device__ __forceinline__ uint32_t smem_u32(const void* p) {
    uint32_t a;
    asm("{ .reg .u64 t; cvta.to.shared.u64 t, %1; cvt.u32.u64 %0, t; }" : "=r"(a) : "l"(p));
    return a;
}
__device__ __forceinline__ void mma_tf32(float c[4], const uint32_t a[4], const uint32_t b[2]) {
    asm volatile(
        "mma.sync.aligned.m16n8k8.row.col.f32.tf32.tf32.f32 "
        "{%0,%1,%2,%3}, {%4,%5,%6,%7}, {%8,%9}, {%0,%1,%2,%3};"
        : "+f"(c[0]), "+f"(c[1]), "+f"(c[2]), "+f"(c[3])
        : "r"(a[0]), "r"(a[1]), "r"(a[2]), "r"(a[3]), "r"(b[0]), "r"(b[1]));
}

// ---------------- in-block 512-pt Stockham FFT (256 threads) ----------------
__device__ __forceinline__ void block_fft512(float* r0, float* i0, float* r1, float* i1,
                                             int tid, float sign, float*& outr, float*& outi)
{
    float *ar = r0, *ai = i0, *br = r1, *bi = i1;
    int l = 256, logm = 0;
#pragma unroll
    for (int st = 0; st < 9; st++) {
        __syncthreads();
        int m = 1 << logm;
        int j = tid >> logm;
        int k = tid & (m - 1);
        float c0r = ar[tid],       c0i = ai[tid];
        float c1r = ar[tid + 256], c1i = ai[tid + 256];
        float sr = c0r - c1r, si = c0i - c1i;
        float invl = 1.0f / (float)l;
        float ang = sign * 3.14159265358979323846f * (float)j * invl;
        float ws, wc;
        sincosf(ang, &ws, &wc);
        int o0 = k + (j << (logm + 1));
        br[o0]     = c0r + c1r;
        bi[o0]     = c0i + c1i;
        br[o0 + m] = wc * sr - ws * si;
        bi[o0 + m] = wc * si + ws * sr;
        float* t;
        t = ar; ar = br; br = t;
        t = ai; ai = bi; bi = t;
        l >>= 1; logm++;
    }
    __syncthreads();
    outr = ar; outi = ai;
}

// ---------------- kernel 1: CSD via channel-sum autocorrelation ----------------
__global__ void k_csd(const float* __restrict__ x)
{
    __shared__ float s[512];
    __shared__ float r0[512], i0[512], r1[512], i1[512];
    int b = blockIdx.x, tid = threadIdx.x;

    for (int t = tid; t < 512; t += 256) {
        const float4* p = (const float4*)(x + ((size_t)(b * 512 + t)) * 16);
        float4 a = p[0], bb = p[1], c = p[2], d = p[3];
        s[t] = (a.x + a.y + a.z + a.w) + (bb.x + bb.y + bb.z + bb.w)
             + (c.x + c.y + c.z + c.w) + (d.x + d.y + d.z + d.w);
    }
    __syncthreads();

    for (int t = tid; t < 512; t += 256) {
        int k0 = 255 - t; if (k0 < 0)   k0 = 0;
        int k1 = 766 - t; if (k1 > 511) k1 = 511;
        float acc = 0.f;
        for (int k = k0; k <= k1; k++)
            acc = fmaf(s[t + k - 255], s[k], acc);
        r0[t] = acc; i0[t] = 0.f;
    }

    float *orr, *oi;
    block_fft512(r0, i0, r1, i1, tid, -1.f, orr, oi);

    const float SC = 0.044194173824159216f / 256.0f;
    for (int n = tid; n < NF_; n += 256) {
        g_csd_re[b * NF_ + n] = orr[n] * SC;
        g_csd_im[b * NF_ + n] = oi[n]  * SC;
    }
}

// ---------------- kernel 2: rfft + csd, features, proj -> g_flat (tf32), heads -> g_new ----------------
__global__ void k_fftproj(const float* __restrict__ x,
                          const float* __restrict__ Wp,
                          const float* __restrict__ bp,
                          const float* __restrict__ mag_w,
                          const float* __restrict__ mag_b,
                          const float* __restrict__ ph_w,
                          const float* __restrict__ ph_b)
{
    __shared__ float r0[512], i0[512], r1[512], i1[512];
    __shared__ __align__(16) float wp_s[256];
    __shared__ __align__(16) float bp_s[64];

    int m = blockIdx.x;
    int b = m >> 4, f = m & 15;
    int tid = threadIdx.x;

    if (tid < 256) wp_s[tid] = Wp[tid];
    if (tid < 64)  bp_s[tid] = bp[tid];

    for (int t = tid; t < 512; t += 256) {
        r0[t] = x[((size_t)(b * 512 + t)) * 16 + f];
        i0[t] = 0.f;
    }

    float *orr, *oi;
    block_fft512(r0, i0, r1, i1, tid, -1.f, orr, oi);

    const float SC = 0.044194173824159216f;
    for (int n = tid; n < NF_; n += 256) {
        float re = orr[n] * SC + g_csd_re[b * NF_ + n];
        float im = oi[n]  * SC + g_csd_im[b * NF_ + n];
        orr[n] = re; oi[n] = im;
        g_fft_re[(size_t)m * NF_ + n] = re;
        g_fft_im[(size_t)m * NF_ + n] = im;
    }
    __syncthreads();

    for (int n = tid; n < NF_; n += 256) {
        float re = orr[n], im = oi[n];
        float mag = sqrtf(re * re + im * im);
        float sa, ca;
        if (mag > 0.f) { float inv = 1.f / mag; sa = im * inv; ca = re * inv; }
        else           { sa = 0.f; ca = 1.f; }
        float fr = (float)n * 0.1953125f;

        float4* dst = (float4*)(g_flat + (size_t)m * K_ + (size_t)n * 64);
        const float4* mw = (const float4*)(mag_w + (size_t)n * 64);
        const float4* pw = (const float4*)(ph_w  + (size_t)n * 64);
        float dm = 0.f, dp = 0.f;
#pragma unroll
        for (int q = 0; q < 16; q++) {
            float4 w0 = *(const float4*)&wp_s[q * 4];
            float4 w1 = *(const float4*)&wp_s[64 + q * 4];
            float4 w2 = *(const float4*)&wp_s[128 + q * 4];
            float4 w3 = *(const float4*)&wp_s[192 + q * 4];
            float4 bb = *(const float4*)&bp_s[q * 4];
            float4 v;
            v.x = fmaxf(fmaf(mag, w0.x, fmaf(sa, w1.x, fmaf(ca, w2.x, fmaf(fr, w3.x, bb.x)))), 0.f);
            v.y = fmaxf(fmaf(mag, w0.y, fmaf(sa, w1.y, fmaf(ca, w2.y, fmaf(fr, w3.y, bb.y)))), 0.f);
            v.z = fmaxf(fmaf(mag, w0.z, fmaf(sa, w1.z, fmaf(ca, w2.z, fmaf(fr, w3.z, bb.z)))), 0.f);
            v.w = fmaxf(fmaf(mag, w0.w, fmaf(sa, w1.w, fmaf(ca, w2.w, fmaf(fr, w3.w, bb.w)))), 0.f);
            float4 vt;
            vt.x = f2tf32(v.x); vt.y = f2tf32(v.y); vt.z = f2tf32(v.z); vt.w = f2tf32(v.w);
            dst[q] = vt;                    // rounded copy for tensor GEMM
            float4 a = __ldg(&mw[q]);
            float4 c = __ldg(&pw[q]);
            dm = fmaf(v.x, a.x, dm); dm = fmaf(v.y, a.y, dm);
            dm = fmaf(v.z, a.z, dm); dm = fmaf(v.w, a.w, dm);
            dp = fmaf(v.x, c.x, dp); dp = fmaf(v.y, c.y, dp);
            dp = fmaf(v.z, c.z, dp); dp = fmaf(v.w, c.w, dp);
        }
        float mo  = fmaxf(dm + __ldg(&mag_b[n]), 0.f);
        float phv = 6.283185307179586f / (1.f + expf(-(dp + __ldg(&ph_b[n]))));
        float sp, cp;
        sincosf(phv, &sp, &cp);
        g_new_re[(size_t)m * NF_ + n] = mo * cp;
        g_new_im[(size_t)m * NF_ + n] = mo * sp;
    }
}

// ---------------- kernel 3a: transpose W_gate [K][257] -> g_wt [288][K] (tf32, zero pad) ----------------
__global__ void k_transpose(const float* __restrict__ Wg)
{
    __shared__ float tile[32][33];
    int tid = threadIdx.x;
    int tx = tid & 31, ty = tid >> 5;
    int kb = blockIdx.x * 32, nb = blockIdx.y * 32;
#pragma unroll
    for (int r = 0; r < 4; r++) {
        int kk = kb + ty + r * 8;
        int nn = nb + tx;
        tile[ty + r * 8][tx] = (nn < NF_) ? f2tf32(Wg[(size_t)kk * NF_ + nn]) : 0.f;
    }
    __syncthreads();
#pragma unroll
    for (int r = 0; r < 4; r++) {
        int nn = nb + ty + r * 8;
        int kk = kb + tx;
        g_wt[(size_t)nn * K_ + kk] = tile[tx][ty + r * 8];
    }
}

// ---------------- kernel 3b: tf32 mma.sync split-K GEMM ----------------
// CTA tile 128x96x32, 8 warps (4x2), warp tile 32x48 (2x6 m16n8k8), 3-stage cp.async.
#define BK_       32
#define NCHUNK_   (K_/BK_)        // 514
#define ASTRIDE_  36
#define A_WORDS_  (128*ASTRIDE_)  // 4608
#define B_WORDS_  (96*ASTRIDE_)   // 3456
#define STG_WORDS_ (A_WORDS_+B_WORDS_)  // 8064
#define GEMM_SMEM_ (3*STG_WORDS_*4)     // 96768 bytes

__device__ __forceinline__ void load_chunk(uint32_t sbase, const float* __restrict__ Ab,
                                           const float* __restrict__ Bb, int kbase, int tid)
{
    uint32_t sA = sbase;
    uint32_t sB = sbase + A_WORDS_ * 4;
#pragma unroll
    for (int i = 0; i < 4; i++) {             // A: 128 rows x 8 float4
        int g = tid + (i << 8);
        int r = g >> 3, c = g & 7;
        CP_ASYNC16(sA + (uint32_t)(r * (ASTRIDE_*4) + c * 16),
                   Ab + (size_t)r * K_ + kbase + c * 4);
    }
#pragma unroll
    for (int i = 0; i < 3; i++) {             // B: 96 rows x 8 float4
        int g = tid + (i << 8);
        int r = g >> 3, c = g & 7;
        CP_ASYNC16(sB + (uint32_t)(r * (ASTRIDE_*4) + c * 16),
                   Bb + (size_t)r * K_ + kbase + c * 4);
    }
    asm volatile("cp.async.commit_group;\n" ::: "memory");
}

__global__ void __launch_bounds__(256, 2) k_gemm()
{
    extern __shared__ __align__(16) float smem[];

    int tid = threadIdx.x;
    int nt0 = blockIdx.x;           // 0..2
    int m0  = blockIdx.y * 128;
    int s   = blockIdx.z;           // split 0..SPLITS_-1
    const float* Ab = g_flat + (size_t)m0 * K_;
    const float* Bb = g_wt + (size_t)(nt0 * 96) * K_;

    int warp = tid >> 5, lane = tid & 31;
    int wm = warp & 3;
    int wn = warp >> 2;
    int lr = lane >> 2, lc = lane & 3;

    float acc[2][6][4];
#pragma unroll
    for (int i = 0; i < 2; i++)
#pragma unroll
        for (int j = 0; j < 6; j++)
#pragma unroll
            for (int q = 0; q < 4; q++) acc[i][j][q] = 0.f;

    const int cs = (s * NCHUNK_) / SPLITS_;
    const int ce = ((s + 1) * NCHUNK_) / SPLITS_;
    const int CN = ce - cs;

    uint32_t sb = smem_u32(smem);

    load_chunk(sb + 0 * STG_WORDS_ * 4, Ab, Bb, (cs + 0) * BK_, tid);
    load_chunk(sb + 1 * STG_WORDS_ * 4, Ab, Bb, (cs + 1) * BK_, tid);

    for (int i = 0; i < CN; i++) {
        if (i + 2 < CN)
            load_chunk(sb + ((i + 2) % 3) * STG_WORDS_ * 4, Ab, Bb, (cs + i + 2) * BK_, tid);
        else
            asm volatile("cp.async.commit_group;\n" ::: "memory");
        asm volatile("cp.async.wait_group 2;\n" ::: "memory");
        __syncthreads();

        const float* sA = smem + ((size_t)(i % 3)) * STG_WORDS_;
        const float* sB = sA + A_WORDS_;
        const uint32_t* Awp = (const uint32_t*)(sA + (wm * 32 + lr) * ASTRIDE_ + lc);
        const uint32_t* Bwp = (const uint32_t*)(sB + (wn * 48 + lr) * ASTRIDE_ + lc);

#pragma unroll
        for (int kt = 0; kt < 4; kt++) {
            uint32_t a[2][4];
#pragma unroll
            for (int mt = 0; mt < 2; mt++) {
                const uint32_t* p = Awp + mt * 16 * ASTRIDE_ + kt * 8;
                a[mt][0] = p[0];
                a[mt][1] = p[8 * ASTRIDE_];
                a[mt][2] = p[4];
                a[mt][3] = p[8 * ASTRIDE_ + 4];
            }
            uint32_t bfr[6][2];
#pragma unroll
            for (int nt = 0; nt < 6; nt++) {
                const uint32_t* p = Bwp + nt * 8 * ASTRIDE_ + kt * 8;
                bfr[nt][0] = p[0];
                bfr[nt][1] = p[4];
            }
#pragma unroll
            for (int mt = 0; mt < 2; mt++)
#pragma unroll
                for (int nt = 0; nt < 6; nt++)
                    mma_tf32(acc[mt][nt], a[mt], bfr[nt]);
        }
        __syncthreads();
    }

    float* P = g_part[s];
#pragma unroll
    for (int mt = 0; mt < 2; mt++) {
        int row = m0 + wm * 32 + mt * 16 + lr;
#pragma unroll
        for (int nt = 0; nt < 6; nt++) {
            int col = nt0 * 96 + wn * 48 + nt * 8 + lc * 2;
            float2 v0 = make_float2(acc[mt][nt][0], acc[mt][nt][1]);
            float2 v1 = make_float2(acc[mt][nt][2], acc[mt][nt][3]);
            *(float2*)(P + (size_t)row * NPAD_ + col)       = v0;
            *(float2*)(P + (size_t)(row + 8) * NPAD_ + col) = v1;
        }
    }
}

// ---------------- kernel 4: fused split-K reduce + gate + blend + irfft + residual ----------------
__global__ void k_irfft(const float* __restrict__ x, float* __restrict__ out,
                        const float* __restrict__ bg)
{
    __shared__ float r0[512], i0[512], r1[512], i1[512];
    __shared__ float fre[NF_], fim[NF_];
    int m = blockIdx.x;
    int b = m >> 4, f = m & 15;
    int tid = threadIdx.x;

    // reduce partials, gate, blend
    for (int n = tid; n < NF_; n += 256) {
        size_t pofs = (size_t)m * NPAD_ + n;
        float acc = 0.f;
#pragma unroll
        for (int s = 0; s < SPLITS_; s++) acc += g_part[s][pofs];
        float g = acc + __ldg(&bg[n]);
        float s1 = 1.f / (1.f + expf(-g));
        g = g * s1;                              // SiLU
        float w = 1.f / (1.f + expf(-g));        // gate weight
        size_t id = (size_t)m * NF_ + n;
        fre[n] = w * g_new_re[id] + (1.f - w) * g_fft_re[id];
        fim[n] = w * g_new_im[id] + (1.f - w) * g_fft_im[id];
    }
    __syncthreads();

    for (int n = tid; n < 512; n += 256) {
        float re, im;
        if (n == 0)        { re = fre[0];   im = 0.f; }
        else if (n < 256)  { re = fre[n];   im = fim[n]; }
        else if (n == 256) { re = fre[256]; im = 0.f; }
        else               { re = fre[512 - n]; im = -fim[512 - n]; }
        r0[n] = re; i0[n] = im;
    }

    float *orr, *oi;
    block_fft512(r0, i0, r1, i1, tid, +1.f, orr, oi);

    const float SC = 0.044194173824159216f;
    for (int t = tid; t < 512; t += 256) {
        size_t xi = ((size_t)(b * 512 + t)) * 16 + f;
        out[xi] = orr[t] * SC + x[xi];
    }
}

// ---------------- kernel 5: LayerNorm over F=16 ----------------
__global__ void k_ln(float* __restrict__ out,
                     const float* __restrict__ gamma, const float* __restrict__ beta)
{
    int row = blockIdx.x * blockDim.x + threadIdx.x;
    if (row >= B_ * H_) return;
    float* p = out + (size_t)row * 16;
    float v[16];
    float4* pv = (float4*)p;
#pragma unroll
    for (int q = 0; q < 4; q++) {
        float4 t = pv[q];
        v[q * 4 + 0] = t.x; v[q * 4 + 1] = t.y; v[q * 4 + 2] = t.z; v[q * 4 + 3] = t.w;
    }
    float sm = 0.f;
#pragma unroll
    for (int i = 0; i < 16; i++) sm += v[i];
    float mu = sm * (1.f / 16.f);
    float ss = 0.f;
#pragma unroll
    for (int i = 0; i < 16; i++) { float d = v[i] - mu; ss = fmaf(d, d, ss); }
    float inv = 1.f / sqrtf(ss * (1.f / 16.f) + 1e-5f);
#pragma unroll
    for (int i = 0; i < 16; i++)
        v[i] = (v[i] - mu) * inv * __ldg(&gamma[i]) + __ldg(&beta[i]);
#pragma unroll
    for (int q = 0; q < 4; q++) {
        float4 t;
        t.x = v[q * 4 + 0]; t.y = v[q * 4 + 1]; t.z = v[q * 4 + 2]; t.w = v[q * 4 + 3];
        pv[q] = t;
    }
}

// ---------------- launcher ----------------
extern "C" void kernel_launch(void* const* d_in, const int* in_sizes, int n_in,
                              void* d_out, int out_size)
{
    const float* x       = (const float*)d_in[0];
    const float* W_proj  = (const float*)d_in[1];
    const float* b_proj  = (const float*)d_in[2];
    const float* W_gate  = (const float*)d_in[3];
    const float* b_gate  = (const float*)d_in[4];
    const float* mag_w   = (const float*)d_in[5];
    const float* mag_b   = (const float*)d_in[6];
    const float* phase_w = (const float*)d_in[7];
    const float* phase_b = (const float*)d_in[8];
    const float* ln_g    = (const float*)d_in[9];
    const float* ln_b    = (const float*)d_in[10];
    float* out = (float*)d_out;

    cudaFuncSetAttribute(k_gemm, cudaFuncAttributeMaxDynamicSharedMemorySize, GEMM_SMEM_);

    k_csd<<<B_, 256>>>(x);
    k_fftproj<<<M_, 256>>>(x, W_proj, b_proj, mag_w, mag_b, phase_w, phase_b);
    k_transpose<<<dim3(K_ / 32, NPAD_ / 32), 256>>>(W_gate);
    k_gemm<<<dim3(3, 16, SPLITS_), 256, GEMM_SMEM_>>>();
    k_irfft<<<M_, 256>>>(x, out, b_gate);
    k_ln<<<(B_ * H_ + 255) / 256, 256>>>(out, ln_g, ln_b);
}

// round 5
// speedup vs baseline: 3.5105x; 1.2453x over previous
#include <cuda_runtime.h>
#include <cuda_bf16.h>
#include <math.h>
#include <stdint.h>

#define B_    128
#define H_    512
#define F_    16
#define HID_  64
#define NF_   257
#define M_    (B_*F_)       // 2048
#define K_    (NF_*HID_)    // 16448
#define NPAD_ 288
#define SPLITS_ 6

// ---------------- scratch (static device memory; no allocations) ----------------
__device__ __align__(128) float g_csd_re[B_*NF_];
__device__ __align__(128) float g_csd_im[B_*NF_];
__device__ __align__(128) float g_fft_re[M_*NF_];
__device__ __align__(128) float g_fft_im[M_*NF_];
__device__ __align__(128) float g_new_re[M_*NF_];
__device__ __align__(128) float g_new_im[M_*NF_];
__device__ __align__(128) __nv_bfloat16 g_wt[(size_t)NPAD_*K_];   // W_gate^T [n][k] bf16
__device__ __align__(128) float g_part[SPLITS_][(size_t)M_*NPAD_];
__device__ __align__(128) __nv_bfloat16 g_flat[(size_t)M_*K_];    // proj bf16, [m][n*64+h]

// ================= helpers =================
#define CP_ASYNC16(dst, src) \
    asm volatile("cp.async.cg.shared.global [%0], [%1], 16;\n" :: "r"(dst), "l"(src))
__device__ __forceinline__ uint32_t smem_u32(const void* p) {
    uint32_t a;
    asm("{ .reg .u64 t; cvta.to.shared.u64 t, %1; cvt.u32.u64 %0, t; }" : "=r"(a) : "l"(p));
    return a;
}
__device__ __forceinline__ void mma_bf16(float c[4], const uint32_t a[4], const uint32_t b[2]) {
    asm volatile(
        "mma.sync.aligned.m16n8k16.row.col.f32.bf16.bf16.f32 "
        "{%0,%1,%2,%3}, {%4,%5,%6,%7}, {%8,%9}, {%0,%1,%2,%3};"
        : "+f"(c[0]), "+f"(c[1]), "+f"(c[2]), "+f"(c[3])
        : "r"(a[0]), "r"(a[1]), "r"(a[2]), "r"(a[3]), "r"(b[0]), "r"(b[1]));
}
__device__ __forceinline__ uint32_t packbf(float x, float y) {
    __nv_bfloat162 h = __float22bfloat162_rn(make_float2(x, y));
    return *(uint32_t*)&h;
}

// ---------------- in-block 512-pt Stockham FFT (256 threads) ----------------
__device__ __forceinline__ void block_fft512(float* r0, float* i0, float* r1, float* i1,
                                             int tid, float sign, float*& outr, float*& outi)
{
    float *ar = r0, *ai = i0, *br = r1, *bi = i1;
    int l = 256, logm = 0;
#pragma unroll
    for (int st = 0; st < 9; st++) {
        __syncthreads();
        int m = 1 << logm;
        int j = tid >> logm;
        int k = tid & (m - 1);
        float c0r = ar[tid],       c0i = ai[tid];
        float c1r = ar[tid + 256], c1i = ai[tid + 256];
        float sr = c0r - c1r, si = c0i - c1i;
        float invl = 1.0f / (float)l;
        float ang = sign * 3.14159265358979323846f * (float)j * invl;
        float ws, wc;
        sincosf(ang, &ws, &wc);
        int o0 = k + (j << (logm + 1));
        br[o0]     = c0r + c1r;
        bi[o0]     = c0i + c1i;
        br[o0 + m] = wc * sr - ws * si;
        bi[o0 + m] = wc * si + ws * sr;
        float* t;
        t = ar; ar = br; br = t;
        t = ai; ai = bi; bi = t;
        l >>= 1; logm++;
    }
    __syncthreads();
    outr = ar; outi = ai;
}

// ---------------- kernel 1: CSD via channel-sum autocorrelation ----------------
__global__ void k_csd(const float* __restrict__ x)
{
    __shared__ float s[512];
    __shared__ float r0[512], i0[512], r1[512], i1[512];
    int b = blockIdx.x, tid = threadIdx.x;

    for (int t = tid; t < 512; t += 256) {
        const float4* p = (const float4*)(x + ((size_t)(b * 512 + t)) * 16);
        float4 a = p[0], bb = p[1], c = p[2], d = p[3];
        s[t] = (a.x + a.y + a.z + a.w) + (bb.x + bb.y + bb.z + bb.w)
             + (c.x + c.y + c.z + c.w) + (d.x + d.y + d.z + d.w);
    }
    __syncthreads();

    for (int t = tid; t < 512; t += 256) {
        int k0 = 255 - t; if (k0 < 0)   k0 = 0;
        int k1 = 766 - t; if (k1 > 511) k1 = 511;
        float acc = 0.f;
        for (int k = k0; k <= k1; k++)
            acc = fmaf(s[t + k - 255], s[k], acc);
        r0[t] = acc; i0[t] = 0.f;
    }

    float *orr, *oi;
    block_fft512(r0, i0, r1, i1, tid, -1.f, orr, oi);

    const float SC = 0.044194173824159216f / 256.0f;
    for (int n = tid; n < NF_; n += 256) {
        g_csd_re[b * NF_ + n] = orr[n] * SC;
        g_csd_im[b * NF_ + n] = oi[n]  * SC;
    }
}

// ---------------- kernel 2: rfft + csd, features, proj -> g_flat (bf16), heads -> g_new ----------------
__global__ void k_fftproj(const float* __restrict__ x,
                          const float* __restrict__ Wp,
                          const float* __restrict__ bp,
                          const float* __restrict__ mag_w,
                          const float* __restrict__ mag_b,
                          const float* __restrict__ ph_w,
                          const float* __restrict__ ph_b)
{
    __shared__ float r0[512], i0[512], r1[512], i1[512];
    __shared__ __align__(16) float wp_s[256];
    __shared__ __align__(16) float bp_s[64];

    int m = blockIdx.x;
    int b = m >> 4, f = m & 15;
    int tid = threadIdx.x;

    if (tid < 256) wp_s[tid] = Wp[tid];
    if (tid < 64)  bp_s[tid] = bp[tid];

    for (int t = tid; t < 512; t += 256) {
        r0[t] = x[((size_t)(b * 512 + t)) * 16 + f];
        i0[t] = 0.f;
    }

    float *orr, *oi;
    block_fft512(r0, i0, r1, i1, tid, -1.f, orr, oi);

    const float SC = 0.044194173824159216f;
    for (int n = tid; n < NF_; n += 256) {
        float re = orr[n] * SC + g_csd_re[b * NF_ + n];
        float im = oi[n]  * SC + g_csd_im[b * NF_ + n];
        orr[n] = re; oi[n] = im;
        g_fft_re[(size_t)m * NF_ + n] = re;
        g_fft_im[(size_t)m * NF_ + n] = im;
    }
    __syncthreads();

    for (int n = tid; n < NF_; n += 256) {
        float re = orr[n], im = oi[n];
        float mag = sqrtf(re * re + im * im);
        float sa, ca;
        if (mag > 0.f) { float inv = 1.f / mag; sa = im * inv; ca = re * inv; }
        else           { sa = 0.f; ca = 1.f; }
        float fr = (float)n * 0.1953125f;

        uint32_t* dst = (uint32_t*)(g_flat + (size_t)m * K_ + (size_t)n * 64);
        const float4* mw = (const float4*)(mag_w + (size_t)n * 64);
        const float4* pw = (const float4*)(ph_w  + (size_t)n * 64);
        float dm = 0.f, dp = 0.f;
#pragma unroll
        for (int q = 0; q < 16; q++) {
            float4 w0 = *(const float4*)&wp_s[q * 4];
            float4 w1 = *(const float4*)&wp_s[64 + q * 4];
            float4 w2 = *(const float4*)&wp_s[128 + q * 4];
            float4 w3 = *(const float4*)&wp_s[192 + q * 4];
            float4 bb = *(const float4*)&bp_s[q * 4];
            float4 v;
            v.x = fmaxf(fmaf(mag, w0.x, fmaf(sa, w1.x, fmaf(ca, w2.x, fmaf(fr, w3.x, bb.x)))), 0.f);
            v.y = fmaxf(fmaf(mag, w0.y, fmaf(sa, w1.y, fmaf(ca, w2.y, fmaf(fr, w3.y, bb.y)))), 0.f);
            v.z = fmaxf(fmaf(mag, w0.z, fmaf(sa, w1.z, fmaf(ca, w2.z, fmaf(fr, w3.z, bb.z)))), 0.f);
            v.w = fmaxf(fmaf(mag, w0.w, fmaf(sa, w1.w, fmaf(ca, w2.w, fmaf(fr, w3.w, bb.w)))), 0.f);
            dst[q * 2]     = packbf(v.x, v.y);
            dst[q * 2 + 1] = packbf(v.z, v.w);
            float4 a = __ldg(&mw[q]);
            float4 c = __ldg(&pw[q]);
            dm = fmaf(v.x, a.x, dm); dm = fmaf(v.y, a.y, dm);
            dm = fmaf(v.z, a.z, dm); dm = fmaf(v.w, a.w, dm);
            dp = fmaf(v.x, c.x, dp); dp = fmaf(v.y, c.y, dp);
            dp = fmaf(v.z, c.z, dp); dp = fmaf(v.w, c.w, dp);
        }
        float mo  = fmaxf(dm + __ldg(&mag_b[n]), 0.f);
        float phv = 6.283185307179586f / (1.f + expf(-(dp + __ldg(&ph_b[n]))));
        float sp, cp;
        sincosf(phv, &sp, &cp);
        g_new_re[(size_t)m * NF_ + n] = mo * cp;
        g_new_im[(size_t)m * NF_ + n] = mo * sp;
    }
}

// ---------------- kernel 3a: transpose W_gate [K][257] -> g_wt [288][K] (bf16, zero pad) ----------------
__global__ void k_transpose(const float* __restrict__ Wg)
{
    __shared__ float tile[32][33];
    int tid = threadIdx.x;
    int tx = tid & 31, ty = tid >> 5;
    int kb = blockIdx.x * 32, nb = blockIdx.y * 32;
#pragma unroll
    for (int r = 0; r < 4; r++) {
        int kk = kb + ty + r * 8;
        int nn = nb + tx;
        tile[ty + r * 8][tx] = (nn < NF_) ? Wg[(size_t)kk * NF_ + nn] : 0.f;
    }
    __syncthreads();
#pragma unroll
    for (int r = 0; r < 4; r++) {
        int nn = nb + ty + r * 8;
        int kk = kb + tx;
        g_wt[(size_t)nn * K_ + kk] = __float2bfloat16(tile[tx][ty + r * 8]);
    }
}

// ---------------- kernel 3b: bf16 mma.sync (m16n8k16) split-K GEMM ----------------
// CTA tile 128x96x64(bf16), 8 warps (4x2), warp tile 32x48, 3-stage cp.async.
#define BK_       64              // bf16 elements per K-chunk
#define NCHUNK_   (K_/BK_)        // 257
#define ASTRIDE_W 36              // words (u32) per row = 72 bf16 (64 + 8 pad)
#define A_WORDS_  (128*ASTRIDE_W) // 4608 words
#define B_WORDS_  (96*ASTRIDE_W)  // 3456 words
#define STG_WORDS_ (A_WORDS_+B_WORDS_)  // 8064 words = 32256 B
#define GEMM_SMEM_ (3*STG_WORDS_*4)     // 96768 bytes

__device__ __forceinline__ void load_chunk(uint32_t sbase, const __nv_bfloat16* __restrict__ Ab,
                                           const __nv_bfloat16* __restrict__ Bb, int kbase, int tid)
{
    uint32_t sA = sbase;
    uint32_t sB = sbase + A_WORDS_ * 4;
#pragma unroll
    for (int i = 0; i < 4; i++) {             // A: 128 rows x 8 x 16B (64 bf16/row)
        int g = tid + (i << 8);
        int r = g >> 3, c = g & 7;
        CP_ASYNC16(sA + (uint32_t)(r * (ASTRIDE_W*4) + c * 16),
                   Ab + (size_t)r * K_ + kbase + c * 8);
    }
#pragma unroll
    for (int i = 0; i < 3; i++) {             // B: 96 rows x 8 x 16B
        int g = tid + (i << 8);
        int r = g >> 3, c = g & 7;
        CP_ASYNC16(sB + (uint32_t)(r * (ASTRIDE_W*4) + c * 16),
                   Bb + (size_t)r * K_ + kbase + c * 8);
    }
    asm volatile("cp.async.commit_group;\n" ::: "memory");
}

__global__ void __launch_bounds__(256, 2) k_gemm()
{
    extern __shared__ __align__(16) uint32_t smem[];

    int tid = threadIdx.x;
    int nt0 = blockIdx.x;           // 0..2
    int m0  = blockIdx.y * 128;
    int s   = blockIdx.z;           // split 0..SPLITS_-1
    const __nv_bfloat16* Ab = g_flat + (size_t)m0 * K_;
    const __nv_bfloat16* Bb = g_wt + (size_t)(nt0 * 96) * K_;

    int warp = tid >> 5, lane = tid & 31;
    int wm = warp & 3;
    int wn = warp >> 2;
    int lr = lane >> 2, lc = lane & 3;

    float acc[2][6][4];
#pragma unroll
    for (int i = 0; i < 2; i++)
#pragma unroll
        for (int j = 0; j < 6; j++)
#pragma unroll
            for (int q = 0; q < 4; q++) acc[i][j][q] = 0.f;

    const int cs = (s * NCHUNK_) / SPLITS_;
    const int ce = ((s + 1) * NCHUNK_) / SPLITS_;
    const int CN = ce - cs;

    uint32_t sb = smem_u32(smem);

    load_chunk(sb + 0 * STG_WORDS_ * 4, Ab, Bb, (cs + 0) * BK_, tid);
    load_chunk(sb + 1 * STG_WORDS_ * 4, Ab, Bb, (cs + 1) * BK_, tid);

    for (int i = 0; i < CN; i++) {
        if (i + 2 < CN)
            load_chunk(sb + ((i + 2) % 3) * STG_WORDS_ * 4, Ab, Bb, (cs + i + 2) * BK_, tid);
        else
            asm volatile("cp.async.commit_group;\n" ::: "memory");
        asm volatile("cp.async.wait_group 2;\n" ::: "memory");
        __syncthreads();

        const uint32_t* sA = smem + ((size_t)(i % 3)) * STG_WORDS_;
        const uint32_t* sB = sA + A_WORDS_;
        const uint32_t* Awp = sA + (wm * 32 + lr) * ASTRIDE_W + lc;
        const uint32_t* Bwp = sB + (wn * 48 + lr) * ASTRIDE_W + lc;

#pragma unroll
        for (int kt = 0; kt < 4; kt++) {       // 4 x k16 = 64 bf16
            uint32_t a[2][4];
#pragma unroll
            for (int mt = 0; mt < 2; mt++) {
                const uint32_t* p = Awp + mt * 16 * ASTRIDE_W + kt * 8;
                a[mt][0] = p[0];
                a[mt][1] = p[8 * ASTRIDE_W];
                a[mt][2] = p[4];
                a[mt][3] = p[8 * ASTRIDE_W + 4];
            }
            uint32_t bfr[6][2];
#pragma unroll
            for (int nt = 0; nt < 6; nt++) {
                const uint32_t* p = Bwp + nt * 8 * ASTRIDE_W + kt * 8;
                bfr[nt][0] = p[0];
                bfr[nt][1] = p[4];
            }
#pragma unroll
            for (int mt = 0; mt < 2; mt++)
#pragma unroll
                for (int nt = 0; nt < 6; nt++)
                    mma_bf16(acc[mt][nt], a[mt], bfr[nt]);
        }
        __syncthreads();
    }

    float* P = g_part[s];
#pragma unroll
    for (int mt = 0; mt < 2; mt++) {
        int row = m0 + wm * 32 + mt * 16 + lr;
#pragma unroll
        for (int nt = 0; nt < 6; nt++) {
            int col = nt0 * 96 + wn * 48 + nt * 8 + lc * 2;
            float2 v0 = make_float2(acc[mt][nt][0], acc[mt][nt][1]);
            float2 v1 = make_float2(acc[mt][nt][2], acc[mt][nt][3]);
            *(float2*)(P + (size_t)row * NPAD_ + col)       = v0;
            *(float2*)(P + (size_t)(row + 8) * NPAD_ + col) = v1;
        }
    }
}

// ---------------- kernel 4: fused split-K reduce + gate + blend + irfft + residual ----------------
__global__ void k_irfft(const float* __restrict__ x, float* __restrict__ out,
                        const float* __restrict__ bg)
{
    __shared__ float r0[512], i0[512], r1[512], i1[512];
    __shared__ float fre[NF_], fim[NF_];
    int m = blockIdx.x;
    int b = m >> 4, f = m & 15;
    int tid = threadIdx.x;

    for (int n = tid; n < NF_; n += 256) {
        size_t pofs = (size_t)m * NPAD_ + n;
        float acc = 0.f;
#pragma unroll
        for (int s = 0; s < SPLITS_; s++) acc += g_part[s][pofs];
        float g = acc + __ldg(&bg[n]);
        float s1 = 1.f / (1.f + expf(-g));
        g = g * s1;                              // SiLU
        float w = 1.f / (1.f + expf(-g));        // gate weight
        size_t id = (size_t)m * NF_ + n;
        fre[n] = w * g_new_re[id] + (1.f - w) * g_fft_re[id];
        fim[n] = w * g_new_im[id] + (1.f - w) * g_fft_im[id];
    }
    __syncthreads();

    for (int n = tid; n < 512; n += 256) {
        float re, im;
        if (n == 0)        { re = fre[0];   im = 0.f; }
        else if (n < 256)  { re = fre[n];   im = fim[n]; }
        else if (n == 256) { re = fre[256]; im = 0.f; }
        else               { re = fre[512 - n]; im = -fim[512 - n]; }
        r0[n] = re; i0[n] = im;
    }

    float *orr, *oi;
    block_fft512(r0, i0, r1, i1, tid, +1.f, orr, oi);

    const float SC = 0.044194173824159216f;
    for (int t = tid; t < 512; t += 256) {
        size_t xi = ((size_t)(b * 512 + t)) * 16 + f;
        out[xi] = orr[t] * SC + x[xi];
    }
}

// ---------------- kernel 5: LayerNorm over F=16 ----------------
__global__ void k_ln(float* __restrict__ out,
                     const float* __restrict__ gamma, const float* __restrict__ beta)
{
    int row = blockIdx.x * blockDim.x + threadIdx.x;
    if (row >= B_ * H_) return;
    float* p = out + (size_t)row * 16;
    float v[16];
    float4* pv = (float4*)p;
#pragma unroll
    for (int q = 0; q < 4; q++) {
        float4 t = pv[q];
        v[q * 4 + 0] = t.x; v[q * 4 + 1] = t.y; v[q * 4 + 2] = t.z; v[q * 4 + 3] = t.w;
    }
    float sm = 0.f;
#pragma unroll
    for (int i = 0; i < 16; i++) sm += v[i];
    float mu = sm * (1.f / 16.f);
    float ss = 0.f;
#pragma unroll
    for (int i = 0; i < 16; i++) { float d = v[i] - mu; ss = fmaf(d, d, ss); }
    float inv = 1.f / sqrtf(ss * (1.f / 16.f) + 1e-5f);
#pragma unroll
    for (int i = 0; i < 16; i++)
        v[i] = (v[i] - mu) * inv * __ldg(&gamma[i]) + __ldg(&beta[i]);
#pragma unroll
    for (int q = 0; q < 4; q++) {
        float4 t;
        t.x = v[q * 4 + 0]; t.y = v[q * 4 + 1]; t.z = v[q * 4 + 2]; t.w = v[q * 4 + 3];
        pv[q] = t;
    }
}

// ---------------- launcher ----------------
extern "C" void kernel_launch(void* const* d_in, const int* in_sizes, int n_in,
                              void* d_out, int out_size)
{
    const float* x       = (const float*)d_in[0];
    const float* W_proj  = (const float*)d_in[1];
    const float* b_proj  = (const float*)d_in[2];
    const float* W_gate  = (const float*)d_in[3];
    const float* b_gate  = (const float*)d_in[4];
    const float* mag_w   = (const float*)d_in[5];
    const float* mag_b   = (const float*)d_in[6];
    const float* phase_w = (const float*)d_in[7];
    const float* phase_b = (const float*)d_in[8];
    const float* ln_g    = (const float*)d_in[9];
    const float* ln_b    = (const float*)d_in[10];
    float* out = (float*)d_out;

    cudaFuncSetAttribute(k_gemm, cudaFuncAttributeMaxDynamicSharedMemorySize, GEMM_SMEM_);

    k_csd<<<B_, 256>>>(x);
    k_fftproj<<<M_, 256>>>(x, W_proj, b_proj, mag_w, mag_b, phase_w, phase_b);
    k_transpose<<<dim3(K_ / 32, NPAD_ / 32), 256>>>(W_gate);
    k_gemm<<<dim3(3, 16, SPLITS_), 256, GEMM_SMEM_>>>();
    k_irfft<<<M_, 256>>>(x, out, b_gate);
    k_ln<<<(B_ * H_ + 255) / 256, 256>>>(out, ln_g, ln_b);
}

// round 6
// speedup vs baseline: 3.6515x; 1.0401x over previous
#include <cuda_runtime.h>
#include <cuda_bf16.h>
#include <math.h>
#include <stdint.h>

#define B_    128
#define H_    512
#define F_    16
#define HID_  64
#define NF_   257
#define M_    (B_*F_)       // 2048
#define K_    (NF_*HID_)    // 16448
#define NPAD_ 288
#define SPLITS_ 6

// ---------------- scratch (static device memory; no allocations) ----------------
__device__ __align__(128) float g_csd_re[B_*NF_];
__device__ __align__(128) float g_csd_im[B_*NF_];
__device__ __align__(128) float g_fft_re[M_*NF_];
__device__ __align__(128) float g_fft_im[M_*NF_];
__device__ __align__(128) float g_new_re[M_*NF_];
__device__ __align__(128) float g_new_im[M_*NF_];
__device__ __align__(128) __nv_bfloat16 g_wt[(size_t)NPAD_*K_];   // W_gate^T [n][k] bf16
__device__ __align__(128) float g_part[SPLITS_][(size_t)M_*NPAD_];
__device__ __align__(128) __nv_bfloat16 g_flat[(size_t)M_*K_];    // proj bf16, [m][n*64+h]

// ================= helpers =================
#define CP_ASYNC16(dst, src) \
    asm volatile("cp.async.cg.shared.global [%0], [%1], 16;\n" :: "r"(dst), "l"(src))
__device__ __forceinline__ uint32_t smem_u32(const void* p) {
    uint32_t a;
    asm("{ .reg .u64 t; cvta.to.shared.u64 t, %1; cvt.u32.u64 %0, t; }" : "=r"(a) : "l"(p));
    return a;
}
__device__ __forceinline__ void mma_bf16(float c[4], const uint32_t a[4], const uint32_t b[2]) {
    asm volatile(
        "mma.sync.aligned.m16n8k16.row.col.f32.bf16.bf16.f32 "
        "{%0,%1,%2,%3}, {%4,%5,%6,%7}, {%8,%9}, {%0,%1,%2,%3};"
        : "+f"(c[0]), "+f"(c[1]), "+f"(c[2]), "+f"(c[3])
        : "r"(a[0]), "r"(a[1]), "r"(a[2]), "r"(a[3]), "r"(b[0]), "r"(b[1]));
}
#define LDSM_X4(R0, R1, R2, R3, ADDR) \
    asm volatile("ldmatrix.sync.aligned.m8n8.x4.shared.b16 {%0,%1,%2,%3}, [%4];" \
        : "=r"(R0), "=r"(R1), "=r"(R2), "=r"(R3) : "r"(ADDR))
__device__ __forceinline__ uint32_t packbf(float x, float y) {
    __nv_bfloat162 h = __float22bfloat162_rn(make_float2(x, y));
    return *(uint32_t*)&h;
}
__device__ __forceinline__ float sigf(float x) {
    return __fdividef(1.f, 1.f + __expf(-x));
}

// ---------------- in-block 512-pt Stockham FFT, table twiddles (256 threads) ----------------
// tc/ts: shared 256-entry tables, ts pre-scaled by sign.
__device__ __forceinline__ void block_fft512(float* r0, float* i0, float* r1, float* i1,
                                             const float* tc, const float* ts,
                                             int tid, float*& outr, float*& outi)
{
    float *ar = r0, *ai = i0, *br = r1, *bi = i1;
#pragma unroll
    for (int st = 0; st < 9; st++) {
        __syncthreads();
        int m = 1 << st;
        int j = tid >> st;
        int k = tid & (m - 1);
        int idx = tid & ~(m - 1);          // = j << st
        float c0r = ar[tid],       c0i = ai[tid];
        float c1r = ar[tid + 256], c1i = ai[tid + 256];
        float sr = c0r - c1r, si = c0i - c1i;
        float wc = tc[idx], ws = ts[idx];
        int o0 = k + (j << (st + 1));
        br[o0]     = c0r + c1r;
        bi[o0]     = c0i + c1i;
        br[o0 + m] = wc * sr - ws * si;
        bi[o0 + m] = wc * si + ws * sr;
        float* t;
        t = ar; ar = br; br = t;
        t = ai; ai = bi; bi = t;
    }
    __syncthreads();
    outr = ar; outi = ai;
}
#define BUILD_TW(tc, ts, sign, tid) do { \
    float _s, _c; \
    sincosf((sign) * 3.14159265358979323846f * (float)(tid) * (1.0f/256.0f), &_s, &_c); \
    (tc)[tid] = _c; (ts)[tid] = _s; \
} while (0)

// ---------------- kernel 1: CSD via channel-sum autocorrelation ----------------
__global__ void k_csd(const float* __restrict__ x)
{
    __shared__ float s[512];
    __shared__ float r0[512], i0[512], r1[512], i1[512];
    __shared__ float tc[256], ts[256];
    int b = blockIdx.x, tid = threadIdx.x;

    BUILD_TW(tc, ts, -1.f, tid);

    for (int t = tid; t < 512; t += 256) {
        const float4* p = (const float4*)(x + ((size_t)(b * 512 + t)) * 16);
        float4 a = p[0], bb = p[1], c = p[2], d = p[3];
        s[t] = (a.x + a.y + a.z + a.w) + (bb.x + bb.y + bb.z + bb.w)
             + (c.x + c.y + c.z + c.w) + (d.x + d.y + d.z + d.w);
    }
    __syncthreads();

    for (int t = tid; t < 512; t += 256) {
        int k0 = 255 - t; if (k0 < 0)   k0 = 0;
        int k1 = 766 - t; if (k1 > 511) k1 = 511;
        float acc0 = 0.f, acc1 = 0.f;
        int k = k0;
        for (; k + 1 <= k1; k += 2) {
            acc0 = fmaf(s[t + k - 255],     s[k],     acc0);
            acc1 = fmaf(s[t + k - 254],     s[k + 1], acc1);
        }
        if (k <= k1) acc0 = fmaf(s[t + k - 255], s[k], acc0);
        r0[t] = acc0 + acc1; i0[t] = 0.f;
    }

    float *orr, *oi;
    block_fft512(r0, i0, r1, i1, tc, ts, tid, orr, oi);

    const float SC = 0.044194173824159216f / 256.0f;
    for (int n = tid; n < NF_; n += 256) {
        g_csd_re[b * NF_ + n] = orr[n] * SC;
        g_csd_im[b * NF_ + n] = oi[n]  * SC;
    }
}

// ---------------- kernel 2: rfft + csd, features, proj -> g_flat (bf16), heads -> g_new ----------------
__global__ void k_fftproj(const float* __restrict__ x,
                          const float* __restrict__ Wp,
                          const float* __restrict__ bp,
                          const float* __restrict__ mag_w,
                          const float* __restrict__ mag_b,
                          const float* __restrict__ ph_w,
                          const float* __restrict__ ph_b)
{
    __shared__ float r0[512], i0[512], r1[512], i1[512];
    __shared__ float tc[256], ts[256];
    __shared__ __align__(16) float wp_s[256];
    __shared__ __align__(16) float bp_s[64];

    int m = blockIdx.x;
    int b = m >> 4, f = m & 15;
    int tid = threadIdx.x;

    BUILD_TW(tc, ts, -1.f, tid);
    if (tid < 256) wp_s[tid] = Wp[tid];
    if (tid < 64)  bp_s[tid] = bp[tid];

    for (int t = tid; t < 512; t += 256) {
        r0[t] = x[((size_t)(b * 512 + t)) * 16 + f];
        i0[t] = 0.f;
    }

    float *orr, *oi;
    block_fft512(r0, i0, r1, i1, tc, ts, tid, orr, oi);

    const float SC = 0.044194173824159216f;
    for (int n = tid; n < NF_; n += 256) {
        float re = orr[n] * SC + g_csd_re[b * NF_ + n];
        float im = oi[n]  * SC + g_csd_im[b * NF_ + n];
        orr[n] = re; oi[n] = im;
        g_fft_re[(size_t)m * NF_ + n] = re;
        g_fft_im[(size_t)m * NF_ + n] = im;
    }
    __syncthreads();

    for (int n = tid; n < NF_; n += 256) {
        float re = orr[n], im = oi[n];
        float s2 = re * re + im * im;
        float mag, sa, ca;
        if (s2 > 0.f) {
            float inv = rsqrtf(s2);
            mag = s2 * inv; sa = im * inv; ca = re * inv;
        } else { mag = 0.f; sa = 0.f; ca = 1.f; }
        float fr = (float)n * 0.1953125f;

        uint32_t* dst = (uint32_t*)(g_flat + (size_t)m * K_ + (size_t)n * 64);
        const float4* mw = (const float4*)(mag_w + (size_t)n * 64);
        const float4* pw = (const float4*)(ph_w  + (size_t)n * 64);
        float dm = 0.f, dp = 0.f;
#pragma unroll
        for (int q = 0; q < 16; q++) {
            float4 w0 = *(const float4*)&wp_s[q * 4];
            float4 w1 = *(const float4*)&wp_s[64 + q * 4];
            float4 w2 = *(const float4*)&wp_s[128 + q * 4];
            float4 w3 = *(const float4*)&wp_s[192 + q * 4];
            float4 bb = *(const float4*)&bp_s[q * 4];
            float4 v;
            v.x = fmaxf(fmaf(mag, w0.x, fmaf(sa, w1.x, fmaf(ca, w2.x, fmaf(fr, w3.x, bb.x)))), 0.f);
            v.y = fmaxf(fmaf(mag, w0.y, fmaf(sa, w1.y, fmaf(ca, w2.y, fmaf(fr, w3.y, bb.y)))), 0.f);
            v.z = fmaxf(fmaf(mag, w0.z, fmaf(sa, w1.z, fmaf(ca, w2.z, fmaf(fr, w3.z, bb.z)))), 0.f);
            v.w = fmaxf(fmaf(mag, w0.w, fmaf(sa, w1.w, fmaf(ca, w2.w, fmaf(fr, w3.w, bb.w)))), 0.f);
            dst[q * 2]     = packbf(v.x, v.y);
            dst[q * 2 + 1] = packbf(v.z, v.w);
            float4 a = __ldg(&mw[q]);
            float4 c = __ldg(&pw[q]);
            dm = fmaf(v.x, a.x, dm); dm = fmaf(v.y, a.y, dm);
            dm = fmaf(v.z, a.z, dm); dm = fmaf(v.w, a.w, dm);
            dp = fmaf(v.x, c.x, dp); dp = fmaf(v.y, c.y, dp);
            dp = fmaf(v.z, c.z, dp); dp = fmaf(v.w, c.w, dp);
        }
        float mo  = fmaxf(dm + __ldg(&mag_b[n]), 0.f);
        float phv = 6.283185307179586f * sigf(dp + __ldg(&ph_b[n]));
        float sp, cp;
        __sincosf(phv, &sp, &cp);
        g_new_re[(size_t)m * NF_ + n] = mo * cp;
        g_new_im[(size_t)m * NF_ + n] = mo * sp;
    }
}

// ---------------- kernel 3a: transpose W_gate [K][257] -> g_wt [288][K] (bf16, zero pad) ----------------
__global__ void k_transpose(const float* __restrict__ Wg)
{
    __shared__ float tile[32][33];
    int tid = threadIdx.x;
    int tx = tid & 31, ty = tid >> 5;
    int kb = blockIdx.x * 32, nb = blockIdx.y * 32;
#pragma unroll
    for (int r = 0; r < 4; r++) {
        int kk = kb + ty + r * 8;
        int nn = nb + tx;
        tile[ty + r * 8][tx] = (nn < NF_) ? Wg[(size_t)kk * NF_ + nn] : 0.f;
    }
    __syncthreads();
#pragma unroll
    for (int r = 0; r < 4; r++) {
        int nn = nb + ty + r * 8;
        int kk = kb + tx;
        g_wt[(size_t)nn * K_ + kk] = __float2bfloat16(tile[tx][ty + r * 8]);
    }
}

// ---------------- kernel 3b: bf16 mma.sync (m16n8k16) split-K GEMM, ldmatrix fragments ----------------
// CTA tile 128x96x64(bf16), 8 warps (4x2), warp tile 32x48, 3-stage cp.async.
#define BK_       64              // bf16 elements per K-chunk
#define NCHUNK_   (K_/BK_)        // 257
#define ASTRIDE_W 36              // words (u32) per row = 72 bf16 (64 + 8 pad)
#define A_WORDS_  (128*ASTRIDE_W) // 4608 words
#define B_WORDS_  (96*ASTRIDE_W)  // 3456 words
#define STG_WORDS_ (A_WORDS_+B_WORDS_)  // 8064 words = 32256 B
#define GEMM_SMEM_ (3*STG_WORDS_*4)     // 96768 bytes

__device__ __forceinline__ void load_chunk(uint32_t sbase, const __nv_bfloat16* __restrict__ Ab,
                                           const __nv_bfloat16* __restrict__ Bb, int kbase, int tid)
{
    uint32_t sA = sbase;
    uint32_t sB = sbase + A_WORDS_ * 4;
#pragma unroll
    for (int i = 0; i < 4; i++) {             // A: 128 rows x 8 x 16B (64 bf16/row)
        int g = tid + (i << 8);
        int r = g >> 3, c = g & 7;
        CP_ASYNC16(sA + (uint32_t)(r * (ASTRIDE_W*4) + c * 16),
                   Ab + (size_t)r * K_ + kbase + c * 8);
    }
#pragma unroll
    for (int i = 0; i < 3; i++) {             // B: 96 rows x 8 x 16B
        int g = tid + (i << 8);
        int r = g >> 3, c = g & 7;
        CP_ASYNC16(sB + (uint32_t)(r * (ASTRIDE_W*4) + c * 16),
                   Bb + (size_t)r * K_ + kbase + c * 8);
    }
    asm volatile("cp.async.commit_group;\n" ::: "memory");
}

__global__ void __launch_bounds__(256, 2) k_gemm()
{
    extern __shared__ __align__(16) uint32_t smem[];

    int tid = threadIdx.x;
    int nt0 = blockIdx.x;           // 0..2
    int m0  = blockIdx.y * 128;
    int s   = blockIdx.z;           // split 0..SPLITS_-1
    const __nv_bfloat16* Ab = g_flat + (size_t)m0 * K_;
    const __nv_bfloat16* Bb = g_wt + (size_t)(nt0 * 96) * K_;

    int warp = tid >> 5, lane = tid & 31;
    int wm = warp & 3;
    int wn = warp >> 2;
    int lr = lane >> 2, lc = lane & 3;

    // ldmatrix lane-address components
    int li = lane >> 3, lrr = lane & 7;
    uint32_t aoff[2], boff[3];
#pragma unroll
    for (int mt = 0; mt < 2; mt++)
        aoff[mt] = (uint32_t)(((wm * 32 + mt * 16 + (li & 1) * 8 + lrr) * ASTRIDE_W + (li >> 1) * 4) * 4);
#pragma unroll
    for (int p = 0; p < 3; p++)
        boff[p] = (uint32_t)(((wn * 48 + (2 * p + (li >> 1)) * 8 + lrr) * ASTRIDE_W + (li & 1) * 4) * 4
                             + A_WORDS_ * 4);

    float acc[2][6][4];
#pragma unroll
    for (int i = 0; i < 2; i++)
#pragma unroll
        for (int j = 0; j < 6; j++)
#pragma unroll
            for (int q = 0; q < 4; q++) acc[i][j][q] = 0.f;

    const int cs = (s * NCHUNK_) / SPLITS_;
    const int ce = ((s + 1) * NCHUNK_) / SPLITS_;
    const int CN = ce - cs;

    uint32_t sb = smem_u32(smem);

    load_chunk(sb + 0 * STG_WORDS_ * 4, Ab, Bb, (cs + 0) * BK_, tid);
    load_chunk(sb + 1 * STG_WORDS_ * 4, Ab, Bb, (cs + 1) * BK_, tid);

    for (int i = 0; i < CN; i++) {
        if (i + 2 < CN)
            load_chunk(sb + ((i + 2) % 3) * STG_WORDS_ * 4, Ab, Bb, (cs + i + 2) * BK_, tid);
        else
            asm volatile("cp.async.commit_group;\n" ::: "memory");
        asm volatile("cp.async.wait_group 2;\n" ::: "memory");
        __syncthreads();

        uint32_t stage = sb + (uint32_t)((i % 3) * STG_WORDS_ * 4);

#pragma unroll
        for (int kt = 0; kt < 4; kt++) {       // 4 x k16 = 64 bf16
            uint32_t kb = stage + (uint32_t)(kt * 32);
            uint32_t a[2][4];
            LDSM_X4(a[0][0], a[0][1], a[0][2], a[0][3], kb + aoff[0]);
            LDSM_X4(a[1][0], a[1][1], a[1][2], a[1][3], kb + aoff[1]);
            uint32_t bfr[6][2];
            LDSM_X4(bfr[0][0], bfr[0][1], bfr[1][0], bfr[1][1], kb + boff[0]);
            LDSM_X4(bfr[2][0], bfr[2][1], bfr[3][0], bfr[3][1], kb + boff[1]);
            LDSM_X4(bfr[4][0], bfr[4][1], bfr[5][0], bfr[5][1], kb + boff[2]);
#pragma unroll
            for (int mt = 0; mt < 2; mt++)
#pragma unroll
                for (int nt = 0; nt < 6; nt++)
                    mma_bf16(acc[mt][nt], a[mt], bfr[nt]);
        }
        __syncthreads();
    }

    float* P = g_part[s];
#pragma unroll
    for (int mt = 0; mt < 2; mt++) {
        int row = m0 + wm * 32 + mt * 16 + lr;
#pragma unroll
        for (int nt = 0; nt < 6; nt++) {
            int col = nt0 * 96 + wn * 48 + nt * 8 + lc * 2;
            float2 v0 = make_float2(acc[mt][nt][0], acc[mt][nt][1]);
            float2 v1 = make_float2(acc[mt][nt][2], acc[mt][nt][3]);
            *(float2*)(P + (size_t)row * NPAD_ + col)       = v0;
            *(float2*)(P + (size_t)(row + 8) * NPAD_ + col) = v1;
        }
    }
}

// ---------------- kernel 4: fused split-K reduce + gate + blend + irfft + residual ----------------
__global__ void k_irfft(const float* __restrict__ x, float* __restrict__ out,
                        const float* __restrict__ bg)
{
    __shared__ float r0[512], i0[512], r1[512], i1[512];
    __shared__ float tc[256], ts[256];
    __shared__ float fre[NF_], fim[NF_];
    int m = blockIdx.x;
    int b = m >> 4, f = m & 15;
    int tid = threadIdx.x;

    BUILD_TW(tc, ts, +1.f, tid);

    for (int n = tid; n < NF_; n += 256) {
        size_t pofs = (size_t)m * NPAD_ + n;
        float acc = 0.f;
#pragma unroll
        for (int s = 0; s < SPLITS_; s++) acc += g_part[s][pofs];
        float g = acc + __ldg(&bg[n]);
        g = g * sigf(g);                          // SiLU
        float w = sigf(g);                        // gate weight
        size_t id = (size_t)m * NF_ + n;
        fre[n] = w * g_new_re[id] + (1.f - w) * g_fft_re[id];
        fim[n] = w * g_new_im[id] + (1.f - w) * g_fft_im[id];
    }
    __syncthreads();

    for (int n = tid; n < 512; n += 256) {
        float re, im;
        if (n == 0)        { re = fre[0];   im = 0.f; }
        else if (n < 256)  { re = fre[n];   im = fim[n]; }
        else if (n == 256) { re = fre[256]; im = 0.f; }
        else               { re = fre[512 - n]; im = -fim[512 - n]; }
        r0[n] = re; i0[n] = im;
    }

    float *orr, *oi;
    block_fft512(r0, i0, r1, i1, tc, ts, tid, orr, oi);

    const float SC = 0.044194173824159216f;
    for (int t = tid; t < 512; t += 256) {
        size_t xi = ((size_t)(b * 512 + t)) * 16 + f;
        out[xi] = orr[t] * SC + x[xi];
    }
}

// ---------------- kernel 5: LayerNorm over F=16 ----------------
__global__ void k_ln(float* __restrict__ out,
                     const float* __restrict__ gamma, const float* __restrict__ beta)
{
    int row = blockIdx.x * blockDim.x + threadIdx.x;
    if (row >= B_ * H_) return;
    float* p = out + (size_t)row * 16;
    float v[16];
    float4* pv = (float4*)p;
#pragma unroll
    for (int q = 0; q < 4; q++) {
        float4 t = pv[q];
        v[q * 4 + 0] = t.x; v[q * 4 + 1] = t.y; v[q * 4 + 2] = t.z; v[q * 4 + 3] = t.w;
    }
    float sm = 0.f;
#pragma unroll
    for (int i = 0; i < 16; i++) sm += v[i];
    float mu = sm * (1.f / 16.f);
    float ss = 0.f;
#pragma unroll
    for (int i = 0; i < 16; i++) { float d = v[i] - mu; ss = fmaf(d, d, ss); }
    float inv = rsqrtf(ss * (1.f / 16.f) + 1e-5f);
#pragma unroll
    for (int i = 0; i < 16; i++)
        v[i] = (v[i] - mu) * inv * __ldg(&gamma[i]) + __ldg(&beta[i]);
#pragma unroll
    for (int q = 0; q < 4; q++) {
        float4 t;
        t.x = v[q * 4 + 0]; t.y = v[q * 4 + 1]; t.z = v[q * 4 + 2]; t.w = v[q * 4 + 3];
        pv[q] = t;
    }
}

// ---------------- launcher ----------------
extern "C" void kernel_launch(void* const* d_in, const int* in_sizes, int n_in,
                              void* d_out, int out_size)
{
    const float* x       = (const float*)d_in[0];
    const float* W_proj  = (const float*)d_in[1];
    const float* b_proj  = (const float*)d_in[2];
    const float* W_gate  = (const float*)d_in[3];
    const float* b_gate  = (const float*)d_in[4];
    const float* mag_w   = (const float*)d_in[5];
    const float* mag_b   = (const float*)d_in[6];
    const float* phase_w = (const float*)d_in[7];
    const float* phase_b = (const float*)d_in[8];
    const float* ln_g    = (const float*)d_in[9];
    const float* ln_b    = (const float*)d_in[10];
    float* out = (float*)d_out;

    cudaFuncSetAttribute(k_gemm, cudaFuncAttributeMaxDynamicSharedMemorySize, GEMM_SMEM_);

    k_csd<<<B_, 256>>>(x);
    k_fftproj<<<M_, 256>>>(x, W_proj, b_proj, mag_w, mag_b, phase_w, phase_b);
    k_transpose<<<dim3(K_ / 32, NPAD_ / 32), 256>>>(W_gate);
    k_gemm<<<dim3(3, 16, SPLITS_), 256, GEMM_SMEM_>>>();
    k_irfft<<<M_, 256>>>(x, out, b_gate);
    k_ln<<<(B_ * H_ + 255) / 256, 256>>>(out, ln_g, ln_b);
}

// round 8
// speedup vs baseline: 3.8589x; 1.0568x over previous
#include <cuda_runtime.h>
#include <cuda_bf16.h>
#include <math.h>
#include <stdint.h>

#define B_    128
#define H_    512
#define F_    16
#define HID_  64
#define NF_   257
#define M_    (B_*F_)       // 2048
#define K_    (NF_*HID_)    // 16448
#define NPAD_ 288
#define SPLITS_ 6

// ---------------- scratch (static device memory; no allocations) ----------------
__device__ __align__(128) float g_fft_re[M_*NF_];
__device__ __align__(128) float g_fft_im[M_*NF_];
__device__ __align__(128) float g_new_re[M_*NF_];
__device__ __align__(128) float g_new_im[M_*NF_];
__device__ __align__(128) __nv_bfloat16 g_wt[(size_t)NPAD_*K_];   // W_gate^T [n][k] bf16
__device__ __align__(128) float g_part[SPLITS_][(size_t)M_*NPAD_];
__device__ __align__(128) __nv_bfloat16 g_flat[(size_t)M_*K_];    // proj bf16, [m][n*64+h]

// ================= helpers =================
#define CP_ASYNC16(dst, src) \
    asm volatile("cp.async.cg.shared.global [%0], [%1], 16;\n" :: "r"(dst), "l"(src))
__device__ __forceinline__ uint32_t smem_u32(const void* p) {
    uint32_t a;
    asm("{ .reg .u64 t; cvta.to.shared.u64 t, %1; cvt.u32.u64 %0, t; }" : "=r"(a) : "l"(p));
    return a;
}
__device__ __forceinline__ void mma_bf16(float c[4], const uint32_t a[4], const uint32_t b[2]) {
    asm volatile(
        "mma.sync.aligned.m16n8k16.row.col.f32.bf16.bf16.f32 "
        "{%0,%1,%2,%3}, {%4,%5,%6,%7}, {%8,%9}, {%0,%1,%2,%3};"
        : "+f"(c[0]), "+f"(c[1]), "+f"(c[2]), "+f"(c[3])
        : "r"(a[0]), "r"(a[1]), "r"(a[2]), "r"(a[3]), "r"(b[0]), "r"(b[1]));
}
#define LDSM_X4(R0, R1, R2, R3, ADDR) \
    asm volatile("ldmatrix.sync.aligned.m8n8.x4.shared.b16 {%0,%1,%2,%3}, [%4];" \
        : "=r"(R0), "=r"(R1), "=r"(R2), "=r"(R3) : "r"(ADDR))
__device__ __forceinline__ uint32_t packbf(float x, float y) {
    __nv_bfloat162 h = __float22bfloat162_rn(make_float2(x, y));
    return *(uint32_t*)&h;
}
__device__ __forceinline__ float sigf(float x) {
    return __fdividef(1.f, 1.f + __expf(-x));
}
#define SC_ORTHO 0.044194173824159216f

// ---------------- batched 8-channel 512-pt Stockham FFT (512 threads) ----------------
__device__ __forceinline__ void fft512x8(float* r0, float* i0, float* r1, float* i1,
                                         const float* tc, const float* ts,
                                         int tid, float*& outr, float*& outi)
{
    float *ar = r0, *ai = i0, *br = r1, *bi = i1;
    int u = tid & 255, cb = (tid >> 8) << 2;
#pragma unroll
    for (int st = 0; st < 9; st++) {
        __syncthreads();
        int m = 1 << st;
        int j = u >> st, k = u & (m - 1), idx = u & ~(m - 1);
        float wc = tc[idx], ws = ts[idx];
        int o0 = k + (j << (st + 1));
#pragma unroll
        for (int q = 0; q < 4; q++) {
            int off = (cb + q) << 9;
            float c0r = ar[off + u],       c0i = ai[off + u];
            float c1r = ar[off + u + 256], c1i = ai[off + u + 256];
            float sr = c0r - c1r, si = c0i - c1i;
            br[off + o0]     = c0r + c1r;
            bi[off + o0]     = c0i + c1i;
            br[off + o0 + m] = wc * sr - ws * si;
            bi[off + o0 + m] = wc * si + ws * sr;
        }
        float* t;
        t = ar; ar = br; br = t;
        t = ai; ai = bi; bi = t;
    }
    __syncthreads();
    outr = ar; outi = ai;
}

// single-channel 512-pt FFT on channel-0 slice; 512 threads (upper half idles at syncs)
__device__ __forceinline__ void fft512x1(float* r0, float* i0, float* r1, float* i1,
                                         const float* tc, const float* ts,
                                         int tid, float*& outr, float*& outi)
{
    float *ar = r0, *ai = i0, *br = r1, *bi = i1;
#pragma unroll
    for (int st = 0; st < 9; st++) {
        __syncthreads();
        if (tid < 256) {
            int m = 1 << st;
            int j = tid >> st, k = tid & (m - 1), idx = tid & ~(m - 1);
            float wc = tc[idx], ws = ts[idx];
            int o0 = k + (j << (st + 1));
            float c0r = ar[tid],       c0i = ai[tid];
            float c1r = ar[tid + 256], c1i = ai[tid + 256];
            float sr = c0r - c1r, si = c0i - c1i;
            br[o0]     = c0r + c1r;
            bi[o0]     = c0i + c1i;
            br[o0 + m] = wc * sr - ws * si;
            bi[o0 + m] = wc * si + ws * sr;
        }
        float* t;
        t = ar; ar = br; br = t;
        t = ai; ai = bi; bi = t;
    }
    __syncthreads();
    outr = ar; outi = ai;
}

// ---------------- kernel 1: fwd — per-batch csd+fft+proj+heads, plus transpose blocks ----------------
// smem layout (floats), ALL float4-read buffers at 16B-aligned offsets:
// r0 @0, i0 @4096, r1 @8192, i1 @12288, s @16384 (512),
// csr @16896 (264), csi @17160 (264), tc @17424 (256), ts @17680 (256),
// wp @17936 (256), bp @18192 (64). total 18256 floats.
#define FWD_SMEMF 18256
#define NT_BLKS_  (257*9)   // 2313 transpose tiles (64k x 32n)

__global__ void __launch_bounds__(512) k_fwd(
    const float* __restrict__ x,
    const float* __restrict__ Wp,  const float* __restrict__ bp,
    const float* __restrict__ mag_w, const float* __restrict__ mag_b,
    const float* __restrict__ ph_w,  const float* __restrict__ ph_b,
    const float* __restrict__ Wg)
{
    extern __shared__ __align__(16) float sm[];
    int tid = threadIdx.x;

    if (blockIdx.x >= B_) {
        // ---- transpose tile: Wg[K][257] -> g_wt[288][K] bf16 (zero pad) ----
        float* tile = sm;                       // [64][33]
        int t  = blockIdx.x - B_;
        int kt = t % 257, nt = t / 257;
        int kb = kt * 64, nb = nt * 32;
        int col = tid & 31, rowb = tid >> 5;    // rowb 0..15
#pragma unroll
        for (int rr = 0; rr < 4; rr++) {
            int row = rowb + rr * 16;
            int nn = nb + col;
            tile[row * 33 + col] = (nn < NF_) ? Wg[(size_t)(kb + row) * NF_ + nn] : 0.f;
        }
        __syncthreads();
#pragma unroll
        for (int i = 0; i < 4; i++) {
            int e = tid + i * 512;
            int nl = e >> 6, kl = e & 63;
            g_wt[(size_t)(nb + nl) * K_ + kb + kl] = __float2bfloat16(tile[kl * 33 + nl]);
        }
        return;
    }

    // ---- per-batch block ----
    int b = blockIdx.x;
    float* r0  = sm;
    float* i0  = sm + 4096;
    float* r1  = sm + 8192;
    float* i1  = sm + 12288;
    float* s   = sm + 16384;
    float* csr = sm + 16896;
    float* csi = sm + 17160;
    float* tc  = sm + 17424;
    float* ts  = sm + 17680;
    float* wp  = sm + 17936;
    float* bpp = sm + 18192;

    if (tid < 256) {
        float _s, _c;
        sincosf(-3.14159265358979323846f * (float)tid * (1.0f / 256.0f), &_s, &_c);
        tc[tid] = _c; ts[tid] = _s;
    } else {
        wp[tid - 256] = Wp[tid - 256];
    }
    if (tid < 64) bpp[tid] = bp[tid];

    // channel sum (thread t reads its 64B row)
    {
        const float4* xr = (const float4*)(x + (size_t)b * 512 * 16);
        float4 a = xr[tid * 4 + 0], c = xr[tid * 4 + 1], d = xr[tid * 4 + 2], e = xr[tid * 4 + 3];
        s[tid] = (a.x + a.y + a.z + a.w) + (c.x + c.y + c.z + c.w)
               + (d.x + d.y + d.z + d.w) + (e.x + e.y + e.z + e.w);
    }
    __syncthreads();

    // autocorrelation -> r0 (ch0 slice)
    {
        int t = tid;
        int k0 = 255 - t; if (k0 < 0)   k0 = 0;
        int k1 = 766 - t; if (k1 > 511) k1 = 511;
        float acc0 = 0.f, acc1 = 0.f;
        int k = k0;
        for (; k + 1 <= k1; k += 2) {
            acc0 = fmaf(s[t + k - 255], s[k],     acc0);
            acc1 = fmaf(s[t + k - 254], s[k + 1], acc1);
        }
        if (k <= k1) acc0 = fmaf(s[t + k - 255], s[k], acc0);
        r0[t] = acc0 + acc1;
        i0[t] = 0.f;
    }

    float *fr, *fi;
    fft512x1(r0, i0, r1, i1, tc, ts, tid, fr, fi);

    const float SCC = SC_ORTHO / 256.0f;
    for (int n = tid; n < NF_; n += 512) {
        csr[n] = fr[n] * SCC;
        csi[n] = fi[n] * SCC;
    }
    __syncthreads();

    for (int g = 0; g < 2; g++) {
        __syncthreads();
        // load 8 channels into FFT buffers
        {
            const float4* xr = (const float4*)(x + (size_t)b * 512 * 16);
#pragma unroll
            for (int i = 0; i < 2; i++) {
                int e = tid + i * 512;            // 0..1023
                int t = e >> 1, j = e & 1;
                float4 v = xr[t * 4 + g * 2 + j];
                int c0 = j * 4;
                r0[(c0 + 0) * 512 + t] = v.x; i0[(c0 + 0) * 512 + t] = 0.f;
                r0[(c0 + 1) * 512 + t] = v.y; i0[(c0 + 1) * 512 + t] = 0.f;
                r0[(c0 + 2) * 512 + t] = v.z; i0[(c0 + 2) * 512 + t] = 0.f;
                r0[(c0 + 3) * 512 + t] = v.w; i0[(c0 + 3) * 512 + t] = 0.f;
            }
        }
        float *gfr, *gfi;
        fft512x8(r0, i0, r1, i1, tc, ts, tid, gfr, gfi);

        // features + proj + heads for these 8 channels
        for (int p = tid; p < NF_ * 8; p += 512) {
            int ch = p / NF_;
            int n  = p - ch * NF_;
            int f  = g * 8 + ch;
            int m  = b * 16 + f;

            float re = gfr[ch * 512 + n] * SC_ORTHO + csr[n];
            float im = gfi[ch * 512 + n] * SC_ORTHO + csi[n];
            g_fft_re[(size_t)m * NF_ + n] = re;
            g_fft_im[(size_t)m * NF_ + n] = im;

            float s2 = re * re + im * im;
            float mag, sa, ca;
            if (s2 > 0.f) {
                float inv = rsqrtf(s2);
                mag = s2 * inv; sa = im * inv; ca = re * inv;
            } else { mag = 0.f; sa = 0.f; ca = 1.f; }
            float freqv = (float)n * 0.1953125f;

            uint32_t* dst = (uint32_t*)(g_flat + (size_t)m * K_ + (size_t)n * 64);
            const float4* mw = (const float4*)(mag_w + (size_t)n * 64);
            const float4* pw = (const float4*)(ph_w  + (size_t)n * 64);
            float dm = 0.f, dp = 0.f;
#pragma unroll
            for (int q = 0; q < 16; q++) {
                float4 w0 = *(const float4*)&wp[q * 4];
                float4 w1 = *(const float4*)&wp[64 + q * 4];
                float4 w2 = *(const float4*)&wp[128 + q * 4];
                float4 w3 = *(const float4*)&wp[192 + q * 4];
                float4 bb = *(const float4*)&bpp[q * 4];
                float4 v;
                v.x = fmaxf(fmaf(mag, w0.x, fmaf(sa, w1.x, fmaf(ca, w2.x, fmaf(freqv, w3.x, bb.x)))), 0.f);
                v.y = fmaxf(fmaf(mag, w0.y, fmaf(sa, w1.y, fmaf(ca, w2.y, fmaf(freqv, w3.y, bb.y)))), 0.f);
                v.z = fmaxf(fmaf(mag, w0.z, fmaf(sa, w1.z, fmaf(ca, w2.z, fmaf(freqv, w3.z, bb.z)))), 0.f);
                v.w = fmaxf(fmaf(mag, w0.w, fmaf(sa, w1.w, fmaf(ca, w2.w, fmaf(freqv, w3.w, bb.w)))), 0.f);
                dst[q * 2]     = packbf(v.x, v.y);
                dst[q * 2 + 1] = packbf(v.z, v.w);
                float4 a = __ldg(&mw[q]);
                float4 c = __ldg(&pw[q]);
                dm = fmaf(v.x, a.x, dm); dm = fmaf(v.y, a.y, dm);
                dm = fmaf(v.z, a.z, dm); dm = fmaf(v.w, a.w, dm);
                dp = fmaf(v.x, c.x, dp); dp = fmaf(v.y, c.y, dp);
                dp = fmaf(v.z, c.z, dp); dp = fmaf(v.w, c.w, dp);
            }
            float mo  = fmaxf(dm + __ldg(&mag_b[n]), 0.f);
            float phv = 6.283185307179586f * sigf(dp + __ldg(&ph_b[n]));
            float sp, cp;
            __sincosf(phv, &sp, &cp);
            g_new_re[(size_t)m * NF_ + n] = mo * cp;
            g_new_im[(size_t)m * NF_ + n] = mo * sp;
        }
    }
}

// ---------------- kernel 2: bf16 mma.sync (m16n8k16) split-K GEMM (R6 version) ----------------
#define BK_       64
#define NCHUNK_   (K_/BK_)        // 257
#define ASTRIDE_W 36
#define A_WORDS_  (128*ASTRIDE_W)
#define B_WORDS_  (96*ASTRIDE_W)
#define STG_WORDS_ (A_WORDS_+B_WORDS_)
#define GEMM_SMEM_ (3*STG_WORDS_*4)

__device__ __forceinline__ void load_chunk(uint32_t sbase, const __nv_bfloat16* __restrict__ Ab,
                                           const __nv_bfloat16* __restrict__ Bb, int kbase, int tid)
{
    uint32_t sA = sbase;
    uint32_t sB = sbase + A_WORDS_ * 4;
#pragma unroll
    for (int i = 0; i < 4; i++) {
        int g = tid + (i << 8);
        int r = g >> 3, c = g & 7;
        CP_ASYNC16(sA + (uint32_t)(r * (ASTRIDE_W*4) + c * 16),
                   Ab + (size_t)r * K_ + kbase + c * 8);
    }
#pragma unroll
    for (int i = 0; i < 3; i++) {
        int g = tid + (i << 8);
        int r = g >> 3, c = g & 7;
        CP_ASYNC16(sB + (uint32_t)(r * (ASTRIDE_W*4) + c * 16),
                   Bb + (size_t)r * K_ + kbase + c * 8);
    }
    asm volatile("cp.async.commit_group;\n" ::: "memory");
}

__global__ void __launch_bounds__(256, 2) k_gemm()
{
    extern __shared__ __align__(16) uint32_t smem[];

    int tid = threadIdx.x;
    int nt0 = blockIdx.x;
    int m0  = blockIdx.y * 128;
    int s   = blockIdx.z;
    const __nv_bfloat16* Ab = g_flat + (size_t)m0 * K_;
    const __nv_bfloat16* Bb = g_wt + (size_t)(nt0 * 96) * K_;

    int warp = tid >> 5, lane = tid & 31;
    int wm = warp & 3;
    int wn = warp >> 2;
    int lr = lane >> 2, lc = lane & 3;

    int li = lane >> 3, lrr = lane & 7;
    uint32_t aoff[2], boff[3];
#pragma unroll
    for (int mt = 0; mt < 2; mt++)
        aoff[mt] = (uint32_t)(((wm * 32 + mt * 16 + (li & 1) * 8 + lrr) * ASTRIDE_W + (li >> 1) * 4) * 4);
#pragma unroll
    for (int p = 0; p < 3; p++)
        boff[p] = (uint32_t)(((wn * 48 + (2 * p + (li >> 1)) * 8 + lrr) * ASTRIDE_W + (li & 1) * 4) * 4
                             + A_WORDS_ * 4);

    float acc[2][6][4];
#pragma unroll
    for (int i = 0; i < 2; i++)
#pragma unroll
        for (int j = 0; j < 6; j++)
#pragma unroll
            for (int q = 0; q < 4; q++) acc[i][j][q] = 0.f;

    const int cs = (s * NCHUNK_) / SPLITS_;
    const int ce = ((s + 1) * NCHUNK_) / SPLITS_;
    const int CN = ce - cs;

    uint32_t sb = smem_u32(smem);

    load_chunk(sb + 0 * STG_WORDS_ * 4, Ab, Bb, (cs + 0) * BK_, tid);
    load_chunk(sb + 1 * STG_WORDS_ * 4, Ab, Bb, (cs + 1) * BK_, tid);

    for (int i = 0; i < CN; i++) {
        if (i + 2 < CN)
            load_chunk(sb + ((i + 2) % 3) * STG_WORDS_ * 4, Ab, Bb, (cs + i + 2) * BK_, tid);
        else
            asm volatile("cp.async.commit_group;\n" ::: "memory");
        asm volatile("cp.async.wait_group 2;\n" ::: "memory");
        __syncthreads();

        uint32_t stage = sb + (uint32_t)((i % 3) * STG_WORDS_ * 4);

#pragma unroll
        for (int kt = 0; kt < 4; kt++) {
            uint32_t kb = stage + (uint32_t)(kt * 32);
            uint32_t a[2][4];
            LDSM_X4(a[0][0], a[0][1], a[0][2], a[0][3], kb + aoff[0]);
            LDSM_X4(a[1][0], a[1][1], a[1][2], a[1][3], kb + aoff[1]);
            uint32_t bfr[6][2];
            LDSM_X4(bfr[0][0], bfr[0][1], bfr[1][0], bfr[1][1], kb + boff[0]);
            LDSM_X4(bfr[2][0], bfr[2][1], bfr[3][0], bfr[3][1], kb + boff[1]);
            LDSM_X4(bfr[4][0], bfr[4][1], bfr[5][0], bfr[5][1], kb + boff[2]);
#pragma unroll
            for (int mt = 0; mt < 2; mt++)
#pragma unroll
                for (int nt = 0; nt < 6; nt++)
                    mma_bf16(acc[mt][nt], a[mt], bfr[nt]);
        }
        __syncthreads();
    }

    float* P = g_part[s];
#pragma unroll
    for (int mt = 0; mt < 2; mt++) {
        int row = m0 + wm * 32 + mt * 16 + lr;
#pragma unroll
        for (int nt = 0; nt < 6; nt++) {
            int col = nt0 * 96 + wn * 48 + nt * 8 + lc * 2;
            float2 v0 = make_float2(acc[mt][nt][0], acc[mt][nt][1]);
            float2 v1 = make_float2(acc[mt][nt][2], acc[mt][nt][3]);
            *(float2*)(P + (size_t)row * NPAD_ + col)       = v0;
            *(float2*)(P + (size_t)(row + 8) * NPAD_ + col) = v1;
        }
    }
}

// ---------------- kernel 3: bwd — reduce+gate+blend + 16 iFFTs + residual + LayerNorm ----------------
// smem (floats): bufs @0/4096/8192/12288, fre @16384 (16*264), fim @20608 (16*264),
// y @24832 (512*17), tc @33536, ts @33792. total 34048. (all float4 buffers aligned: none in smem)
#define BWD_SMEMF 34048

__global__ void __launch_bounds__(512) k_bwd(
    const float* __restrict__ x, float* __restrict__ out,
    const float* __restrict__ bg,
    const float* __restrict__ gamma, const float* __restrict__ beta)
{
    extern __shared__ __align__(16) float sm[];
    int b = blockIdx.x, tid = threadIdx.x;

    float* r0  = sm;
    float* i0  = sm + 4096;
    float* r1  = sm + 8192;
    float* i1  = sm + 12288;
    float* fre = sm + 16384;   // [16][264]
    float* fim = sm + 20608;
    float* y   = sm + 24832;   // [512][17]
    float* tc  = sm + 33536;
    float* ts  = sm + 33792;

    if (tid < 256) {
        float _s, _c;
        sincosf(3.14159265358979323846f * (float)tid * (1.0f / 256.0f), &_s, &_c);
        tc[tid] = _c; ts[tid] = _s;
    }

    // split-K reduce + gate + blend
    for (int p = tid; p < 16 * NF_; p += 512) {
        int f = p / NF_;
        int n = p - f * NF_;
        int m = b * 16 + f;
        size_t pofs = (size_t)m * NPAD_ + n;
        float acc = 0.f;
#pragma unroll
        for (int s2 = 0; s2 < SPLITS_; s2++) acc += g_part[s2][pofs];
        float g = acc + __ldg(&bg[n]);
        g = g * sigf(g);
        float w = sigf(g);
        size_t id = (size_t)m * NF_ + n;
        fre[f * 264 + n] = w * g_new_re[id] + (1.f - w) * g_fft_re[id];
        fim[f * 264 + n] = w * g_new_im[id] + (1.f - w) * g_fft_im[id];
    }

    for (int g = 0; g < 2; g++) {
        __syncthreads();
        // hermitian spectrum build for 8 channels
#pragma unroll
        for (int i = 0; i < 8; i++) {
            int e = tid + i * 512;
            int ch = e >> 9, pos = e & 511;
            int f = g * 8 + ch;
            float re, im;
            if (pos == 0)        { re = fre[f * 264];       im = 0.f; }
            else if (pos < 256)  { re = fre[f * 264 + pos]; im = fim[f * 264 + pos]; }
            else if (pos == 256) { re = fre[f * 264 + 256]; im = 0.f; }
            else                 { re = fre[f * 264 + 512 - pos]; im = -fim[f * 264 + 512 - pos]; }
            r0[ch * 512 + pos] = re;
            i0[ch * 512 + pos] = im;
        }
        float *fr2, *fi2;
        fft512x8(r0, i0, r1, i1, tc, ts, tid, fr2, fi2);
#pragma unroll
        for (int i = 0; i < 8; i++) {
            int e = tid + i * 512;
            int ch = e >> 9, t = e & 511;
            y[t * 17 + g * 8 + ch] = fr2[ch * 512 + t] * SC_ORTHO;
        }
    }
    __syncthreads();

    // residual + LayerNorm, thread t owns row t
    {
        int t = tid;
        const float4* xr = (const float4*)(x + ((size_t)(b * 512 + t)) * 16);
        float v[16];
#pragma unroll
        for (int q = 0; q < 4; q++) {
            float4 xv = xr[q];
            v[q * 4 + 0] = y[t * 17 + q * 4 + 0] + xv.x;
            v[q * 4 + 1] = y[t * 17 + q * 4 + 1] + xv.y;
            v[q * 4 + 2] = y[t * 17 + q * 4 + 2] + xv.z;
            v[q * 4 + 3] = y[t * 17 + q * 4 + 3] + xv.w;
        }
        float smv = 0.f;
#pragma unroll
        for (int i = 0; i < 16; i++) smv += v[i];
        float mu = smv * (1.f / 16.f);
        float ss = 0.f;
#pragma unroll
        for (int i = 0; i < 16; i++) { float d = v[i] - mu; ss = fmaf(d, d, ss); }
        float inv = rsqrtf(ss * (1.f / 16.f) + 1e-5f);
        float4* ov = (float4*)(out + ((size_t)(b * 512 + t)) * 16);
#pragma unroll
        for (int q = 0; q < 4; q++) {
            float4 o;
            o.x = (v[q * 4 + 0] - mu) * inv * __ldg(&gamma[q * 4 + 0]) + __ldg(&beta[q * 4 + 0]);
            o.y = (v[q * 4 + 1] - mu) * inv * __ldg(&gamma[q * 4 + 1]) + __ldg(&beta[q * 4 + 1]);
            o.z = (v[q * 4 + 2] - mu) * inv * __ldg(&gamma[q * 4 + 2]) + __ldg(&beta[q * 4 + 2]);
            o.w = (v[q * 4 + 3] - mu) * inv * __ldg(&gamma[q * 4 + 3]) + __ldg(&beta[q * 4 + 3]);
            ov[q] = o;
        }
    }
}

// ---------------- launcher: 3 kernels ----------------
extern "C" void kernel_launch(void* const* d_in, const int* in_sizes, int n_in,
                              void* d_out, int out_size)
{
    const float* x       = (const float*)d_in[0];
    const float* W_proj  = (const float*)d_in[1];
    const float* b_proj  = (const float*)d_in[2];
    const float* W_gate  = (const float*)d_in[3];
    const float* b_gate  = (const float*)d_in[4];
    const float* mag_w   = (const float*)d_in[5];
    const float* mag_b   = (const float*)d_in[6];
    const float* phase_w = (const float*)d_in[7];
    const float* phase_b = (const float*)d_in[8];
    const float* ln_g    = (const float*)d_in[9];
    const float* ln_b    = (const float*)d_in[10];
    float* out = (float*)d_out;

    cudaFuncSetAttribute(k_fwd,  cudaFuncAttributeMaxDynamicSharedMemorySize, FWD_SMEMF * 4);
    cudaFuncSetAttribute(k_gemm, cudaFuncAttributeMaxDynamicSharedMemorySize, GEMM_SMEM_);
    cudaFuncSetAttribute(k_bwd,  cudaFuncAttributeMaxDynamicSharedMemorySize, BWD_SMEMF * 4);

    k_fwd<<<B_ + NT_BLKS_, 512, FWD_SMEMF * 4>>>(x, W_proj, b_proj, mag_w, mag_b,
                                                 phase_w, phase_b, W_gate);
    k_gemm<<<dim3(3, 16, SPLITS_), 256, GEMM_SMEM_>>>();
    k_bwd<<<B_, 512, BWD_SMEMF * 4>>>(x, out, b_gate, ln_g, ln_b);
}

// round 9
// speedup vs baseline: 4.8893x; 1.2670x over previous
#include <cuda_runtime.h>
#include <cuda_bf16.h>
#include <math.h>
#include <stdint.h>

#define B_    128
#define H_    512
#define F_    16
#define HID_  64
#define NF_   257
#define M_    (B_*F_)       // 2048
#define K_    (NF_*HID_)    // 16448
#define NPAD_ 288
#define SPLITS_ 6

// ---------------- scratch (static device memory; no allocations) ----------------
__device__ __align__(128) float g_fft_re[M_*NF_];
__device__ __align__(128) float g_fft_im[M_*NF_];
__device__ __align__(128) float g_new_re[M_*NF_];
__device__ __align__(128) float g_new_im[M_*NF_];
__device__ __align__(128) __nv_bfloat16 g_wt[(size_t)NPAD_*K_];   // W_gate^T [n][k] bf16
__device__ __align__(128) float g_part[SPLITS_][(size_t)M_*NPAD_];
__device__ __align__(128) __nv_bfloat16 g_flat[(size_t)M_*K_];    // proj bf16, [m][n*64+h]

// ================= helpers =================
#define CP_ASYNC16(dst, src) \
    asm volatile("cp.async.cg.shared.global [%0], [%1], 16;\n" :: "r"(dst), "l"(src))
__device__ __forceinline__ uint32_t smem_u32(const void* p) {
    uint32_t a;
    asm("{ .reg .u64 t; cvta.to.shared.u64 t, %1; cvt.u32.u64 %0, t; }" : "=r"(a) : "l"(p));
    return a;
}
__device__ __forceinline__ void mma_bf16(float c[4], const uint32_t a[4], const uint32_t b[2]) {
    asm volatile(
        "mma.sync.aligned.m16n8k16.row.col.f32.bf16.bf16.f32 "
        "{%0,%1,%2,%3}, {%4,%5,%6,%7}, {%8,%9}, {%0,%1,%2,%3};"
        : "+f"(c[0]), "+f"(c[1]), "+f"(c[2]), "+f"(c[3])
        : "r"(a[0]), "r"(a[1]), "r"(a[2]), "r"(a[3]), "r"(b[0]), "r"(b[1]));
}
#define LDSM_X4(R0, R1, R2, R3, ADDR) \
    asm volatile("ldmatrix.sync.aligned.m8n8.x4.shared.b16 {%0,%1,%2,%3}, [%4];" \
        : "=r"(R0), "=r"(R1), "=r"(R2), "=r"(R3) : "r"(ADDR))
__device__ __forceinline__ uint32_t packbf(float x, float y) {
    __nv_bfloat162 h = __float22bfloat162_rn(make_float2(x, y));
    return *(uint32_t*)&h;
}
__device__ __forceinline__ float sigf(float x) {
    return __fdividef(1.f, 1.f + __expf(-x));
}
#define SC_ORTHO 0.044194173824159216f

// ---------------- batched 8-channel 512-pt Stockham FFT (512 threads) ----------------
__device__ __forceinline__ void fft512x8(float* r0, float* i0, float* r1, float* i1,
                                         const float* tc, const float* ts,
                                         int tid, float*& outr, float*& outi)
{
    float *ar = r0, *ai = i0, *br = r1, *bi = i1;
    int u = tid & 255, cb = (tid >> 8) << 2;
#pragma unroll
    for (int st = 0; st < 9; st++) {
        __syncthreads();
        int m = 1 << st;
        int j = u >> st, k = u & (m - 1), idx = u & ~(m - 1);
        float wc = tc[idx], ws = ts[idx];
        int o0 = k + (j << (st + 1));
#pragma unroll
        for (int q = 0; q < 4; q++) {
            int off = (cb + q) << 9;
            float c0r = ar[off + u],       c0i = ai[off + u];
            float c1r = ar[off + u + 256], c1i = ai[off + u + 256];
            float sr = c0r - c1r, si = c0i - c1i;
            br[off + o0]     = c0r + c1r;
            bi[off + o0]     = c0i + c1i;
            br[off + o0 + m] = wc * sr - ws * si;
            bi[off + o0 + m] = wc * si + ws * sr;
        }
        float* t;
        t = ar; ar = br; br = t;
        t = ai; ai = bi; bi = t;
    }
    __syncthreads();
    outr = ar; outi = ai;
}

// single-channel 512-pt FFT on channel-0 slice; only threads <256 butterfly
__device__ __forceinline__ void fft512x1(float* r0, float* i0, float* r1, float* i1,
                                         const float* tc, const float* ts,
                                         int tid, float*& outr, float*& outi)
{
    float *ar = r0, *ai = i0, *br = r1, *bi = i1;
#pragma unroll
    for (int st = 0; st < 9; st++) {
        __syncthreads();
        if (tid < 256) {
            int m = 1 << st;
            int j = tid >> st, k = tid & (m - 1), idx = tid & ~(m - 1);
            float wc = tc[idx], ws = ts[idx];
            int o0 = k + (j << (st + 1));
            float c0r = ar[tid],       c0i = ai[tid];
            float c1r = ar[tid + 256], c1i = ai[tid + 256];
            float sr = c0r - c1r, si = c0i - c1i;
            br[o0]     = c0r + c1r;
            bi[o0]     = c0i + c1i;
            br[o0 + m] = wc * sr - ws * si;
            bi[o0 + m] = wc * si + ws * sr;
        }
        float* t;
        t = ar; ar = br; br = t;
        t = ai; ai = bi; bi = t;
    }
    __syncthreads();
    outr = ar; outi = ai;
}

// ---------------- kernel 1: fwd — (batch,half) blocks: csd+fft+proj+heads; plus transpose ----------------
// smem layout (floats), float4 buffers 16B-aligned:
// r0 @0, i0 @4096, r1 @8192, i1 @12288, s @16384 (512),
// csr @16896 (264), csi @17160 (264), tc @17424 (256), ts @17680 (256),
// wp @17936 (256), bp @18192 (64). total 18256 floats.
#define FWD_SMEMF 18256
#define NHEAVY_   (B_*2)    // 256 (batch, channel-half) blocks
#define NT_BLKS_  (257*9)   // 2313 transpose tiles (64k x 32n)

__global__ void __launch_bounds__(512) k_fwd(
    const float* __restrict__ x,
    const float* __restrict__ Wp,  const float* __restrict__ bp,
    const float* __restrict__ mag_w, const float* __restrict__ mag_b,
    const float* __restrict__ ph_w,  const float* __restrict__ ph_b,
    const float* __restrict__ Wg)
{
    extern __shared__ __align__(16) float sm[];
    int tid = threadIdx.x;

    if (blockIdx.x >= NHEAVY_) {
        // ---- transpose tile: Wg[K][257] -> g_wt[288][K] bf16 (zero pad) ----
        float* tile = sm;                       // [64][33]
        int t  = blockIdx.x - NHEAVY_;
        int kt = t % 257, nt = t / 257;
        int kb = kt * 64, nb = nt * 32;
        int col = tid & 31, rowb = tid >> 5;
#pragma unroll
        for (int rr = 0; rr < 4; rr++) {
            int row = rowb + rr * 16;
            int nn = nb + col;
            tile[row * 33 + col] = (nn < NF_) ? Wg[(size_t)(kb + row) * NF_ + nn] : 0.f;
        }
        __syncthreads();
#pragma unroll
        for (int i = 0; i < 4; i++) {
            int e = tid + i * 512;
            int nl = e >> 6, kl = e & 63;
            g_wt[(size_t)(nb + nl) * K_ + kb + kl] = __float2bfloat16(tile[kl * 33 + nl]);
        }
        return;
    }

    // ---- heavy block: batch b, channel-half g ----
    int b = blockIdx.x >> 1;
    int g = blockIdx.x & 1;
    float* r0  = sm;
    float* i0  = sm + 4096;
    float* r1  = sm + 8192;
    float* i1  = sm + 12288;
    float* s   = sm + 16384;
    float* csr = sm + 16896;
    float* csi = sm + 17160;
    float* tc  = sm + 17424;
    float* ts  = sm + 17680;
    float* wp  = sm + 17936;
    float* bpp = sm + 18192;

    if (tid < 256) {
        float _s, _c;
        sincosf(-3.14159265358979323846f * (float)tid * (1.0f / 256.0f), &_s, &_c);
        tc[tid] = _c; ts[tid] = _s;
    } else {
        wp[tid - 256] = Wp[tid - 256];
    }
    if (tid < 64) bpp[tid] = bp[tid];

    // channel sum
    {
        const float4* xr = (const float4*)(x + (size_t)b * 512 * 16);
        float4 a = xr[tid * 4 + 0], c = xr[tid * 4 + 1], d = xr[tid * 4 + 2], e = xr[tid * 4 + 3];
        s[tid] = (a.x + a.y + a.z + a.w) + (c.x + c.y + c.z + c.w)
               + (d.x + d.y + d.z + d.w) + (e.x + e.y + e.z + e.w);
    }
    __syncthreads();

    // autocorrelation -> r0 (ch0 slice)
    {
        int t = tid;
        int k0 = 255 - t; if (k0 < 0)   k0 = 0;
        int k1 = 766 - t; if (k1 > 511) k1 = 511;
        float acc0 = 0.f, acc1 = 0.f;
        int k = k0;
        for (; k + 1 <= k1; k += 2) {
            acc0 = fmaf(s[t + k - 255], s[k],     acc0);
            acc1 = fmaf(s[t + k - 254], s[k + 1], acc1);
        }
        if (k <= k1) acc0 = fmaf(s[t + k - 255], s[k], acc0);
        r0[t] = acc0 + acc1;
        i0[t] = 0.f;
    }

    float *fr, *fi;
    fft512x1(r0, i0, r1, i1, tc, ts, tid, fr, fi);

    const float SCC = SC_ORTHO / 256.0f;
    for (int n = tid; n < NF_; n += 512) {
        csr[n] = fr[n] * SCC;
        csi[n] = fi[n] * SCC;
    }
    __syncthreads();

    // load this half's 8 channels into FFT buffers
    {
        const float4* xr = (const float4*)(x + (size_t)b * 512 * 16);
#pragma unroll
        for (int i = 0; i < 2; i++) {
            int e = tid + i * 512;            // 0..1023
            int t = e >> 1, j = e & 1;
            float4 v = xr[t * 4 + g * 2 + j];
            int c0 = j * 4;
            r0[(c0 + 0) * 512 + t] = v.x; i0[(c0 + 0) * 512 + t] = 0.f;
            r0[(c0 + 1) * 512 + t] = v.y; i0[(c0 + 1) * 512 + t] = 0.f;
            r0[(c0 + 2) * 512 + t] = v.z; i0[(c0 + 2) * 512 + t] = 0.f;
            r0[(c0 + 3) * 512 + t] = v.w; i0[(c0 + 3) * 512 + t] = 0.f;
        }
    }
    float *gfr, *gfi;
    fft512x8(r0, i0, r1, i1, tc, ts, tid, gfr, gfi);

    // features + proj + heads: 8-lane team per (ch, n) item
    {
        int lane8 = tid & 7;           // h-chunk owner: h in [lane8*8, lane8*8+8)
        int team  = tid >> 3;          // 64 teams
        int h0 = lane8 * 8;
        const int NITEM = 8 * NF_;     // 2056
        for (int it = team; it < NITEM; it += 64) {
            int ch = it / NF_;
            int n  = it - ch * NF_;
            int m  = b * 16 + g * 8 + ch;
            size_t id = (size_t)m * NF_ + n;

            float re = gfr[ch * 512 + n] * SC_ORTHO + csr[n];
            float im = gfi[ch * 512 + n] * SC_ORTHO + csi[n];
            if (lane8 == 0) {
                g_fft_re[id] = re;
                g_fft_im[id] = im;
            }
            float s2 = re * re + im * im;
            float mag, sa, ca;
            if (s2 > 0.f) {
                float inv = rsqrtf(s2);
                mag = s2 * inv; sa = im * inv; ca = re * inv;
            } else { mag = 0.f; sa = 0.f; ca = 1.f; }
            float freqv = (float)n * 0.1953125f;

            float dm = 0.f, dp = 0.f;
            uint32_t pk[4];
#pragma unroll
            for (int j = 0; j < 2; j++) {
                int h = h0 + j * 4;
                float4 w0 = *(const float4*)&wp[h];
                float4 w1 = *(const float4*)&wp[64 + h];
                float4 w2 = *(const float4*)&wp[128 + h];
                float4 w3 = *(const float4*)&wp[192 + h];
                float4 bb = *(const float4*)&bpp[h];
                float4 v;
                v.x = fmaxf(fmaf(mag, w0.x, fmaf(sa, w1.x, fmaf(ca, w2.x, fmaf(freqv, w3.x, bb.x)))), 0.f);
                v.y = fmaxf(fmaf(mag, w0.y, fmaf(sa, w1.y, fmaf(ca, w2.y, fmaf(freqv, w3.y, bb.y)))), 0.f);
                v.z = fmaxf(fmaf(mag, w0.z, fmaf(sa, w1.z, fmaf(ca, w2.z, fmaf(freqv, w3.z, bb.z)))), 0.f);
                v.w = fmaxf(fmaf(mag, w0.w, fmaf(sa, w1.w, fmaf(ca, w2.w, fmaf(freqv, w3.w, bb.w)))), 0.f);
                pk[j * 2]     = packbf(v.x, v.y);
                pk[j * 2 + 1] = packbf(v.z, v.w);
                float4 a = __ldg((const float4*)&mag_w[(size_t)n * 64 + h]);
                float4 c = __ldg((const float4*)&ph_w[(size_t)n * 64 + h]);
                dm = fmaf(v.x, a.x, dm); dm = fmaf(v.y, a.y, dm);
                dm = fmaf(v.z, a.z, dm); dm = fmaf(v.w, a.w, dm);
                dp = fmaf(v.x, c.x, dp); dp = fmaf(v.y, c.y, dp);
                dp = fmaf(v.z, c.z, dp); dp = fmaf(v.w, c.w, dp);
            }
            // coalesced proj store: lane8 writes its 16B chunk
            *(uint4*)(g_flat + (size_t)m * K_ + (size_t)n * 64 + h0) =
                make_uint4(pk[0], pk[1], pk[2], pk[3]);

            // reduce dm, dp over the 8-lane team
#pragma unroll
            for (int off = 4; off >= 1; off >>= 1) {
                dm += __shfl_xor_sync(0xffffffffu, dm, off, 8);
                dp += __shfl_xor_sync(0xffffffffu, dp, off, 8);
            }
            if (lane8 == 0) {
                float mo  = fmaxf(dm + __ldg(&mag_b[n]), 0.f);
                float phv = 6.283185307179586f * sigf(dp + __ldg(&ph_b[n]));
                float sp, cp;
                __sincosf(phv, &sp, &cp);
                g_new_re[id] = mo * cp;
                g_new_im[id] = mo * sp;
            }
        }
    }
}

// ---------------- kernel 2: bf16 mma.sync (m16n8k16) split-K GEMM (R6 version) ----------------
#define BK_       64
#define NCHUNK_   (K_/BK_)        // 257
#define ASTRIDE_W 36
#define A_WORDS_  (128*ASTRIDE_W)
#define B_WORDS_  (96*ASTRIDE_W)
#define STG_WORDS_ (A_WORDS_+B_WORDS_)
#define GEMM_SMEM_ (3*STG_WORDS_*4)

__device__ __forceinline__ void load_chunk(uint32_t sbase, const __nv_bfloat16* __restrict__ Ab,
                                           const __nv_bfloat16* __restrict__ Bb, int kbase, int tid)
{
    uint32_t sA = sbase;
    uint32_t sB = sbase + A_WORDS_ * 4;
#pragma unroll
    for (int i = 0; i < 4; i++) {
        int g = tid + (i << 8);
        int r = g >> 3, c = g & 7;
        CP_ASYNC16(sA + (uint32_t)(r * (ASTRIDE_W*4) + c * 16),
                   Ab + (size_t)r * K_ + kbase + c * 8);
    }
#pragma unroll
    for (int i = 0; i < 3; i++) {
        int g = tid + (i << 8);
        int r = g >> 3, c = g & 7;
        CP_ASYNC16(sB + (uint32_t)(r * (ASTRIDE_W*4) + c * 16),
                   Bb + (size_t)r * K_ + kbase + c * 8);
    }
    asm volatile("cp.async.commit_group;\n" ::: "memory");
}

__global__ void __launch_bounds__(256, 2) k_gemm()
{
    extern __shared__ __align__(16) uint32_t smem[];

    int tid = threadIdx.x;
    int nt0 = blockIdx.x;
    int m0  = blockIdx.y * 128;
    int s   = blockIdx.z;
    const __nv_bfloat16* Ab = g_flat + (size_t)m0 * K_;
    const __nv_bfloat16* Bb = g_wt + (size_t)(nt0 * 96) * K_;

    int warp = tid >> 5, lane = tid & 31;
    int wm = warp & 3;
    int wn = warp >> 2;
    int lr = lane >> 2, lc = lane & 3;

    int li = lane >> 3, lrr = lane & 7;
    uint32_t aoff[2], boff[3];
#pragma unroll
    for (int mt = 0; mt < 2; mt++)
        aoff[mt] = (uint32_t)(((wm * 32 + mt * 16 + (li & 1) * 8 + lrr) * ASTRIDE_W + (li >> 1) * 4) * 4);
#pragma unroll
    for (int p = 0; p < 3; p++)
        boff[p] = (uint32_t)(((wn * 48 + (2 * p + (li >> 1)) * 8 + lrr) * ASTRIDE_W + (li & 1) * 4) * 4
                             + A_WORDS_ * 4);

    float acc[2][6][4];
#pragma unroll
    for (int i = 0; i < 2; i++)
#pragma unroll
        for (int j = 0; j < 6; j++)
#pragma unroll
            for (int q = 0; q < 4; q++) acc[i][j][q] = 0.f;

    const int cs = (s * NCHUNK_) / SPLITS_;
    const int ce = ((s + 1) * NCHUNK_) / SPLITS_;
    const int CN = ce - cs;

    uint32_t sb = smem_u32(smem);

    load_chunk(sb + 0 * STG_WORDS_ * 4, Ab, Bb, (cs + 0) * BK_, tid);
    load_chunk(sb + 1 * STG_WORDS_ * 4, Ab, Bb, (cs + 1) * BK_, tid);

    for (int i = 0; i < CN; i++) {
        if (i + 2 < CN)
            load_chunk(sb + ((i + 2) % 3) * STG_WORDS_ * 4, Ab, Bb, (cs + i + 2) * BK_, tid);
        else
            asm volatile("cp.async.commit_group;\n" ::: "memory");
        asm volatile("cp.async.wait_group 2;\n" ::: "memory");
        __syncthreads();

        uint32_t stage = sb + (uint32_t)((i % 3) * STG_WORDS_ * 4);

#pragma unroll
        for (int kt = 0; kt < 4; kt++) {
            uint32_t kb = stage + (uint32_t)(kt * 32);
            uint32_t a[2][4];
            LDSM_X4(a[0][0], a[0][1], a[0][2], a[0][3], kb + aoff[0]);
            LDSM_X4(a[1][0], a[1][1], a[1][2], a[1][3], kb + aoff[1]);
            uint32_t bfr[6][2];
            LDSM_X4(bfr[0][0], bfr[0][1], bfr[1][0], bfr[1][1], kb + boff[0]);
            LDSM_X4(bfr[2][0], bfr[2][1], bfr[3][0], bfr[3][1], kb + boff[1]);
            LDSM_X4(bfr[4][0], bfr[4][1], bfr[5][0], bfr[5][1], kb + boff[2]);
#pragma unroll
            for (int mt = 0; mt < 2; mt++)
#pragma unroll
                for (int nt = 0; nt < 6; nt++)
                    mma_bf16(acc[mt][nt], a[mt], bfr[nt]);
        }
        __syncthreads();
    }

    float* P = g_part[s];
#pragma unroll
    for (int mt = 0; mt < 2; mt++) {
        int row = m0 + wm * 32 + mt * 16 + lr;
#pragma unroll
        for (int nt = 0; nt < 6; nt++) {
            int col = nt0 * 96 + wn * 48 + nt * 8 + lc * 2;
            float2 v0 = make_float2(acc[mt][nt][0], acc[mt][nt][1]);
            float2 v1 = make_float2(acc[mt][nt][2], acc[mt][nt][3]);
            *(float2*)(P + (size_t)row * NPAD_ + col)       = v0;
            *(float2*)(P + (size_t)(row + 8) * NPAD_ + col) = v1;
        }
    }
}

// ---------------- kernel 3: bwd — reduce+gate+blend + 16 iFFTs + residual + LayerNorm ----------------
#define BWD_SMEMF 34048

__global__ void __launch_bounds__(512) k_bwd(
    const float* __restrict__ x, float* __restrict__ out,
    const float* __restrict__ bg,
    const float* __restrict__ gamma, const float* __restrict__ beta)
{
    extern __shared__ __align__(16) float sm[];
    int b = blockIdx.x, tid = threadIdx.x;

    float* r0  = sm;
    float* i0  = sm + 4096;
    float* r1  = sm + 8192;
    float* i1  = sm + 12288;
    float* fre = sm + 16384;   // [16][264]
    float* fim = sm + 20608;
    float* y   = sm + 24832;   // [512][17]
    float* tc  = sm + 33536;
    float* ts  = sm + 33792;

    if (tid < 256) {
        float _s, _c;
        sincosf(3.14159265358979323846f * (float)tid * (1.0f / 256.0f), &_s, &_c);
        tc[tid] = _c; ts[tid] = _s;
    }

    // split-K reduce + gate + blend
    for (int p = tid; p < 16 * NF_; p += 512) {
        int f = p / NF_;
        int n = p - f * NF_;
        int m = b * 16 + f;
        size_t pofs = (size_t)m * NPAD_ + n;
        float acc = 0.f;
#pragma unroll
        for (int s2 = 0; s2 < SPLITS_; s2++) acc += g_part[s2][pofs];
        float g = acc + __ldg(&bg[n]);
        g = g * sigf(g);
        float w = sigf(g);
        size_t id = (size_t)m * NF_ + n;
        fre[f * 264 + n] = w * g_new_re[id] + (1.f - w) * g_fft_re[id];
        fim[f * 264 + n] = w * g_new_im[id] + (1.f - w) * g_fft_im[id];
    }

    for (int g = 0; g < 2; g++) {
        __syncthreads();
#pragma unroll
        for (int i = 0; i < 8; i++) {
            int e = tid + i * 512;
            int ch = e >> 9, pos = e & 511;
            int f = g * 8 + ch;
            float re, im;
            if (pos == 0)        { re = fre[f * 264];       im = 0.f; }
            else if (pos < 256)  { re = fre[f * 264 + pos]; im = fim[f * 264 + pos]; }
            else if (pos == 256) { re = fre[f * 264 + 256]; im = 0.f; }
            else                 { re = fre[f * 264 + 512 - pos]; im = -fim[f * 264 + 512 - pos]; }
            r0[ch * 512 + pos] = re;
            i0[ch * 512 + pos] = im;
        }
        float *fr2, *fi2;
        fft512x8(r0, i0, r1, i1, tc, ts, tid, fr2, fi2);
#pragma unroll
        for (int i = 0; i < 8; i++) {
            int e = tid + i * 512;
            int ch = e >> 9, t = e & 511;
            y[t * 17 + g * 8 + ch] = fr2[ch * 512 + t] * SC_ORTHO;
        }
    }
    __syncthreads();

    // residual + LayerNorm, thread t owns row t
    {
        int t = tid;
        const float4* xr = (const float4*)(x + ((size_t)(b * 512 + t)) * 16);
        float v[16];
#pragma unroll
        for (int q = 0; q < 4; q++) {
            float4 xv = xr[q];
            v[q * 4 + 0] = y[t * 17 + q * 4 + 0] + xv.x;
            v[q * 4 + 1] = y[t * 17 + q * 4 + 1] + xv.y;
            v[q * 4 + 2] = y[t * 17 + q * 4 + 2] + xv.z;
            v[q * 4 + 3] = y[t * 17 + q * 4 + 3] + xv.w;
        }
        float smv = 0.f;
#pragma unroll
        for (int i = 0; i < 16; i++) smv += v[i];
        float mu = smv * (1.f / 16.f);
        float ss = 0.f;
#pragma unroll
        for (int i = 0; i < 16; i++) { float d = v[i] - mu; ss = fmaf(d, d, ss); }
        float inv = rsqrtf(ss * (1.f / 16.f) + 1e-5f);
        float4* ov = (float4*)(out + ((size_t)(b * 512 + t)) * 16);
#pragma unroll
        for (int q = 0; q < 4; q++) {
            float4 o;
            o.x = (v[q * 4 + 0] - mu) * inv * __ldg(&gamma[q * 4 + 0]) + __ldg(&beta[q * 4 + 0]);
            o.y = (v[q * 4 + 1] - mu) * inv * __ldg(&gamma[q * 4 + 1]) + __ldg(&beta[q * 4 + 1]);
            o.z = (v[q * 4 + 2] - mu) * inv * __ldg(&gamma[q * 4 + 2]) + __ldg(&beta[q * 4 + 2]);
            o.w = (v[q * 4 + 3] - mu) * inv * __ldg(&gamma[q * 4 + 3]) + __ldg(&beta[q * 4 + 3]);
            ov[q] = o;
        }
    }
}

// ---------------- launcher: 3 kernels ----------------
extern "C" void kernel_launch(void* const* d_in, const int* in_sizes, int n_in,
                              void* d_out, int out_size)
{
    const float* x       = (const float*)d_in[0];
    const float* W_proj  = (const float*)d_in[1];
    const float* b_proj  = (const float*)d_in[2];
    const float* W_gate  = (const float*)d_in[3];
    const float* b_gate  = (const float*)d_in[4];
    const float* mag_w   = (const float*)d_in[5];
    const float* mag_b   = (const float*)d_in[6];
    const float* phase_w = (const float*)d_in[7];
    const float* phase_b = (const float*)d_in[8];
    const float* ln_g    = (const float*)d_in[9];
    const float* ln_b    = (const float*)d_in[10];
    float* out = (float*)d_out;

    cudaFuncSetAttribute(k_fwd,  cudaFuncAttributeMaxDynamicSharedMemorySize, FWD_SMEMF * 4);
    cudaFuncSetAttribute(k_gemm, cudaFuncAttributeMaxDynamicSharedMemorySize, GEMM_SMEM_);
    cudaFuncSetAttribute(k_bwd,  cudaFuncAttributeMaxDynamicSharedMemorySize, BWD_SMEMF * 4);

    k_fwd<<<NHEAVY_ + NT_BLKS_, 512, FWD_SMEMF * 4>>>(x, W_proj, b_proj, mag_w, mag_b,
                                                      phase_w, phase_b, W_gate);
    k_gemm<<<dim3(3, 16, SPLITS_), 256, GEMM_SMEM_>>>();
    k_bwd<<<B_, 512, BWD_SMEMF * 4>>>(x, out, b_gate, ln_g, ln_b);
}

// round 10
// speedup vs baseline: 5.3089x; 1.0858x over previous
#include <cuda_runtime.h>
#include <cuda_bf16.h>
#include <math.h>
#include <stdint.h>

#define B_    128
#define H_    512
#define F_    16
#define HID_  64
#define NF_   257
#define M_    (B_*F_)       // 2048
#define K_    (NF_*HID_)    // 16448
#define NPAD_ 288
#define SPLITS_ 6

// ---------------- scratch (static device memory; no allocations) ----------------
__device__ __align__(128) float g_fft_re[M_*NF_];
__device__ __align__(128) float g_fft_im[M_*NF_];
__device__ __align__(128) float g_new_re[M_*NF_];
__device__ __align__(128) float g_new_im[M_*NF_];
__device__ __align__(128) __nv_bfloat16 g_wt[(size_t)NPAD_*K_];   // W_gate^T [n][k] bf16
__device__ __align__(128) float g_part[SPLITS_][(size_t)M_*NPAD_];
__device__ __align__(128) __nv_bfloat16 g_flat[(size_t)M_*K_];    // proj bf16, [m][n*64+h]

// ================= helpers =================
#define CP_ASYNC16(dst, src) \
    asm volatile("cp.async.cg.shared.global [%0], [%1], 16;\n" :: "r"(dst), "l"(src))
__device__ __forceinline__ uint32_t smem_u32(const void* p) {
    uint32_t a;
    asm("{ .reg .u64 t; cvta.to.shared.u64 t, %1; cvt.u32.u64 %0, t; }" : "=r"(a) : "l"(p));
    return a;
}
__device__ __forceinline__ void mma_bf16(float c[4], const uint32_t a[4], const uint32_t b[2]) {
    asm volatile(
        "mma.sync.aligned.m16n8k16.row.col.f32.bf16.bf16.f32 "
        "{%0,%1,%2,%3}, {%4,%5,%6,%7}, {%8,%9}, {%0,%1,%2,%3};"
        : "+f"(c[0]), "+f"(c[1]), "+f"(c[2]), "+f"(c[3])
        : "r"(a[0]), "r"(a[1]), "r"(a[2]), "r"(a[3]), "r"(b[0]), "r"(b[1]));
}
#define LDSM_X4(R0, R1, R2, R3, ADDR) \
    asm volatile("ldmatrix.sync.aligned.m8n8.x4.shared.b16 {%0,%1,%2,%3}, [%4];" \
        : "=r"(R0), "=r"(R1), "=r"(R2), "=r"(R3) : "r"(ADDR))
__device__ __forceinline__ uint32_t packbf(float x, float y) {
    __nv_bfloat162 h = __float22bfloat162_rn(make_float2(x, y));
    return *(uint32_t*)&h;
}
__device__ __forceinline__ float sigf(float x) {
    return __fdividef(1.f, 1.f + __expf(-x));
}
#define SC_ORTHO 0.044194173824159216f

// ---------------- batched 8-channel 512-pt Stockham FFT (512 threads) ----------------
__device__ __forceinline__ void fft512x8(float* r0, float* i0, float* r1, float* i1,
                                         const float* tc, const float* ts,
                                         int tid, float*& outr, float*& outi)
{
    float *ar = r0, *ai = i0, *br = r1, *bi = i1;
    int u = tid & 255, cb = (tid >> 8) << 2;
#pragma unroll
    for (int st = 0; st < 9; st++) {
        __syncthreads();
        int m = 1 << st;
        int j = u >> st, k = u & (m - 1), idx = u & ~(m - 1);
        float wc = tc[idx], ws = ts[idx];
        int o0 = k + (j << (st + 1));
#pragma unroll
        for (int q = 0; q < 4; q++) {
            int off = (cb + q) << 9;
            float c0r = ar[off + u],       c0i = ai[off + u];
            float c1r = ar[off + u + 256], c1i = ai[off + u + 256];
            float sr = c0r - c1r, si = c0i - c1i;
            br[off + o0]     = c0r + c1r;
            bi[off + o0]     = c0i + c1i;
            br[off + o0 + m] = wc * sr - ws * si;
            bi[off + o0 + m] = wc * si + ws * sr;
        }
        float* t;
        t = ar; ar = br; br = t;
        t = ai; ai = bi; bi = t;
    }
    __syncthreads();
    outr = ar; outi = ai;
}

// single-channel 512-pt FFT on channel-0 slice; only threads <256 butterfly
__device__ __forceinline__ void fft512x1(float* r0, float* i0, float* r1, float* i1,
                                         const float* tc, const float* ts,
                                         int tid, float*& outr, float*& outi)
{
    float *ar = r0, *ai = i0, *br = r1, *bi = i1;
#pragma unroll
    for (int st = 0; st < 9; st++) {
        __syncthreads();
        if (tid < 256) {
            int m = 1 << st;
            int j = tid >> st, k = tid & (m - 1), idx = tid & ~(m - 1);
            float wc = tc[idx], ws = ts[idx];
            int o0 = k + (j << (st + 1));
            float c0r = ar[tid],       c0i = ai[tid];
            float c1r = ar[tid + 256], c1i = ai[tid + 256];
            float sr = c0r - c1r, si = c0i - c1i;
            br[o0]     = c0r + c1r;
            bi[o0]     = c0i + c1i;
            br[o0 + m] = wc * sr - ws * si;
            bi[o0 + m] = wc * si + ws * sr;
        }
        float* t;
        t = ar; ar = br; br = t;
        t = ai; ai = bi; bi = t;
    }
    __syncthreads();
    outr = ar; outi = ai;
}

// ---------------- kernel 1: fwd — (batch,half) blocks: csd+fft+proj+heads; plus transpose ----------------
// smem layout (floats), float4 buffers 16B-aligned:
// r0 @0, i0 @4096, r1 @8192, i1 @12288, s @16384 (512),
// csr @16896 (264), csi @17160 (264), tc @17424 (256), ts @17680 (256),
// wp @17936 (256), bp @18192 (64), sp @18256 (1024). total 19280 floats.
#define FWD_SMEMF 19280
#define NHEAVY_   (B_*2)    // 256 (batch, channel-half) blocks
#define NT_BLKS_  (257*9)   // 2313 transpose tiles (64k x 32n)

__global__ void __launch_bounds__(512) k_fwd(
    const float* __restrict__ x,
    const float* __restrict__ Wp,  const float* __restrict__ bp,
    const float* __restrict__ mag_w, const float* __restrict__ mag_b,
    const float* __restrict__ ph_w,  const float* __restrict__ ph_b,
    const float* __restrict__ Wg)
{
    extern __shared__ __align__(16) float sm[];
    int tid = threadIdx.x;

    if (blockIdx.x >= NHEAVY_) {
        // ---- transpose tile: Wg[K][257] -> g_wt[288][K] bf16 (zero pad) ----
        float* tile = sm;                       // [64][33]
        int t  = blockIdx.x - NHEAVY_;
        int kt = t % 257, nt = t / 257;
        int kb = kt * 64, nb = nt * 32;
        int col = tid & 31, rowb = tid >> 5;
#pragma unroll
        for (int rr = 0; rr < 4; rr++) {
            int row = rowb + rr * 16;
            int nn = nb + col;
            tile[row * 33 + col] = (nn < NF_) ? Wg[(size_t)(kb + row) * NF_ + nn] : 0.f;
        }
        __syncthreads();
#pragma unroll
        for (int i = 0; i < 4; i++) {
            int e = tid + i * 512;
            int nl = e >> 6, kl = e & 63;
            g_wt[(size_t)(nb + nl) * K_ + kb + kl] = __float2bfloat16(tile[kl * 33 + nl]);
        }
        return;
    }

    // ---- heavy block: batch b, channel-half g ----
    int b = blockIdx.x >> 1;
    int g = blockIdx.x & 1;
    float* r0  = sm;
    float* i0  = sm + 4096;
    float* r1  = sm + 8192;
    float* i1  = sm + 12288;
    float* s   = sm + 16384;
    float* csr = sm + 16896;
    float* csi = sm + 17160;
    float* tc  = sm + 17424;
    float* ts  = sm + 17680;
    float* wp  = sm + 17936;
    float* bpp = sm + 18192;
    float* sp  = sm + 18256;   // zero-padded: sp[i] = s[i-255] for i in [255,767)

    if (tid < 256) {
        float _s, _c;
        sincosf(-3.14159265358979323846f * (float)tid * (1.0f / 256.0f), &_s, &_c);
        tc[tid] = _c; ts[tid] = _s;
    } else {
        wp[tid - 256] = Wp[tid - 256];
    }
    if (tid < 64) bpp[tid] = bp[tid];

    // channel sum -> s, zero sp wings
    {
        const float4* xr = (const float4*)(x + (size_t)b * 512 * 16);
        float4 a = xr[tid * 4 + 0], c = xr[tid * 4 + 1], d = xr[tid * 4 + 2], e = xr[tid * 4 + 3];
        s[tid] = (a.x + a.y + a.z + a.w) + (c.x + c.y + c.z + c.w)
               + (d.x + d.y + d.z + d.w) + (e.x + e.y + e.z + e.w);
        sp[tid] = 0.f;
        sp[512 + tid] = 0.f;
    }
    __syncthreads();
    sp[255 + tid] = s[tid];
    __syncthreads();

    // autocorrelation (uniform range, broadcast float4 on s) -> r0 (ch0 slice)
    {
        int t = tid;
        float acc0 = 0.f, acc1 = 0.f, acc2 = 0.f, acc3 = 0.f;
#pragma unroll 4
        for (int k = 0; k < 512; k += 4) {
            float4 sk = *(const float4*)&s[k];
            acc0 = fmaf(sp[t + k + 0], sk.x, acc0);
            acc1 = fmaf(sp[t + k + 1], sk.y, acc1);
            acc2 = fmaf(sp[t + k + 2], sk.z, acc2);
            acc3 = fmaf(sp[t + k + 3], sk.w, acc3);
        }
        r0[t] = (acc0 + acc1) + (acc2 + acc3);
        i0[t] = 0.f;
    }

    float *fr, *fi;
    fft512x1(r0, i0, r1, i1, tc, ts, tid, fr, fi);

    const float SCC = SC_ORTHO / 256.0f;
    for (int n = tid; n < NF_; n += 512) {
        csr[n] = fr[n] * SCC;
        csi[n] = fi[n] * SCC;
    }
    __syncthreads();

    // load this half's 8 channels into FFT buffers
    {
        const float4* xr = (const float4*)(x + (size_t)b * 512 * 16);
#pragma unroll
        for (int i = 0; i < 2; i++) {
            int e = tid + i * 512;            // 0..1023
            int t = e >> 1, j = e & 1;
            float4 v = xr[t * 4 + g * 2 + j];
            int c0 = j * 4;
            r0[(c0 + 0) * 512 + t] = v.x; i0[(c0 + 0) * 512 + t] = 0.f;
            r0[(c0 + 1) * 512 + t] = v.y; i0[(c0 + 1) * 512 + t] = 0.f;
            r0[(c0 + 2) * 512 + t] = v.z; i0[(c0 + 2) * 512 + t] = 0.f;
            r0[(c0 + 3) * 512 + t] = v.w; i0[(c0 + 3) * 512 + t] = 0.f;
        }
    }
    float *gfr, *gfi;
    fft512x8(r0, i0, r1, i1, tc, ts, tid, gfr, gfi);

    // features + proj + heads: 16-lane team per (ch, n), weights hoisted to registers
    {
        int lane16 = tid & 15;         // h-chunk owner: h in [lane16*4, lane16*4+4)
        int team   = tid >> 4;         // 32 teams
        int h0 = lane16 * 4;
        float4 w0 = *(const float4*)&wp[h0];
        float4 w1 = *(const float4*)&wp[64 + h0];
        float4 w2 = *(const float4*)&wp[128 + h0];
        float4 w3 = *(const float4*)&wp[192 + h0];
        float4 bb = *(const float4*)&bpp[h0];

        const int NITEM = 8 * NF_;     // 2056
        for (int it = team; it < NITEM; it += 32) {
            int ch = it / NF_;
            int n  = it - ch * NF_;
            int m  = b * 16 + g * 8 + ch;
            size_t id = (size_t)m * NF_ + n;

            float re = gfr[ch * 512 + n] * SC_ORTHO + csr[n];
            float im = gfi[ch * 512 + n] * SC_ORTHO + csi[n];
            float s2 = re * re + im * im;
            float mag, sa, ca;
            if (s2 > 0.f) {
                float inv = rsqrtf(s2);
                mag = s2 * inv; sa = im * inv; ca = re * inv;
            } else { mag = 0.f; sa = 0.f; ca = 1.f; }
            float freqv = (float)n * 0.1953125f;

            float4 v;
            v.x = fmaxf(fmaf(mag, w0.x, fmaf(sa, w1.x, fmaf(ca, w2.x, fmaf(freqv, w3.x, bb.x)))), 0.f);
            v.y = fmaxf(fmaf(mag, w0.y, fmaf(sa, w1.y, fmaf(ca, w2.y, fmaf(freqv, w3.y, bb.y)))), 0.f);
            v.z = fmaxf(fmaf(mag, w0.z, fmaf(sa, w1.z, fmaf(ca, w2.z, fmaf(freqv, w3.z, bb.z)))), 0.f);
            v.w = fmaxf(fmaf(mag, w0.w, fmaf(sa, w1.w, fmaf(ca, w2.w, fmaf(freqv, w3.w, bb.w)))), 0.f);

            // coalesced proj store: 16 lanes x 8B = 128B contiguous
            *(uint2*)(g_flat + (size_t)m * K_ + (size_t)n * 64 + h0) =
                make_uint2(packbf(v.x, v.y), packbf(v.z, v.w));

            float4 a = __ldg((const float4*)&mag_w[(size_t)n * 64 + h0]);
            float4 c = __ldg((const float4*)&ph_w[(size_t)n * 64 + h0]);
            float dm = 0.f, dp = 0.f;
            dm = fmaf(v.x, a.x, dm); dm = fmaf(v.y, a.y, dm);
            dm = fmaf(v.z, a.z, dm); dm = fmaf(v.w, a.w, dm);
            dp = fmaf(v.x, c.x, dp); dp = fmaf(v.y, c.y, dp);
            dp = fmaf(v.z, c.z, dp); dp = fmaf(v.w, c.w, dp);

            // reduce dm, dp over the 16-lane team
#pragma unroll
            for (int off = 8; off >= 1; off >>= 1) {
                dm += __shfl_xor_sync(0xffffffffu, dm, off, 16);
                dp += __shfl_xor_sync(0xffffffffu, dp, off, 16);
            }
            if (lane16 == 0) {
                g_fft_re[id] = re;
                g_fft_im[id] = im;
                float mo  = fmaxf(dm + __ldg(&mag_b[n]), 0.f);
                float phv = 6.283185307179586f * sigf(dp + __ldg(&ph_b[n]));
                float spv, cpv;
                __sincosf(phv, &spv, &cpv);
                g_new_re[id] = mo * cpv;
                g_new_im[id] = mo * spv;
            }
        }
    }
}

// ---------------- kernel 2: bf16 mma.sync (m16n8k16) split-K GEMM (R6 version) ----------------
#define BK_       64
#define NCHUNK_   (K_/BK_)        // 257
#define ASTRIDE_W 36
#define A_WORDS_  (128*ASTRIDE_W)
#define B_WORDS_  (96*ASTRIDE_W)
#define STG_WORDS_ (A_WORDS_+B_WORDS_)
#define GEMM_SMEM_ (3*STG_WORDS_*4)

__device__ __forceinline__ void load_chunk(uint32_t sbase, const __nv_bfloat16* __restrict__ Ab,
                                           const __nv_bfloat16* __restrict__ Bb, int kbase, int tid)
{
    uint32_t sA = sbase;
    uint32_t sB = sbase + A_WORDS_ * 4;
#pragma unroll
    for (int i = 0; i < 4; i++) {
        int g = tid + (i << 8);
        int r = g >> 3, c = g & 7;
        CP_ASYNC16(sA + (uint32_t)(r * (ASTRIDE_W*4) + c * 16),
                   Ab + (size_t)r * K_ + kbase + c * 8);
    }
#pragma unroll
    for (int i = 0; i < 3; i++) {
        int g = tid + (i << 8);
        int r = g >> 3, c = g & 7;
        CP_ASYNC16(sB + (uint32_t)(r * (ASTRIDE_W*4) + c * 16),
                   Bb + (size_t)r * K_ + kbase + c * 8);
    }
    asm volatile("cp.async.commit_group;\n" ::: "memory");
}

__global__ void __launch_bounds__(256, 2) k_gemm()
{
    extern __shared__ __align__(16) uint32_t smem[];

    int tid = threadIdx.x;
    int nt0 = blockIdx.x;
    int m0  = blockIdx.y * 128;
    int s   = blockIdx.z;
    const __nv_bfloat16* Ab = g_flat + (size_t)m0 * K_;
    const __nv_bfloat16* Bb = g_wt + (size_t)(nt0 * 96) * K_;

    int warp = tid >> 5, lane = tid & 31;
    int wm = warp & 3;
    int wn = warp >> 2;
    int lr = lane >> 2, lc = lane & 3;

    int li = lane >> 3, lrr = lane & 7;
    uint32_t aoff[2], boff[3];
#pragma unroll
    for (int mt = 0; mt < 2; mt++)
        aoff[mt] = (uint32_t)(((wm * 32 + mt * 16 + (li & 1) * 8 + lrr) * ASTRIDE_W + (li >> 1) * 4) * 4);
#pragma unroll
    for (int p = 0; p < 3; p++)
        boff[p] = (uint32_t)(((wn * 48 + (2 * p + (li >> 1)) * 8 + lrr) * ASTRIDE_W + (li & 1) * 4) * 4
                             + A_WORDS_ * 4);

    float acc[2][6][4];
#pragma unroll
    for (int i = 0; i < 2; i++)
#pragma unroll
        for (int j = 0; j < 6; j++)
#pragma unroll
            for (int q = 0; q < 4; q++) acc[i][j][q] = 0.f;

    const int cs = (s * NCHUNK_) / SPLITS_;
    const int ce = ((s + 1) * NCHUNK_) / SPLITS_;
    const int CN = ce - cs;

    uint32_t sb = smem_u32(smem);

    load_chunk(sb + 0 * STG_WORDS_ * 4, Ab, Bb, (cs + 0) * BK_, tid);
    load_chunk(sb + 1 * STG_WORDS_ * 4, Ab, Bb, (cs + 1) * BK_, tid);

    for (int i = 0; i < CN; i++) {
        if (i + 2 < CN)
            load_chunk(sb + ((i + 2) % 3) * STG_WORDS_ * 4, Ab, Bb, (cs + i + 2) * BK_, tid);
        else
            asm volatile("cp.async.commit_group;\n" ::: "memory");
        asm volatile("cp.async.wait_group 2;\n" ::: "memory");
        __syncthreads();

        uint32_t stage = sb + (uint32_t)((i % 3) * STG_WORDS_ * 4);

#pragma unroll
        for (int kt = 0; kt < 4; kt++) {
            uint32_t kb = stage + (uint32_t)(kt * 32);
            uint32_t a[2][4];
            LDSM_X4(a[0][0], a[0][1], a[0][2], a[0][3], kb + aoff[0]);
            LDSM_X4(a[1][0], a[1][1], a[1][2], a[1][3], kb + aoff[1]);
            uint32_t bfr[6][2];
            LDSM_X4(bfr[0][0], bfr[0][1], bfr[1][0], bfr[1][1], kb + boff[0]);
            LDSM_X4(bfr[2][0], bfr[2][1], bfr[3][0], bfr[3][1], kb + boff[1]);
            LDSM_X4(bfr[4][0], bfr[4][1], bfr[5][0], bfr[5][1], kb + boff[2]);
#pragma unroll
            for (int mt = 0; mt < 2; mt++)
#pragma unroll
                for (int nt = 0; nt < 6; nt++)
                    mma_bf16(acc[mt][nt], a[mt], bfr[nt]);
        }
        __syncthreads();
    }

    float* P = g_part[s];
#pragma unroll
    for (int mt = 0; mt < 2; mt++) {
        int row = m0 + wm * 32 + mt * 16 + lr;
#pragma unroll
        for (int nt = 0; nt < 6; nt++) {
            int col = nt0 * 96 + wn * 48 + nt * 8 + lc * 2;
            float2 v0 = make_float2(acc[mt][nt][0], acc[mt][nt][1]);
            float2 v1 = make_float2(acc[mt][nt][2], acc[mt][nt][3]);
            *(float2*)(P + (size_t)row * NPAD_ + col)       = v0;
            *(float2*)(P + (size_t)(row + 8) * NPAD_ + col) = v1;
        }
    }
}

// ---------------- kernel 3: bwd — reduce+gate+blend + 16 iFFTs + residual + LayerNorm ----------------
#define BWD_SMEMF 34048

__global__ void __launch_bounds__(512) k_bwd(
    const float* __restrict__ x, float* __restrict__ out,
    const float* __restrict__ bg,
    const float* __restrict__ gamma, const float* __restrict__ beta)
{
    extern __shared__ __align__(16) float sm[];
    int b = blockIdx.x, tid = threadIdx.x;

    float* r0  = sm;
    float* i0  = sm + 4096;
    float* r1  = sm + 8192;
    float* i1  = sm + 12288;
    float* fre = sm + 16384;   // [16][264]
    float* fim = sm + 20608;
    float* y   = sm + 24832;   // [512][17]
    float* tc  = sm + 33536;
    float* ts  = sm + 33792;

    if (tid < 256) {
        float _s, _c;
        sincosf(3.14159265358979323846f * (float)tid * (1.0f / 256.0f), &_s, &_c);
        tc[tid] = _c; ts[tid] = _s;
    }

    // split-K reduce + gate + blend
    for (int p = tid; p < 16 * NF_; p += 512) {
        int f = p / NF_;
        int n = p - f * NF_;
        int m = b * 16 + f;
        size_t pofs = (size_t)m * NPAD_ + n;
        float acc = 0.f;
#pragma unroll
        for (int s2 = 0; s2 < SPLITS_; s2++) acc += g_part[s2][pofs];
        float g = acc + __ldg(&bg[n]);
        g = g * sigf(g);
        float w = sigf(g);
        size_t id = (size_t)m * NF_ + n;
        fre[f * 264 + n] = w * g_new_re[id] + (1.f - w) * g_fft_re[id];
        fim[f * 264 + n] = w * g_new_im[id] + (1.f - w) * g_fft_im[id];
    }

    for (int g = 0; g < 2; g++) {
        __syncthreads();
#pragma unroll
        for (int i = 0; i < 8; i++) {
            int e = tid + i * 512;
            int ch = e >> 9, pos = e & 511;
            int f = g * 8 + ch;
            float re, im;
            if (pos == 0)        { re = fre[f * 264];       im = 0.f; }
            else if (pos < 256)  { re = fre[f * 264 + pos]; im = fim[f * 264 + pos]; }
            else if (pos == 256) { re = fre[f * 264 + 256]; im = 0.f; }
            else                 { re = fre[f * 264 + 512 - pos]; im = -fim[f * 264 + 512 - pos]; }
            r0[ch * 512 + pos] = re;
            i0[ch * 512 + pos] = im;
        }
        float *fr2, *fi2;
        fft512x8(r0, i0, r1, i1, tc, ts, tid, fr2, fi2);
#pragma unroll
        for (int i = 0; i < 8; i++) {
            int e = tid + i * 512;
            int ch = e >> 9, t = e & 511;
            y[t * 17 + g * 8 + ch] = fr2[ch * 512 + t] * SC_ORTHO;
        }
    }
    __syncthreads();

    // residual + LayerNorm, thread t owns row t
    {
        int t = tid;
        const float4* xr = (const float4*)(x + ((size_t)(b * 512 + t)) * 16);
        float v[16];
#pragma unroll
        for (int q = 0; q < 4; q++) {
            float4 xv = xr[q];
            v[q * 4 + 0] = y[t * 17 + q * 4 + 0] + xv.x;
            v[q * 4 + 1] = y[t * 17 + q * 4 + 1] + xv.y;
            v[q * 4 + 2] = y[t * 17 + q * 4 + 2] + xv.z;
            v[q * 4 + 3] = y[t * 17 + q * 4 + 3] + xv.w;
        }
        float smv = 0.f;
#pragma unroll
        for (int i = 0; i < 16; i++) smv += v[i];
        float mu = smv * (1.f / 16.f);
        float ss = 0.f;
#pragma unroll
        for (int i = 0; i < 16; i++) { float d = v[i] - mu; ss = fmaf(d, d, ss); }
        float inv = rsqrtf(ss * (1.f / 16.f) + 1e-5f);
        float4* ov = (float4*)(out + ((size_t)(b * 512 + t)) * 16);
#pragma unroll
        for (int q = 0; q < 4; q++) {
            float4 o;
            o.x = (v[q * 4 + 0] - mu) * inv * __ldg(&gamma[q * 4 + 0]) + __ldg(&beta[q * 4 + 0]);
            o.y = (v[q * 4 + 1] - mu) * inv * __ldg(&gamma[q * 4 + 1]) + __ldg(&beta[q * 4 + 1]);
            o.z = (v[q * 4 + 2] - mu) * inv * __ldg(&gamma[q * 4 + 2]) + __ldg(&beta[q * 4 + 2]);
            o.w = (v[q * 4 + 3] - mu) * inv * __ldg(&gamma[q * 4 + 3]) + __ldg(&beta[q * 4 + 3]);
            ov[q] = o;
        }
    }
}

// ---------------- launcher: 3 kernels ----------------
extern "C" void kernel_launch(void* const* d_in, const int* in_sizes, int n_in,
                              void* d_out, int out_size)
{
    const float* x       = (const float*)d_in[0];
    const float* W_proj  = (const float*)d_in[1];
    const float* b_proj  = (const float*)d_in[2];
    const float* W_gate  = (const float*)d_in[3];
    const float* b_gate  = (const float*)d_in[4];
    const float* mag_w   = (const float*)d_in[5];
    const float* mag_b   = (const float*)d_in[6];
    const float* phase_w = (const float*)d_in[7];
    const float* phase_b = (const float*)d_in[8];
    const float* ln_g    = (const float*)d_in[9];
    const float* ln_b    = (const float*)d_in[10];
    float* out = (float*)d_out;

    cudaFuncSetAttribute(k_fwd,  cudaFuncAttributeMaxDynamicSharedMemorySize, FWD_SMEMF * 4);
    cudaFuncSetAttribute(k_gemm, cudaFuncAttributeMaxDynamicSharedMemorySize, GEMM_SMEM_);
    cudaFuncSetAttribute(k_bwd,  cudaFuncAttributeMaxDynamicSharedMemorySize, BWD_SMEMF * 4);

    k_fwd<<<NHEAVY_ + NT_BLKS_, 512, FWD_SMEMF * 4>>>(x, W_proj, b_proj, mag_w, mag_b,
                                                      phase_w, phase_b, W_gate);
    k_gemm<<<dim3(3, 16, SPLITS_), 256, GEMM_SMEM_>>>();
    k_bwd<<<B_, 512, BWD_SMEMF * 4>>>(x, out, b_gate, ln_g, ln_b);
}

// round 11
// speedup vs baseline: 5.5834x; 1.0517x over previous
#include <cuda_runtime.h>
#include <cuda_bf16.h>
#include <math.h>
#include <stdint.h>

#define B_    128
#define H_    512
#define F_    16
#define HID_  64
#define NF_   257
#define M_    (B_*F_)       // 2048
#define K_    (NF_*HID_)    // 16448
#define NPAD_ 288
#define SPLITS_ 6

// ---------------- scratch (static device memory; no allocations) ----------------
__device__ __align__(128) float g_fft_re[M_*NF_];
__device__ __align__(128) float g_fft_im[M_*NF_];
__device__ __align__(128) float g_new_re[M_*NF_];
__device__ __align__(128) float g_new_im[M_*NF_];
__device__ __align__(128) __nv_bfloat16 g_wt[(size_t)NPAD_*K_];   // W_gate^T [n][k] bf16
__device__ __align__(128) float g_part[SPLITS_][(size_t)M_*NPAD_];
__device__ __align__(128) __nv_bfloat16 g_flat[(size_t)M_*K_];    // proj bf16, [m][n*64+h]

// ================= helpers =================
#define CP_ASYNC16(dst, src) \
    asm volatile("cp.async.cg.shared.global [%0], [%1], 16;\n" :: "r"(dst), "l"(src))
__device__ __forceinline__ uint32_t smem_u32(const void* p) {
    uint32_t a;
    asm("{ .reg .u64 t; cvta.to.shared.u64 t, %1; cvt.u32.u64 %0, t; }" : "=r"(a) : "l"(p));
    return a;
}
__device__ __forceinline__ void mma_bf16(float c[4], const uint32_t a[4], const uint32_t b[2]) {
    asm volatile(
        "mma.sync.aligned.m16n8k16.row.col.f32.bf16.bf16.f32 "
        "{%0,%1,%2,%3}, {%4,%5,%6,%7}, {%8,%9}, {%0,%1,%2,%3};"
        : "+f"(c[0]), "+f"(c[1]), "+f"(c[2]), "+f"(c[3])
        : "r"(a[0]), "r"(a[1]), "r"(a[2]), "r"(a[3]), "r"(b[0]), "r"(b[1]));
}
#define LDSM_X4(R0, R1, R2, R3, ADDR) \
    asm volatile("ldmatrix.sync.aligned.m8n8.x4.shared.b16 {%0,%1,%2,%3}, [%4];" \
        : "=r"(R0), "=r"(R1), "=r"(R2), "=r"(R3) : "r"(ADDR))
__device__ __forceinline__ uint32_t packbf(float x, float y) {
    __nv_bfloat162 h = __float22bfloat162_rn(make_float2(x, y));
    return *(uint32_t*)&h;
}
__device__ __forceinline__ float sigf(float x) {
    return __fdividef(1.f, 1.f + __expf(-x));
}
#define SC_ORTHO 0.044194173824159216f

// ---------------- batched N-channel 512-pt Stockham FFT (512 threads) ----------------
// 8-channel: each thread does 4 butterflies
__device__ __forceinline__ void fft512x8(float* r0, float* i0, float* r1, float* i1,
                                         const float* tc, const float* ts,
                                         int tid, float*& outr, float*& outi)
{
    float *ar = r0, *ai = i0, *br = r1, *bi = i1;
    int u = tid & 255, cb = (tid >> 8) << 2;
#pragma unroll
    for (int st = 0; st < 9; st++) {
        __syncthreads();
        int m = 1 << st;
        int j = u >> st, k = u & (m - 1), idx = u & ~(m - 1);
        float wc = tc[idx], ws = ts[idx];
        int o0 = k + (j << (st + 1));
#pragma unroll
        for (int q = 0; q < 4; q++) {
            int off = (cb + q) << 9;
            float c0r = ar[off + u],       c0i = ai[off + u];
            float c1r = ar[off + u + 256], c1i = ai[off + u + 256];
            float sr = c0r - c1r, si = c0i - c1i;
            br[off + o0]     = c0r + c1r;
            bi[off + o0]     = c0i + c1i;
            br[off + o0 + m] = wc * sr - ws * si;
            bi[off + o0 + m] = wc * si + ws * sr;
        }
        float* t;
        t = ar; ar = br; br = t;
        t = ai; ai = bi; bi = t;
    }
    __syncthreads();
    outr = ar; outi = ai;
}

// 5-channel: channels {tid>>8, 2+(tid>>8)} for all threads, channel 4 for tid<256
__device__ __forceinline__ void fft512x5(float* r0, float* i0, float* r1, float* i1,
                                         const float* tc, const float* ts,
                                         int tid, float*& outr, float*& outi)
{
    float *ar = r0, *ai = i0, *br = r1, *bi = i1;
    int u = tid & 255;
    int c0ch = tid >> 8;            // 0 or 1
#pragma unroll
    for (int st = 0; st < 9; st++) {
        __syncthreads();
        int m = 1 << st;
        int j = u >> st, k = u & (m - 1), idx = u & ~(m - 1);
        float wc = tc[idx], ws = ts[idx];
        int o0 = k + (j << (st + 1));
#pragma unroll
        for (int q = 0; q < 2; q++) {
            int off = (c0ch + q * 2) << 9;
            float c0r = ar[off + u],       c0i = ai[off + u];
            float c1r = ar[off + u + 256], c1i = ai[off + u + 256];
            float sr = c0r - c1r, si = c0i - c1i;
            br[off + o0]     = c0r + c1r;
            bi[off + o0]     = c0i + c1i;
            br[off + o0 + m] = wc * sr - ws * si;
            bi[off + o0 + m] = wc * si + ws * sr;
        }
        if (tid < 256) {
            int off = 4 << 9;
            float c0r = ar[off + u],       c0i = ai[off + u];
            float c1r = ar[off + u + 256], c1i = ai[off + u + 256];
            float sr = c0r - c1r, si = c0i - c1i;
            br[off + o0]     = c0r + c1r;
            bi[off + o0]     = c0i + c1i;
            br[off + o0 + m] = wc * sr - ws * si;
            bi[off + o0 + m] = wc * si + ws * sr;
        }
        float* t;
        t = ar; ar = br; br = t;
        t = ai; ai = bi; bi = t;
    }
    __syncthreads();
    outr = ar; outi = ai;
}

// ---------------- kernel 1: fwd — (batch,half) blocks, packed real FFTs ----------------
// smem floats: r0 @0 (2560), i0 @2560, r1 @5120, i1 @7680, s @10240 (512),
// sp @10752 (1024), tc @11776 (256), ts @12032 (256), wp @12288 (256), bp @12544 (64)
#define FWD_SMEMF 12608
#define NHEAVY_   (B_*2)    // 256 (batch, channel-half) blocks
#define NT_BLKS_  (257*9)   // 2313 transpose tiles (64k x 32n)

__global__ void __launch_bounds__(512) k_fwd(
    const float* __restrict__ x,
    const float* __restrict__ Wp,  const float* __restrict__ bp,
    const float* __restrict__ mag_w, const float* __restrict__ mag_b,
    const float* __restrict__ ph_w,  const float* __restrict__ ph_b,
    const float* __restrict__ Wg)
{
    extern __shared__ __align__(16) float sm[];
    int tid = threadIdx.x;

    if (blockIdx.x >= NHEAVY_) {
        // ---- transpose tile: Wg[K][257] -> g_wt[288][K] bf16 (zero pad) ----
        float* tile = sm;                       // [64][33]
        int t  = blockIdx.x - NHEAVY_;
        int kt = t % 257, nt = t / 257;
        int kb = kt * 64, nb = nt * 32;
        int col = tid & 31, rowb = tid >> 5;
#pragma unroll
        for (int rr = 0; rr < 4; rr++) {
            int row = rowb + rr * 16;
            int nn = nb + col;
            tile[row * 33 + col] = (nn < NF_) ? Wg[(size_t)(kb + row) * NF_ + nn] : 0.f;
        }
        __syncthreads();
#pragma unroll
        for (int i = 0; i < 4; i++) {
            int e = tid + i * 512;
            int nl = e >> 6, kl = e & 63;
            g_wt[(size_t)(nb + nl) * K_ + kb + kl] = __float2bfloat16(tile[kl * 33 + nl]);
        }
        return;
    }

    // ---- heavy block: batch b, channel-half g ----
    int b = blockIdx.x >> 1;
    int g = blockIdx.x & 1;
    float* r0  = sm;
    float* i0  = sm + 2560;
    float* r1  = sm + 5120;
    float* i1  = sm + 7680;
    float* s   = sm + 10240;
    float* sp  = sm + 10752;   // zero-padded: sp[i] = s[i-255] for i in [255,767)
    float* tc  = sm + 11776;
    float* ts  = sm + 12032;
    float* wp  = sm + 12288;
    float* bpp = sm + 12544;

    if (tid < 256) {
        float _s, _c;
        sincosf(-3.14159265358979323846f * (float)tid * (1.0f / 256.0f), &_s, &_c);
        tc[tid] = _c; ts[tid] = _s;
    } else {
        wp[tid - 256] = Wp[tid - 256];
    }
    if (tid < 64) bpp[tid] = bp[tid];

    // channel sum -> s, zero sp wings; also load 8 packed channels (4 complex)
    {
        const float4* xr = (const float4*)(x + (size_t)b * 512 * 16);
        float4 a = xr[tid * 4 + 0], c = xr[tid * 4 + 1], d = xr[tid * 4 + 2], e = xr[tid * 4 + 3];
        s[tid] = (a.x + a.y + a.z + a.w) + (c.x + c.y + c.z + c.w)
               + (d.x + d.y + d.z + d.w) + (e.x + e.y + e.z + e.w);
        sp[tid] = 0.f;
        sp[512 + tid] = 0.f;
#pragma unroll
        for (int i = 0; i < 2; i++) {
            int e2 = tid + i * 512;           // 0..1023
            int t = e2 >> 1, j = e2 & 1;
            float4 v = xr[t * 4 + g * 2 + j];
            int p0 = j * 2;
            r0[(p0 + 0) * 512 + t] = v.x; i0[(p0 + 0) * 512 + t] = v.y;
            r0[(p0 + 1) * 512 + t] = v.z; i0[(p0 + 1) * 512 + t] = v.w;
        }
    }
    __syncthreads();
    sp[255 + tid] = s[tid];
    __syncthreads();

    // autocorrelation -> slot 4 (csd channel)
    {
        int t = tid;
        float acc0 = 0.f, acc1 = 0.f, acc2 = 0.f, acc3 = 0.f;
#pragma unroll 4
        for (int k = 0; k < 512; k += 4) {
            float4 sk = *(const float4*)&s[k];
            acc0 = fmaf(sp[t + k + 0], sk.x, acc0);
            acc1 = fmaf(sp[t + k + 1], sk.y, acc1);
            acc2 = fmaf(sp[t + k + 2], sk.z, acc2);
            acc3 = fmaf(sp[t + k + 3], sk.w, acc3);
        }
        r0[2048 + t] = (acc0 + acc1) + (acc2 + acc3);
        i0[2048 + t] = 0.f;
    }

    float *gfr, *gfi;
    fft512x5(r0, i0, r1, i1, tc, ts, tid, gfr, gfi);

    // features + proj + heads: 16-lane team per (ch, n), two-for-one unpack
    {
        const float SCC = SC_ORTHO / 256.0f;
        int lane16 = tid & 15;         // h-chunk owner: h in [lane16*4, lane16*4+4)
        int team   = tid >> 4;         // 32 teams
        int h0 = lane16 * 4;
        float4 w0 = *(const float4*)&wp[h0];
        float4 w1 = *(const float4*)&wp[64 + h0];
        float4 w2 = *(const float4*)&wp[128 + h0];
        float4 w3 = *(const float4*)&wp[192 + h0];
        float4 bb = *(const float4*)&bpp[h0];

        const int NITEM = 8 * NF_;     // 2056
        for (int it = team; it < NITEM; it += 32) {
            int ch = it / NF_;
            int n  = it - ch * NF_;
            int m  = b * 16 + g * 8 + ch;
            size_t id = (size_t)m * NF_ + n;

            int p  = ch >> 1, odd = ch & 1;
            int ml = (512 - n) & 511;
            float zr = gfr[p * 512 + n],  zi = gfi[p * 512 + n];
            float wr = gfr[p * 512 + ml], wi = gfi[p * 512 + ml];
            float fav_r = 0.5f * (zr + wr), fav_i = 0.5f * (zi - wi);
            float fbv_r = 0.5f * (zi + wi), fbv_i = 0.5f * (wr - zr);
            float fv_r = odd ? fbv_r : fav_r;
            float fv_i = odd ? fbv_i : fav_i;
            float re = fv_r * SC_ORTHO + gfr[2048 + n] * SCC;
            float im = fv_i * SC_ORTHO + gfi[2048 + n] * SCC;

            float s2 = re * re + im * im;
            float mag, sa, ca;
            if (s2 > 0.f) {
                float inv = rsqrtf(s2);
                mag = s2 * inv; sa = im * inv; ca = re * inv;
            } else { mag = 0.f; sa = 0.f; ca = 1.f; }
            float freqv = (float)n * 0.1953125f;

            float4 v;
            v.x = fmaxf(fmaf(mag, w0.x, fmaf(sa, w1.x, fmaf(ca, w2.x, fmaf(freqv, w3.x, bb.x)))), 0.f);
            v.y = fmaxf(fmaf(mag, w0.y, fmaf(sa, w1.y, fmaf(ca, w2.y, fmaf(freqv, w3.y, bb.y)))), 0.f);
            v.z = fmaxf(fmaf(mag, w0.z, fmaf(sa, w1.z, fmaf(ca, w2.z, fmaf(freqv, w3.z, bb.z)))), 0.f);
            v.w = fmaxf(fmaf(mag, w0.w, fmaf(sa, w1.w, fmaf(ca, w2.w, fmaf(freqv, w3.w, bb.w)))), 0.f);

            *(uint2*)(g_flat + (size_t)m * K_ + (size_t)n * 64 + h0) =
                make_uint2(packbf(v.x, v.y), packbf(v.z, v.w));

            float4 a = __ldg((const float4*)&mag_w[(size_t)n * 64 + h0]);
            float4 c = __ldg((const float4*)&ph_w[(size_t)n * 64 + h0]);
            float dm = 0.f, dp = 0.f;
            dm = fmaf(v.x, a.x, dm); dm = fmaf(v.y, a.y, dm);
            dm = fmaf(v.z, a.z, dm); dm = fmaf(v.w, a.w, dm);
            dp = fmaf(v.x, c.x, dp); dp = fmaf(v.y, c.y, dp);
            dp = fmaf(v.z, c.z, dp); dp = fmaf(v.w, c.w, dp);

#pragma unroll
            for (int off = 8; off >= 1; off >>= 1) {
                dm += __shfl_xor_sync(0xffffffffu, dm, off, 16);
                dp += __shfl_xor_sync(0xffffffffu, dp, off, 16);
            }
            if (lane16 == 0) {
                g_fft_re[id] = re;
                g_fft_im[id] = im;
                float mo  = fmaxf(dm + __ldg(&mag_b[n]), 0.f);
                float phv = 6.283185307179586f * sigf(dp + __ldg(&ph_b[n]));
                float spv, cpv;
                __sincosf(phv, &spv, &cpv);
                g_new_re[id] = mo * cpv;
                g_new_im[id] = mo * spv;
            }
        }
    }
}

// ---------------- kernel 2: bf16 mma.sync (m16n8k16) split-K GEMM (R6 version) ----------------
#define BK_       64
#define NCHUNK_   (K_/BK_)        // 257
#define ASTRIDE_W 36
#define A_WORDS_  (128*ASTRIDE_W)
#define B_WORDS_  (96*ASTRIDE_W)
#define STG_WORDS_ (A_WORDS_+B_WORDS_)
#define GEMM_SMEM_ (3*STG_WORDS_*4)

__device__ __forceinline__ void load_chunk(uint32_t sbase, const __nv_bfloat16* __restrict__ Ab,
                                           const __nv_bfloat16* __restrict__ Bb, int kbase, int tid)
{
    uint32_t sA = sbase;
    uint32_t sB = sbase + A_WORDS_ * 4;
#pragma unroll
    for (int i = 0; i < 4; i++) {
        int g = tid + (i << 8);
        int r = g >> 3, c = g & 7;
        CP_ASYNC16(sA + (uint32_t)(r * (ASTRIDE_W*4) + c * 16),
                   Ab + (size_t)r * K_ + kbase + c * 8);
    }
#pragma unroll
    for (int i = 0; i < 3; i++) {
        int g = tid + (i << 8);
        int r = g >> 3, c = g & 7;
        CP_ASYNC16(sB + (uint32_t)(r * (ASTRIDE_W*4) + c * 16),
                   Bb + (size_t)r * K_ + kbase + c * 8);
    }
    asm volatile("cp.async.commit_group;\n" ::: "memory");
}

__global__ void __launch_bounds__(256, 2) k_gemm()
{
    extern __shared__ __align__(16) uint32_t smem[];

    int tid = threadIdx.x;
    int nt0 = blockIdx.x;
    int m0  = blockIdx.y * 128;
    int s   = blockIdx.z;
    const __nv_bfloat16* Ab = g_flat + (size_t)m0 * K_;
    const __nv_bfloat16* Bb = g_wt + (size_t)(nt0 * 96) * K_;

    int warp = tid >> 5, lane = tid & 31;
    int wm = warp & 3;
    int wn = warp >> 2;
    int lr = lane >> 2, lc = lane & 3;

    int li = lane >> 3, lrr = lane & 7;
    uint32_t aoff[2], boff[3];
#pragma unroll
    for (int mt = 0; mt < 2; mt++)
        aoff[mt] = (uint32_t)(((wm * 32 + mt * 16 + (li & 1) * 8 + lrr) * ASTRIDE_W + (li >> 1) * 4) * 4);
#pragma unroll
    for (int p = 0; p < 3; p++)
        boff[p] = (uint32_t)(((wn * 48 + (2 * p + (li >> 1)) * 8 + lrr) * ASTRIDE_W + (li & 1) * 4) * 4
                             + A_WORDS_ * 4);

    float acc[2][6][4];
#pragma unroll
    for (int i = 0; i < 2; i++)
#pragma unroll
        for (int j = 0; j < 6; j++)
#pragma unroll
            for (int q = 0; q < 4; q++) acc[i][j][q] = 0.f;

    const int cs = (s * NCHUNK_) / SPLITS_;
    const int ce = ((s + 1) * NCHUNK_) / SPLITS_;
    const int CN = ce - cs;

    uint32_t sb = smem_u32(smem);

    load_chunk(sb + 0 * STG_WORDS_ * 4, Ab, Bb, (cs + 0) * BK_, tid);
    load_chunk(sb + 1 * STG_WORDS_ * 4, Ab, Bb, (cs + 1) * BK_, tid);

    for (int i = 0; i < CN; i++) {
        if (i + 2 < CN)
            load_chunk(sb + ((i + 2) % 3) * STG_WORDS_ * 4, Ab, Bb, (cs + i + 2) * BK_, tid);
        else
            asm volatile("cp.async.commit_group;\n" ::: "memory");
        asm volatile("cp.async.wait_group 2;\n" ::: "memory");
        __syncthreads();

        uint32_t stage = sb + (uint32_t)((i % 3) * STG_WORDS_ * 4);

#pragma unroll
        for (int kt = 0; kt < 4; kt++) {
            uint32_t kb = stage + (uint32_t)(kt * 32);
            uint32_t a[2][4];
            LDSM_X4(a[0][0], a[0][1], a[0][2], a[0][3], kb + aoff[0]);
            LDSM_X4(a[1][0], a[1][1], a[1][2], a[1][3], kb + aoff[1]);
            uint32_t bfr[6][2];
            LDSM_X4(bfr[0][0], bfr[0][1], bfr[1][0], bfr[1][1], kb + boff[0]);
            LDSM_X4(bfr[2][0], bfr[2][1], bfr[3][0], bfr[3][1], kb + boff[1]);
            LDSM_X4(bfr[4][0], bfr[4][1], bfr[5][0], bfr[5][1], kb + boff[2]);
#pragma unroll
            for (int mt = 0; mt < 2; mt++)
#pragma unroll
                for (int nt = 0; nt < 6; nt++)
                    mma_bf16(acc[mt][nt], a[mt], bfr[nt]);
        }
        __syncthreads();
    }

    float* P = g_part[s];
#pragma unroll
    for (int mt = 0; mt < 2; mt++) {
        int row = m0 + wm * 32 + mt * 16 + lr;
#pragma unroll
        for (int nt = 0; nt < 6; nt++) {
            int col = nt0 * 96 + wn * 48 + nt * 8 + lc * 2;
            float2 v0 = make_float2(acc[mt][nt][0], acc[mt][nt][1]);
            float2 v1 = make_float2(acc[mt][nt][2], acc[mt][nt][3]);
            *(float2*)(P + (size_t)row * NPAD_ + col)       = v0;
            *(float2*)(P + (size_t)(row + 8) * NPAD_ + col) = v1;
        }
    }
}

// ---------------- kernel 3: bwd — reduce+gate+blend + packed iFFTs + residual + LayerNorm ----------------
#define BWD_SMEMF 34048

__global__ void __launch_bounds__(512) k_bwd(
    const float* __restrict__ x, float* __restrict__ out,
    const float* __restrict__ bg,
    const float* __restrict__ gamma, const float* __restrict__ beta)
{
    extern __shared__ __align__(16) float sm[];
    int b = blockIdx.x, tid = threadIdx.x;

    float* r0  = sm;
    float* i0  = sm + 4096;
    float* r1  = sm + 8192;
    float* i1  = sm + 12288;
    float* fre = sm + 16384;   // [16][264]
    float* fim = sm + 20608;
    float* y   = sm + 24832;   // [512][17]
    float* tc  = sm + 33536;
    float* ts  = sm + 33792;

    if (tid < 256) {
        float _s, _c;
        sincosf(3.14159265358979323846f * (float)tid * (1.0f / 256.0f), &_s, &_c);
        tc[tid] = _c; ts[tid] = _s;
    }

    // split-K reduce + gate + blend
    for (int p = tid; p < 16 * NF_; p += 512) {
        int f = p / NF_;
        int n = p - f * NF_;
        int m = b * 16 + f;
        size_t pofs = (size_t)m * NPAD_ + n;
        float acc = 0.f;
#pragma unroll
        for (int s2 = 0; s2 < SPLITS_; s2++) acc += g_part[s2][pofs];
        float g = acc + __ldg(&bg[n]);
        g = g * sigf(g);
        float w = sigf(g);
        size_t id = (size_t)m * NF_ + n;
        fre[f * 264 + n] = w * g_new_re[id] + (1.f - w) * g_fft_re[id];
        fim[f * 264 + n] = w * g_new_im[id] + (1.f - w) * g_fft_im[id];
    }
    __syncthreads();

    // build 8 packed spectra: slot p holds Z = Fa + i*Fb, fa=2p, fb=2p+1 (hermitian extended)
#pragma unroll
    for (int i = 0; i < 8; i++) {
        int e = tid + i * 512;
        int p = e >> 9, pos = e & 511;
        int fa = (2 * p) * 264, fb = (2 * p + 1) * 264;
        float far, fai, fbr, fbi;
        if (pos == 0)        { far = fre[fa];       fai = 0.f;
                               fbr = fre[fb];       fbi = 0.f; }
        else if (pos < 256)  { far = fre[fa + pos]; fai = fim[fa + pos];
                               fbr = fre[fb + pos]; fbi = fim[fb + pos]; }
        else if (pos == 256) { far = fre[fa + 256]; fai = 0.f;
                               fbr = fre[fb + 256]; fbi = 0.f; }
        else                 { far = fre[fa + 512 - pos]; fai = -fim[fa + 512 - pos];
                               fbr = fre[fb + 512 - pos]; fbi = -fim[fb + 512 - pos]; }
        r0[p * 512 + pos] = far - fbi;
        i0[p * 512 + pos] = fai + fbr;
    }

    float *fr2, *fi2;
    fft512x8(r0, i0, r1, i1, tc, ts, tid, fr2, fi2);

#pragma unroll
    for (int i = 0; i < 8; i++) {
        int e = tid + i * 512;
        int p = e >> 9, t = e & 511;
        y[t * 17 + 2 * p]     = fr2[p * 512 + t] * SC_ORTHO;
        y[t * 17 + 2 * p + 1] = fi2[p * 512 + t] * SC_ORTHO;
    }
    __syncthreads();

    // residual + LayerNorm, thread t owns row t
    {
        int t = tid;
        const float4* xr = (const float4*)(x + ((size_t)(b * 512 + t)) * 16);
        float v[16];
#pragma unroll
        for (int q = 0; q < 4; q++) {
            float4 xv = xr[q];
            v[q * 4 + 0] = y[t * 17 + q * 4 + 0] + xv.x;
            v[q * 4 + 1] = y[t * 17 + q * 4 + 1] + xv.y;
            v[q * 4 + 2] = y[t * 17 + q * 4 + 2] + xv.z;
            v[q * 4 + 3] = y[t * 17 + q * 4 + 3] + xv.w;
        }
        float smv = 0.f;
#pragma unroll
        for (int i = 0; i < 16; i++) smv += v[i];
        float mu = smv * (1.f / 16.f);
        float ss = 0.f;
#pragma unroll
        for (int i = 0; i < 16; i++) { float d = v[i] - mu; ss = fmaf(d, d, ss); }
        float inv = rsqrtf(ss * (1.f / 16.f) + 1e-5f);
        float4* ov = (float4*)(out + ((size_t)(b * 512 + t)) * 16);
#pragma unroll
        for (int q = 0; q < 4; q++) {
            float4 o;
            o.x = (v[q * 4 + 0] - mu) * inv * __ldg(&gamma[q * 4 + 0]) + __ldg(&beta[q * 4 + 0]);
            o.y = (v[q * 4 + 1] - mu) * inv * __ldg(&gamma[q * 4 + 1]) + __ldg(&beta[q * 4 + 1]);
            o.z = (v[q * 4 + 2] - mu) * inv * __ldg(&gamma[q * 4 + 2]) + __ldg(&beta[q * 4 + 2]);
            o.w = (v[q * 4 + 3] - mu) * inv * __ldg(&gamma[q * 4 + 3]) + __ldg(&beta[q * 4 + 3]);
            ov[q] = o;
        }
    }
}

// ---------------- launcher: 3 kernels ----------------
extern "C" void kernel_launch(void* const* d_in, const int* in_sizes, int n_in,
                              void* d_out, int out_size)
{
    const float* x       = (const float*)d_in[0];
    const float* W_proj  = (const float*)d_in[1];
    const float* b_proj  = (const float*)d_in[2];
    const float* W_gate  = (const float*)d_in[3];
    const float* b_gate  = (const float*)d_in[4];
    const float* mag_w   = (const float*)d_in[5];
    const float* mag_b   = (const float*)d_in[6];
    const float* phase_w = (const float*)d_in[7];
    const float* phase_b = (const float*)d_in[8];
    const float* ln_g    = (const float*)d_in[9];
    const float* ln_b    = (const float*)d_in[10];
    float* out = (float*)d_out;

    cudaFuncSetAttribute(k_fwd,  cudaFuncAttributeMaxDynamicSharedMemorySize, FWD_SMEMF * 4);
    cudaFuncSetAttribute(k_gemm, cudaFuncAttributeMaxDynamicSharedMemorySize, GEMM_SMEM_);
    cudaFuncSetAttribute(k_bwd,  cudaFuncAttributeMaxDynamicSharedMemorySize, BWD_SMEMF * 4);

    k_fwd<<<NHEAVY_ + NT_BLKS_, 512, FWD_SMEMF * 4>>>(x, W_proj, b_proj, mag_w, mag_b,
                                                      phase_w, phase_b, W_gate);
    k_gemm<<<dim3(3, 16, SPLITS_), 256, GEMM_SMEM_>>>();
    k_bwd<<<B_, 512, BWD_SMEMF * 4>>>(x, out, b_gate, ln_g, ln_b);
}